// round 2
// baseline (speedup 1.0000x reference)
#include <cuda_runtime.h>
#include <cuda_bf16.h>
#include <math.h>

// Problem constants
#define BATCH 2
#define T_LEN 2048
#define D_MODEL 2048
#define NH 16
#define NKV 4
#define HD 128
#define EPS 1e-6f

// ---------------- scratch (device globals; no allocation allowed) ----------
__device__ float g_q[BATCH * T_LEN * NH * HD];
__device__ float g_k[BATCH * T_LEN * NKV * HD];
__device__ float g_v[BATCH * T_LEN * NKV * HD];
__device__ float g_att[BATCH * T_LEN * NH * HD];

// ---------------- helpers ----------------------------------------------------
__device__ __forceinline__ void split_pack(float x, float y, unsigned& hi, unsigned& lo) {
    __nv_bfloat16 hx = __float2bfloat16_rn(x);
    __nv_bfloat16 hy = __float2bfloat16_rn(y);
    float lx = x - __bfloat162float(hx);
    float ly = y - __bfloat162float(hy);
    __nv_bfloat162 h2 = __halves2bfloat162(hx, hy);   // x -> low half
    __nv_bfloat162 l2 = __floats2bfloat162_rn(lx, ly);
    hi = *reinterpret_cast<unsigned*>(&h2);
    lo = *reinterpret_cast<unsigned*>(&l2);
}

__device__ __forceinline__ void mma16816(float* c, const unsigned* a, const unsigned* b) {
    asm volatile(
        "mma.sync.aligned.m16n8k16.row.col.f32.bf16.bf16.f32 "
        "{%0,%1,%2,%3}, {%4,%5,%6,%7}, {%8,%9}, {%0,%1,%2,%3};"
        : "+f"(c[0]), "+f"(c[1]), "+f"(c[2]), "+f"(c[3])
        : "r"(a[0]), "r"(a[1]), "r"(a[2]), "r"(a[3]), "r"(b[0]), "r"(b[1]));
}

// ---------------- 3xBF16 tensor-core GEMM: C = A[MxK] @ B[KxN] --------------
// 128x128 block tile, BK=32, 256 threads (8 warps, 4x2 warp grid, 32x64/warp).
// Shared memory holds mma fragments directly (scattered at store time), so
// compute-side loads are conflict-free uint4 / uint2.
__global__ __launch_bounds__(256) void hgemm3bf(
    const float* __restrict__ A, const float* __restrict__ B,
    float* __restrict__ C, int M, int N, int K)
{
    __shared__ __align__(16) unsigned Afh[2048];       // [2 ks][8 mt][32 lane][4]
    __shared__ __align__(16) unsigned Afl[2048];
    __shared__ __align__(16) __nv_bfloat16 Bfh[4096];  // [2 ks][16 nt][32 lane][2 slot][2 half]
    __shared__ __align__(16) __nv_bfloat16 Bfl[4096];

    const int tid = threadIdx.x;
    const int lane = tid & 31, wid = tid >> 5;
    const int wm = wid >> 1, wn = wid & 1;
    const int bm = blockIdx.y * 128, bn = blockIdx.x * 128;

    float acc[2][8][4];
#pragma unroll
    for (int i = 0; i < 2; i++)
#pragma unroll
        for (int j = 0; j < 8; j++)
#pragma unroll
            for (int l = 0; l < 4; l++) acc[i][j][l] = 0.f;

    for (int k0 = 0; k0 < K; k0 += 32) {
        // ---- A tile 128x32 (1024 float4, 4 per thread), scatter to frag layout
#pragma unroll
        for (int it = 0; it < 4; it++) {
            int id = it * 256 + tid;
            int row = id >> 3, c4 = (id & 7) << 2;
            float4 v = *(const float4*)&A[(size_t)(bm + row) * K + k0 + c4];
            int ks = c4 >> 4, mt = row >> 4, r = row & 15;
            int lane0 = (r & 7) * 4 + ((c4 & 7) >> 1);
            int slot = (r >> 3) + ((c4 & 8) >> 2);
            int idx = ((ks * 8 + mt) * 32 + lane0) * 4 + slot;
            unsigned h0, l0, h1, l1;
            split_pack(v.x, v.y, h0, l0);
            split_pack(v.z, v.w, h1, l1);
            Afh[idx] = h0;     Afl[idx] = l0;
            Afh[idx + 4] = h1; Afl[idx + 4] = l1;
        }
        // ---- B tile 32x128 (1024 float4), scatter to frag layout (col-major frags)
#pragma unroll
        for (int it = 0; it < 4; it++) {
            int id = it * 256 + tid;
            int krow = id >> 5, c4 = (id & 31) << 2;
            float4 v = *(const float4*)&B[(size_t)(k0 + krow) * N + bn + c4];
            int ks = krow >> 4, kr = krow & 15;
            int nt = c4 >> 3;
            int tq = (kr & 7) >> 1, slot = kr >> 3, half = kr & 1;
            int base16 = ((((ks * 16 + nt) * 32) + ((c4 & 7) * 4 + tq)) * 2 + slot) * 2 + half;
            float vv[4] = {v.x, v.y, v.z, v.w};
#pragma unroll
            for (int e = 0; e < 4; e++) {
                __nv_bfloat16 h = __float2bfloat16_rn(vv[e]);
                Bfh[base16 + e * 16] = h;
                Bfl[base16 + e * 16] = __float2bfloat16_rn(vv[e] - __bfloat162float(h));
            }
        }
        __syncthreads();

        // ---- compute: 2 k16-steps, 2 m-tiles x 8 n-tiles, 3 mma each
#pragma unroll
        for (int ks = 0; ks < 2; ks++) {
            unsigned ah[2][4], al[2][4];
#pragma unroll
            for (int mt = 0; mt < 2; mt++) {
                int aidx = ((ks * 8 + wm * 2 + mt) * 32 + lane) * 4;
                uint4 t = *(const uint4*)&Afh[aidx];
                ah[mt][0] = t.x; ah[mt][1] = t.y; ah[mt][2] = t.z; ah[mt][3] = t.w;
                uint4 u = *(const uint4*)&Afl[aidx];
                al[mt][0] = u.x; al[mt][1] = u.y; al[mt][2] = u.z; al[mt][3] = u.w;
            }
#pragma unroll
            for (int nt = 0; nt < 8; nt++) {
                int bidx = ((ks * 16 + wn * 8 + nt) * 32 + lane) * 2;  // u32 index
                uint2 bhv2 = *(const uint2*)&reinterpret_cast<const unsigned*>(Bfh)[bidx];
                uint2 blv2 = *(const uint2*)&reinterpret_cast<const unsigned*>(Bfl)[bidx];
                unsigned bh[2] = {bhv2.x, bhv2.y};
                unsigned bl[2] = {blv2.x, blv2.y};
#pragma unroll
                for (int mt = 0; mt < 2; mt++) {
                    mma16816(acc[mt][nt], ah[mt], bh);
                    mma16816(acc[mt][nt], ah[mt], bl);
                    mma16816(acc[mt][nt], al[mt], bh);
                }
            }
        }
        __syncthreads();
    }

    // ---- epilogue
    const int g = lane >> 2, tq = lane & 3;
#pragma unroll
    for (int mt = 0; mt < 2; mt++) {
#pragma unroll
        for (int nt = 0; nt < 8; nt++) {
            int row = bm + wm * 32 + mt * 16 + g;
            int col = bn + wn * 64 + nt * 8 + 2 * tq;
            *(float2*)&C[(size_t)row * N + col] =
                make_float2(acc[mt][nt][0], acc[mt][nt][1]);
            *(float2*)&C[(size_t)(row + 8) * N + col] =
                make_float2(acc[mt][nt][2], acc[mt][nt][3]);
        }
    }
}

// ---------------- fused RMSNorm (over HD) + interleaved RoPE ----------------
__global__ __launch_bounds__(128) void rmsnorm_rope(
    float* __restrict__ x, const float* __restrict__ scale,
    const float* __restrict__ cosT, const float* __restrict__ sinT, int heads)
{
    const int row = blockIdx.x;
    const int t = (row / heads) % T_LEN;
    const int d = threadIdx.x;

    float v = x[(size_t)row * HD + d];
    float ss = v * v;
#pragma unroll
    for (int m = 16; m > 0; m >>= 1)
        ss += __shfl_xor_sync(0xffffffffu, ss, m);
    __shared__ float wsum[4];
    if ((d & 31) == 0) wsum[d >> 5] = ss;
    __syncthreads();
    float tot = wsum[0] + wsum[1] + wsum[2] + wsum[3];
    float r = rsqrtf(tot * (1.0f / HD) + EPS);

    float xn = v * r * scale[d];
    float part = __shfl_xor_sync(0xffffffffu, xn, 1);
    float rot = (d & 1) ? part : -part;
    x[(size_t)row * HD + d] = xn * cosT[t * HD + d] + rot * sinT[t * HD + d];
}

// ---------------- causal GQA flash attention (fp32) -------------------------
#define KPAD 68
__global__ __launch_bounds__(256) void flash_attn(
    const float* __restrict__ q, const float* __restrict__ k,
    const float* __restrict__ v, float* __restrict__ o)
{
    extern __shared__ float sm[];
    float* Qs = sm;                    // [64][128]
    float* Ks = Qs + 64 * 128;         // [128][KPAD] transposed
    float* Vs = Ks + 128 * KPAD;       // [64][128]
    float* Ps = Vs + 64 * 128;         // [64][64]

    const int qt = blockIdx.x, h = blockIdx.y, b = blockIdx.z;
    const int tid = threadIdx.x;
    const int kvh = h >> 2;
    const int sr = (tid >> 4) * 4;
    const int sc = (tid & 15) * 4;
    const int oc = (tid & 15) * 8;
    const float qk_scale = 0.08838834764831845f;

    const int q0 = ((b * T_LEN + qt * 64) * NH + h) * HD;
    for (int idx = tid; idx < 64 * 128; idx += 256) {
        int r = idx >> 7, c = idx & 127;
        Qs[r * 128 + c] = q[q0 + r * NH * HD + c] * qk_scale;
    }

    float m_i[4], l_i[4], Oacc[4][8];
#pragma unroll
    for (int i = 0; i < 4; i++) {
        m_i[i] = -1e30f; l_i[i] = 0.f;
#pragma unroll
        for (int j = 0; j < 8; j++) Oacc[i][j] = 0.f;
    }

    for (int kt = 0; kt <= qt; kt++) {
        const int kb = ((b * T_LEN + kt * 64) * NKV + kvh) * HD;
        for (int idx = tid; idx < 64 * 128; idx += 256) {
            int r = idx >> 7, c = idx & 127;
            Ks[c * KPAD + r] = k[kb + r * NKV * HD + c];
            Vs[idx]          = v[kb + r * NKV * HD + c];
        }
        __syncthreads();

        float s[4][4];
#pragma unroll
        for (int i = 0; i < 4; i++)
#pragma unroll
            for (int j = 0; j < 4; j++) s[i][j] = 0.f;
#pragma unroll 8
        for (int kk = 0; kk < 128; kk++) {
            float4 bb = *(float4*)&Ks[kk * KPAD + sc];
#pragma unroll
            for (int i = 0; i < 4; i++) {
                float a = Qs[(sr + i) * 128 + kk];
                s[i][0] = fmaf(a, bb.x, s[i][0]);
                s[i][1] = fmaf(a, bb.y, s[i][1]);
                s[i][2] = fmaf(a, bb.z, s[i][2]);
                s[i][3] = fmaf(a, bb.w, s[i][3]);
            }
        }
        if (kt == qt) {
#pragma unroll
            for (int i = 0; i < 4; i++)
#pragma unroll
                for (int j = 0; j < 4; j++)
                    if (sc + j > sr + i) s[i][j] = -1e30f;
        }

        float alpha[4];
#pragma unroll
        for (int i = 0; i < 4; i++) {
            float mx = fmaxf(fmaxf(s[i][0], s[i][1]), fmaxf(s[i][2], s[i][3]));
#pragma unroll
            for (int m = 8; m > 0; m >>= 1)
                mx = fmaxf(mx, __shfl_xor_sync(0xffffffffu, mx, m));
            float mnew = fmaxf(m_i[i], mx);
            alpha[i] = __expf(m_i[i] - mnew);
            m_i[i] = mnew;
            float rs = 0.f;
#pragma unroll
            for (int j = 0; j < 4; j++) {
                s[i][j] = __expf(s[i][j] - mnew);
                rs += s[i][j];
            }
#pragma unroll
            for (int m = 8; m > 0; m >>= 1)
                rs += __shfl_xor_sync(0xffffffffu, rs, m);
            l_i[i] = l_i[i] * alpha[i] + rs;
            *(float4*)&Ps[(sr + i) * 64 + sc] =
                make_float4(s[i][0], s[i][1], s[i][2], s[i][3]);
        }
#pragma unroll
        for (int i = 0; i < 4; i++)
#pragma unroll
            for (int j = 0; j < 8; j++) Oacc[i][j] *= alpha[i];
        __syncthreads();

#pragma unroll 4
        for (int kc = 0; kc < 64; kc++) {
            float4 b0 = *(float4*)&Vs[kc * 128 + oc];
            float4 b1 = *(float4*)&Vs[kc * 128 + oc + 4];
#pragma unroll
            for (int i = 0; i < 4; i++) {
                float a = Ps[(sr + i) * 64 + kc];
                Oacc[i][0] = fmaf(a, b0.x, Oacc[i][0]);
                Oacc[i][1] = fmaf(a, b0.y, Oacc[i][1]);
                Oacc[i][2] = fmaf(a, b0.z, Oacc[i][2]);
                Oacc[i][3] = fmaf(a, b0.w, Oacc[i][3]);
                Oacc[i][4] = fmaf(a, b1.x, Oacc[i][4]);
                Oacc[i][5] = fmaf(a, b1.y, Oacc[i][5]);
                Oacc[i][6] = fmaf(a, b1.z, Oacc[i][6]);
                Oacc[i][7] = fmaf(a, b1.w, Oacc[i][7]);
            }
        }
        __syncthreads();
    }

#pragma unroll
    for (int i = 0; i < 4; i++) {
        float inv = 1.f / l_i[i];
        size_t ob = ((size_t)(b * T_LEN + qt * 64 + sr + i) * NH + h) * HD + oc;
        *(float4*)&o[ob] = make_float4(Oacc[i][0] * inv, Oacc[i][1] * inv,
                                       Oacc[i][2] * inv, Oacc[i][3] * inv);
        *(float4*)&o[ob + 4] = make_float4(Oacc[i][4] * inv, Oacc[i][5] * inv,
                                           Oacc[i][6] * inv, Oacc[i][7] * inv);
    }
}

// ---------------- launcher ---------------------------------------------------
extern "C" void kernel_launch(void* const* d_in, const int* in_sizes, int n_in,
                              void* d_out, int out_size)
{
    const float* x       = (const float*)d_in[0];
    const float* Wq      = (const float*)d_in[1];
    const float* Wk      = (const float*)d_in[2];
    const float* Wv      = (const float*)d_in[3];
    const float* Wo      = (const float*)d_in[4];
    const float* q_scale = (const float*)d_in[5];
    const float* k_scale = (const float*)d_in[6];
    const float* cosT    = (const float*)d_in[7];
    const float* sinT    = (const float*)d_in[8];
    float* out = (float*)d_out;

    float *pq, *pk, *pv, *patt;
    cudaGetSymbolAddress((void**)&pq,   g_q);
    cudaGetSymbolAddress((void**)&pk,   g_k);
    cudaGetSymbolAddress((void**)&pv,   g_v);
    cudaGetSymbolAddress((void**)&patt, g_att);

    const int M = BATCH * T_LEN;  // 4096

    hgemm3bf<<<dim3(NH * HD / 128, M / 128), 256>>>(x, Wq, pq, M, NH * HD, D_MODEL);
    hgemm3bf<<<dim3(NKV * HD / 128, M / 128), 256>>>(x, Wk, pk, M, NKV * HD, D_MODEL);
    hgemm3bf<<<dim3(NKV * HD / 128, M / 128), 256>>>(x, Wv, pv, M, NKV * HD, D_MODEL);

    rmsnorm_rope<<<M * NH, 128>>>(pq, q_scale, cosT, sinT, NH);
    rmsnorm_rope<<<M * NKV, 128>>>(pk, k_scale, cosT, sinT, NKV);

    const int smem = (64 * 128 + 128 * KPAD + 64 * 128 + 64 * 64) * sizeof(float);
    static bool attr_set = false;
    if (!attr_set) {
        cudaFuncSetAttribute(flash_attn, cudaFuncAttributeMaxDynamicSharedMemorySize, smem);
        attr_set = true;
    }
    flash_attn<<<dim3(T_LEN / 64, NH, BATCH), 256, smem>>>(pq, pk, pv, patt);

    hgemm3bf<<<dim3(D_MODEL / 128, M / 128), 256>>>(patt, Wo, out, M, D_MODEL, D_MODEL);
}

// round 4
// speedup vs baseline: 1.8425x; 1.8425x over previous
#include <cuda_runtime.h>
#include <cuda_bf16.h>
#include <math.h>
#include <stdint.h>

// Problem constants
#define BATCH 2
#define T_LEN 2048
#define D_MODEL 2048
#define NH 16
#define NKV 4
#define HD 128
#define EPS 1e-6f
#define M_ROWS (BATCH * T_LEN)  // 4096

// ---------------- scratch (device globals; no allocation allowed) ----------
__device__ float g_q[M_ROWS * NH * HD];
__device__ float g_k[M_ROWS * NKV * HD];
__device__ float g_v[M_ROWS * NKV * HD];
__device__ float g_att[M_ROWS * NH * HD];

__device__ __nv_bfloat16 g_xh[M_ROWS * D_MODEL], g_xl[M_ROWS * D_MODEL];
__device__ __nv_bfloat16 g_ah[M_ROWS * D_MODEL], g_al[M_ROWS * D_MODEL];
__device__ __nv_bfloat16 g_wqh[D_MODEL * D_MODEL], g_wql[D_MODEL * D_MODEL];  // [N,K]
__device__ __nv_bfloat16 g_wkh[NKV * HD * D_MODEL], g_wkl[NKV * HD * D_MODEL];
__device__ __nv_bfloat16 g_wvh[NKV * HD * D_MODEL], g_wvl[NKV * HD * D_MODEL];
__device__ __nv_bfloat16 g_woh[D_MODEL * D_MODEL], g_wol[D_MODEL * D_MODEL];

// ---------------- helpers -----------------------------------------------------
__device__ __forceinline__ uint32_t smem_u32(const void* p) {
    uint32_t a;
    asm("{ .reg .u64 t; cvta.to.shared.u64 t, %1; cvt.u32.u64 %0, t; }"
        : "=r"(a) : "l"(p));
    return a;
}

#define CP16(dst, src) \
    asm volatile("cp.async.cg.shared.global [%0], [%1], 16;" :: "r"(dst), "l"(src))
#define CP_COMMIT() asm volatile("cp.async.commit_group;" ::: "memory")
#define CP_WAIT(n)  asm volatile("cp.async.wait_group %0;" :: "n"(n) : "memory")

__device__ __forceinline__ void mma16816(float* c, const uint32_t* a, const uint32_t* b) {
    asm volatile(
        "mma.sync.aligned.m16n8k16.row.col.f32.bf16.bf16.f32 "
        "{%0,%1,%2,%3}, {%4,%5,%6,%7}, {%8,%9}, {%0,%1,%2,%3};"
        : "+f"(c[0]), "+f"(c[1]), "+f"(c[2]), "+f"(c[3])
        : "r"(a[0]), "r"(a[1]), "r"(a[2]), "r"(a[3]), "r"(b[0]), "r"(b[1]));
}

// ---------------- conversion kernels -----------------------------------------
__global__ __launch_bounds__(256) void cvt_hilo(
    const float4* __restrict__ src, uint2* __restrict__ hi, uint2* __restrict__ lo, int n4)
{
    int i = blockIdx.x * 256 + threadIdx.x;
    if (i >= n4) return;
    float4 v = src[i];
    __nv_bfloat162 h01 = __floats2bfloat162_rn(v.x, v.y);
    __nv_bfloat162 h23 = __floats2bfloat162_rn(v.z, v.w);
    __nv_bfloat162 l01 = __floats2bfloat162_rn(v.x - __bfloat162float(h01.x),
                                               v.y - __bfloat162float(h01.y));
    __nv_bfloat162 l23 = __floats2bfloat162_rn(v.z - __bfloat162float(h23.x),
                                               v.w - __bfloat162float(h23.y));
    hi[i] = make_uint2(*(uint32_t*)&h01, *(uint32_t*)&h23);
    lo[i] = make_uint2(*(uint32_t*)&l01, *(uint32_t*)&l23);
}

// W [K,N] fp32 -> Th/Tl [N,K] bf16 (transpose + hi/lo split)
__global__ __launch_bounds__(256) void trans_cvt(
    const float* __restrict__ W, __nv_bfloat16* __restrict__ Th,
    __nv_bfloat16* __restrict__ Tl, int K, int N)
{
    __shared__ float tile[32][33];
    const int n0 = blockIdx.x * 32, k0 = blockIdx.y * 32;
    const int tx = threadIdx.x & 31, ty4 = (threadIdx.x >> 5) * 4;
#pragma unroll
    for (int i = 0; i < 4; i++)
        tile[ty4 + i][tx] = W[(size_t)(k0 + ty4 + i) * N + n0 + tx];
    __syncthreads();
#pragma unroll
    for (int i = 0; i < 4; i++) {
        float v = tile[tx][ty4 + i];
        __nv_bfloat16 h = __float2bfloat16_rn(v);
        size_t o = (size_t)(n0 + ty4 + i) * K + k0 + tx;
        Th[o] = h;
        Tl[o] = __float2bfloat16_rn(v - __bfloat162float(h));
    }
}

// ---------------- 3xBF16 HMMA GEMM: C[M,N] = A[M,K] @ Bt[N,K]^T ---------------
// 128x128 CTA tile, BK=32, 256 threads (8 warps, 4x2), cp.async double buffer.
// Smem holds mma fragments directly (u32 pair-packed), conflict-free both ways.
#define KC 32
#define BUF_U32 8192                    // per-stage u32s: Ah(2048) Al Bh Bl
#define GEMM_SMEM (2 * BUF_U32 * 4)     // 64 KB

__global__ __launch_bounds__(256) void mma_gemm(
    const __nv_bfloat16* __restrict__ Ahp, const __nv_bfloat16* __restrict__ Alp,
    const __nv_bfloat16* __restrict__ Bhp, const __nv_bfloat16* __restrict__ Blp,
    float* __restrict__ C, int M, int N, int K)
{
    extern __shared__ uint32_t s32[];
    const uint32_t sbase = smem_u32(s32);

    const int tid = threadIdx.x;
    const int lane = tid & 31, wid = tid >> 5;
    const int wm = wid >> 1, wn = wid & 1;
    const int bm = blockIdx.y * 128, bn = blockIdx.x * 128;
    const int NT = K / KC;

    float acc[2][8][4];
#pragma unroll
    for (int i = 0; i < 2; i++)
#pragma unroll
        for (int j = 0; j < 8; j++)
#pragma unroll
            for (int l = 0; l < 4; l++) acc[i][j][l] = 0.f;

    // ---- cp.async issue of one stage's tiles (8x 16B per thread) ----
    auto issue = [&](int it) {
        const int k0 = it * KC;
        const uint32_t sb = sbase + (it & 1) * (BUF_U32 * 4);
#pragma unroll
        for (int half = 0; half < 2; half++) {
            const __nv_bfloat16* As = half ? Alp : Ahp;
            const __nv_bfloat16* Bs = half ? Blp : Bhp;
            const uint32_t aoff = sb + half * 8192;
            const uint32_t boff = sb + 16384 + half * 8192;
#pragma unroll
            for (int i = 0; i < 2; i++) {
                int id = i * 256 + tid;          // 0..511
                int r = id >> 2, c8 = id & 3;
                int ks = c8 >> 1, j = c8 & 1;
                // A: row r (m), reg = (m%16>=8) + 2*j
                int mt = r >> 4, mrow = r & 15;
                uint32_t da = aoff +
                    (((((ks * 8 + mt) * 4) + ((mrow >> 3) & 1) + 2 * j) * 32 +
                      (mrow & 7) * 4) << 2);
                CP16(da, As + (size_t)(bm + r) * K + k0 + c8 * 8);
                // B: row r (n), reg = j
                int nt = r >> 3;
                uint32_t db = boff +
                    ((((ks * 16 + nt) * 2 + j) * 32 + (r & 7) * 4) << 2);
                CP16(db, Bs + (size_t)(bn + r) * K + k0 + c8 * 8);
            }
        }
    };

    issue(0);
    CP_COMMIT();

    for (int it = 0; it < NT; ++it) {
        if (it + 1 < NT) {
            issue(it + 1);
            CP_COMMIT();
            CP_WAIT(1);
        } else {
            CP_WAIT(0);
        }
        __syncthreads();

        const uint32_t* Afh = s32 + (it & 1) * BUF_U32;
        const uint32_t* Afl = Afh + 2048;
        const uint32_t* Bfh = Afh + 4096;
        const uint32_t* Bfl = Afh + 6144;

#pragma unroll
        for (int ks = 0; ks < 2; ks++) {
            uint32_t ah[2][4], al[2][4];
#pragma unroll
            for (int m2 = 0; m2 < 2; m2++) {
                int base = ((ks * 8 + wm * 2 + m2) * 4) * 32 + lane;
#pragma unroll
                for (int r = 0; r < 4; r++) {
                    ah[m2][r] = Afh[base + r * 32];
                    al[m2][r] = Afl[base + r * 32];
                }
            }
#pragma unroll
            for (int nt = 0; nt < 8; nt++) {
                int bb = ((ks * 16 + wn * 8 + nt) * 2) * 32 + lane;
                uint32_t bh[2] = {Bfh[bb], Bfh[bb + 32]};
                uint32_t bl[2] = {Bfl[bb], Bfl[bb + 32]};
#pragma unroll
                for (int m2 = 0; m2 < 2; m2++) {
                    mma16816(acc[m2][nt], ah[m2], bh);
                    mma16816(acc[m2][nt], ah[m2], bl);
                    mma16816(acc[m2][nt], al[m2], bh);
                }
            }
        }
        __syncthreads();
    }

    // ---- epilogue ----
    const int g = lane >> 2, q = lane & 3;
#pragma unroll
    for (int m2 = 0; m2 < 2; m2++) {
#pragma unroll
        for (int nt = 0; nt < 8; nt++) {
            int row = bm + wm * 32 + m2 * 16 + g;
            int col = bn + wn * 64 + nt * 8 + 2 * q;
            *(float2*)&C[(size_t)row * N + col] =
                make_float2(acc[m2][nt][0], acc[m2][nt][1]);
            *(float2*)&C[(size_t)(row + 8) * N + col] =
                make_float2(acc[m2][nt][2], acc[m2][nt][3]);
        }
    }
}

// ---------------- fused RMSNorm (over HD) + interleaved RoPE ----------------
__global__ __launch_bounds__(128) void rmsnorm_rope(
    float* __restrict__ x, const float* __restrict__ scale,
    const float* __restrict__ cosT, const float* __restrict__ sinT, int heads)
{
    const int row = blockIdx.x;
    const int t = (row / heads) % T_LEN;
    const int d = threadIdx.x;

    float v = x[(size_t)row * HD + d];
    float ss = v * v;
#pragma unroll
    for (int m = 16; m > 0; m >>= 1)
        ss += __shfl_xor_sync(0xffffffffu, ss, m);
    __shared__ float wsum[4];
    if ((d & 31) == 0) wsum[d >> 5] = ss;
    __syncthreads();
    float tot = wsum[0] + wsum[1] + wsum[2] + wsum[3];
    float r = rsqrtf(tot * (1.0f / HD) + EPS);

    float xn = v * r * scale[d];
    float part = __shfl_xor_sync(0xffffffffu, xn, 1);
    float rot = (d & 1) ? part : -part;
    x[(size_t)row * HD + d] = xn * cosT[t * HD + d] + rot * sinT[t * HD + d];
}

// ---------------- causal GQA flash attention (fp32) -------------------------
#define KPAD 68
__global__ __launch_bounds__(256) void flash_attn(
    const float* __restrict__ q, const float* __restrict__ k,
    const float* __restrict__ v, float* __restrict__ o)
{
    extern __shared__ float sm[];
    float* Qs = sm;                    // [64][128]
    float* Ks = Qs + 64 * 128;         // [128][KPAD] transposed
    float* Vs = Ks + 128 * KPAD;       // [64][128]
    float* Ps = Vs + 64 * 128;         // [64][64]

    const int qt = blockIdx.x, h = blockIdx.y, b = blockIdx.z;
    const int tid = threadIdx.x;
    const int kvh = h >> 2;
    const int sr = (tid >> 4) * 4;
    const int sc = (tid & 15) * 4;
    const int oc = (tid & 15) * 8;
    const float qk_scale = 0.08838834764831845f;

    const int q0 = ((b * T_LEN + qt * 64) * NH + h) * HD;
    for (int idx = tid; idx < 64 * 128; idx += 256) {
        int r = idx >> 7, c = idx & 127;
        Qs[r * 128 + c] = q[q0 + r * NH * HD + c] * qk_scale;
    }

    float m_i[4], l_i[4], Oacc[4][8];
#pragma unroll
    for (int i = 0; i < 4; i++) {
        m_i[i] = -1e30f; l_i[i] = 0.f;
#pragma unroll
        for (int j = 0; j < 8; j++) Oacc[i][j] = 0.f;
    }

    for (int kt = 0; kt <= qt; kt++) {
        const int kb = ((b * T_LEN + kt * 64) * NKV + kvh) * HD;
        for (int idx = tid; idx < 64 * 128; idx += 256) {
            int r = idx >> 7, c = idx & 127;
            Ks[c * KPAD + r] = k[kb + r * NKV * HD + c];
            Vs[idx]          = v[kb + r * NKV * HD + c];
        }
        __syncthreads();

        float s[4][4];
#pragma unroll
        for (int i = 0; i < 4; i++)
#pragma unroll
            for (int j = 0; j < 4; j++) s[i][j] = 0.f;
#pragma unroll 8
        for (int kk = 0; kk < 128; kk++) {
            float4 bb = *(float4*)&Ks[kk * KPAD + sc];
#pragma unroll
            for (int i = 0; i < 4; i++) {
                float a = Qs[(sr + i) * 128 + kk];
                s[i][0] = fmaf(a, bb.x, s[i][0]);
                s[i][1] = fmaf(a, bb.y, s[i][1]);
                s[i][2] = fmaf(a, bb.z, s[i][2]);
                s[i][3] = fmaf(a, bb.w, s[i][3]);
            }
        }
        if (kt == qt) {
#pragma unroll
            for (int i = 0; i < 4; i++)
#pragma unroll
                for (int j = 0; j < 4; j++)
                    if (sc + j > sr + i) s[i][j] = -1e30f;
        }

        float alpha[4];
#pragma unroll
        for (int i = 0; i < 4; i++) {
            float mx = fmaxf(fmaxf(s[i][0], s[i][1]), fmaxf(s[i][2], s[i][3]));
#pragma unroll
            for (int m = 8; m > 0; m >>= 1)
                mx = fmaxf(mx, __shfl_xor_sync(0xffffffffu, mx, m));
            float mnew = fmaxf(m_i[i], mx);
            alpha[i] = __expf(m_i[i] - mnew);
            m_i[i] = mnew;
            float rs = 0.f;
#pragma unroll
            for (int j = 0; j < 4; j++) {
                s[i][j] = __expf(s[i][j] - mnew);
                rs += s[i][j];
            }
#pragma unroll
            for (int m = 8; m > 0; m >>= 1)
                rs += __shfl_xor_sync(0xffffffffu, rs, m);
            l_i[i] = l_i[i] * alpha[i] + rs;
            *(float4*)&Ps[(sr + i) * 64 + sc] =
                make_float4(s[i][0], s[i][1], s[i][2], s[i][3]);
        }
#pragma unroll
        for (int i = 0; i < 4; i++)
#pragma unroll
            for (int j = 0; j < 8; j++) Oacc[i][j] *= alpha[i];
        __syncthreads();

#pragma unroll 4
        for (int kc = 0; kc < 64; kc++) {
            float4 b0 = *(float4*)&Vs[kc * 128 + oc];
            float4 b1 = *(float4*)&Vs[kc * 128 + oc + 4];
#pragma unroll
            for (int i = 0; i < 4; i++) {
                float a = Ps[(sr + i) * 64 + kc];
                Oacc[i][0] = fmaf(a, b0.x, Oacc[i][0]);
                Oacc[i][1] = fmaf(a, b0.y, Oacc[i][1]);
                Oacc[i][2] = fmaf(a, b0.z, Oacc[i][2]);
                Oacc[i][3] = fmaf(a, b0.w, Oacc[i][3]);
                Oacc[i][4] = fmaf(a, b1.x, Oacc[i][4]);
                Oacc[i][5] = fmaf(a, b1.y, Oacc[i][5]);
                Oacc[i][6] = fmaf(a, b1.z, Oacc[i][6]);
                Oacc[i][7] = fmaf(a, b1.w, Oacc[i][7]);
            }
        }
        __syncthreads();
    }

#pragma unroll
    for (int i = 0; i < 4; i++) {
        float inv = 1.f / l_i[i];
        size_t ob = ((size_t)(b * T_LEN + qt * 64 + sr + i) * NH + h) * HD + oc;
        *(float4*)&o[ob] = make_float4(Oacc[i][0] * inv, Oacc[i][1] * inv,
                                       Oacc[i][2] * inv, Oacc[i][3] * inv);
        *(float4*)&o[ob + 4] = make_float4(Oacc[i][4] * inv, Oacc[i][5] * inv,
                                           Oacc[i][6] * inv, Oacc[i][7] * inv);
    }
}

// ---------------- launcher ---------------------------------------------------
extern "C" void kernel_launch(void* const* d_in, const int* in_sizes, int n_in,
                              void* d_out, int out_size)
{
    const float* x       = (const float*)d_in[0];
    const float* Wq      = (const float*)d_in[1];
    const float* Wk      = (const float*)d_in[2];
    const float* Wv      = (const float*)d_in[3];
    const float* Wo      = (const float*)d_in[4];
    const float* q_scale = (const float*)d_in[5];
    const float* k_scale = (const float*)d_in[6];
    const float* cosT    = (const float*)d_in[7];
    const float* sinT    = (const float*)d_in[8];
    float* out = (float*)d_out;

    float *pq, *pk, *pv, *patt;
    cudaGetSymbolAddress((void**)&pq,   g_q);
    cudaGetSymbolAddress((void**)&pk,   g_k);
    cudaGetSymbolAddress((void**)&pv,   g_v);
    cudaGetSymbolAddress((void**)&patt, g_att);
    __nv_bfloat16 *xh, *xl, *ah, *al, *wqh, *wql, *wkh, *wkl, *wvh, *wvl, *woh, *wol;
    cudaGetSymbolAddress((void**)&xh, g_xh);  cudaGetSymbolAddress((void**)&xl, g_xl);
    cudaGetSymbolAddress((void**)&ah, g_ah);  cudaGetSymbolAddress((void**)&al, g_al);
    cudaGetSymbolAddress((void**)&wqh, g_wqh); cudaGetSymbolAddress((void**)&wql, g_wql);
    cudaGetSymbolAddress((void**)&wkh, g_wkh); cudaGetSymbolAddress((void**)&wkl, g_wkl);
    cudaGetSymbolAddress((void**)&wvh, g_wvh); cudaGetSymbolAddress((void**)&wvl, g_wvl);
    cudaGetSymbolAddress((void**)&woh, g_woh); cudaGetSymbolAddress((void**)&wol, g_wol);

    static bool attr_set = false;
    if (!attr_set) {
        cudaFuncSetAttribute(mma_gemm, cudaFuncAttributeMaxDynamicSharedMemorySize, GEMM_SMEM);
        const int fsmem = (64 * 128 + 128 * KPAD + 64 * 128 + 64 * 64) * sizeof(float);
        cudaFuncSetAttribute(flash_attn, cudaFuncAttributeMaxDynamicSharedMemorySize, fsmem);
        attr_set = true;
    }

    const int M = M_ROWS;  // 4096

    // one-time conversions
    cvt_hilo<<<(M * D_MODEL / 4 + 255) / 256, 256>>>((const float4*)x, (uint2*)xh, (uint2*)xl, M * D_MODEL / 4);
    trans_cvt<<<dim3(D_MODEL / 32, D_MODEL / 32), 256>>>(Wq, wqh, wql, D_MODEL, D_MODEL);
    trans_cvt<<<dim3(NKV * HD / 32, D_MODEL / 32), 256>>>(Wk, wkh, wkl, D_MODEL, NKV * HD);
    trans_cvt<<<dim3(NKV * HD / 32, D_MODEL / 32), 256>>>(Wv, wvh, wvl, D_MODEL, NKV * HD);
    trans_cvt<<<dim3(D_MODEL / 32, D_MODEL / 32), 256>>>(Wo, woh, wol, NH * HD, D_MODEL);

    // projections (tensor cores, 3xBF16)
    mma_gemm<<<dim3(NH * HD / 128, M / 128), 256, GEMM_SMEM>>>(xh, xl, wqh, wql, pq, M, NH * HD, D_MODEL);
    mma_gemm<<<dim3(NKV * HD / 128, M / 128), 256, GEMM_SMEM>>>(xh, xl, wkh, wkl, pk, M, NKV * HD, D_MODEL);
    mma_gemm<<<dim3(NKV * HD / 128, M / 128), 256, GEMM_SMEM>>>(xh, xl, wvh, wvl, pv, M, NKV * HD, D_MODEL);

    rmsnorm_rope<<<M * NH, 128>>>(pq, q_scale, cosT, sinT, NH);
    rmsnorm_rope<<<M * NKV, 128>>>(pk, k_scale, cosT, sinT, NKV);

    const int fsmem = (64 * 128 + 128 * KPAD + 64 * 128 + 64 * 64) * sizeof(float);
    flash_attn<<<dim3(T_LEN / 64, NH, BATCH), 256, fsmem>>>(pq, pk, pv, patt);

    // output projection
    cvt_hilo<<<(M * D_MODEL / 4 + 255) / 256, 256>>>((const float4*)patt, (uint2*)ah, (uint2*)al, M * D_MODEL / 4);
    mma_gemm<<<dim3(D_MODEL / 128, M / 128), 256, GEMM_SMEM>>>(ah, al, woh, wol, out, M, D_MODEL, D_MODEL);
}

// round 5
// speedup vs baseline: 4.0952x; 2.2226x over previous
#include <cuda_runtime.h>
#include <cuda_bf16.h>
#include <math.h>
#include <stdint.h>

// Problem constants
#define BATCH 2
#define T_LEN 2048
#define D_MODEL 2048
#define NH 16
#define NKV 4
#define HD 128
#define EPS 1e-6f
#define M_ROWS (BATCH * T_LEN)  // 4096

// ---------------- scratch (device globals; no allocation allowed) ----------
__device__ float g_q[M_ROWS * NH * HD];
__device__ float g_k[M_ROWS * NKV * HD];
__device__ float g_v[M_ROWS * NKV * HD];
__device__ float g_att[M_ROWS * NH * HD];

__device__ __nv_bfloat16 g_xh[M_ROWS * D_MODEL], g_xl[M_ROWS * D_MODEL];
__device__ __nv_bfloat16 g_ah[M_ROWS * D_MODEL], g_al[M_ROWS * D_MODEL];
__device__ __nv_bfloat16 g_wqh[D_MODEL * D_MODEL], g_wql[D_MODEL * D_MODEL];  // [N,K]
__device__ __nv_bfloat16 g_wkh[NKV * HD * D_MODEL], g_wkl[NKV * HD * D_MODEL];
__device__ __nv_bfloat16 g_wvh[NKV * HD * D_MODEL], g_wvl[NKV * HD * D_MODEL];
__device__ __nv_bfloat16 g_woh[D_MODEL * D_MODEL], g_wol[D_MODEL * D_MODEL];

__device__ __nv_bfloat16 g_qh[M_ROWS * NH * HD], g_ql[M_ROWS * NH * HD];
__device__ __nv_bfloat16 g_kh[M_ROWS * NKV * HD], g_kl[M_ROWS * NKV * HD];
__device__ __nv_bfloat16 g_vh[M_ROWS * NKV * HD], g_vl[M_ROWS * NKV * HD];

// ---------------- helpers -----------------------------------------------------
__device__ __forceinline__ uint32_t smem_u32(const void* p) {
    uint32_t a;
    asm("{ .reg .u64 t; cvta.to.shared.u64 t, %1; cvt.u32.u64 %0, t; }"
        : "=r"(a) : "l"(p));
    return a;
}

#define CP16(dst, src) \
    asm volatile("cp.async.cg.shared.global [%0], [%1], 16;" :: "r"(dst), "l"(src))
#define CP_COMMIT() asm volatile("cp.async.commit_group;" ::: "memory")
#define CP_WAIT(n)  asm volatile("cp.async.wait_group %0;" :: "n"(n) : "memory")

#define LDSM_X4(r0, r1, r2, r3, addr) \
    asm volatile("ldmatrix.sync.aligned.m8n8.x4.shared.b16 {%0,%1,%2,%3}, [%4];" \
                 : "=r"(r0), "=r"(r1), "=r"(r2), "=r"(r3) : "r"(addr))
#define LDSM_X4_T(r0, r1, r2, r3, addr) \
    asm volatile("ldmatrix.sync.aligned.m8n8.x4.trans.shared.b16 {%0,%1,%2,%3}, [%4];" \
                 : "=r"(r0), "=r"(r1), "=r"(r2), "=r"(r3) : "r"(addr))

__device__ __forceinline__ void mma_b(float* c, const uint32_t* a, uint32_t b0, uint32_t b1) {
    asm volatile(
        "mma.sync.aligned.m16n8k16.row.col.f32.bf16.bf16.f32 "
        "{%0,%1,%2,%3}, {%4,%5,%6,%7}, {%8,%9}, {%0,%1,%2,%3};"
        : "+f"(c[0]), "+f"(c[1]), "+f"(c[2]), "+f"(c[3])
        : "r"(a[0]), "r"(a[1]), "r"(a[2]), "r"(a[3]), "r"(b0), "r"(b1));
}

// pack two fp32 (x -> low half, y -> high half) into bf16x2 hi + residual lo
__device__ __forceinline__ void pack_hilo(float x, float y, uint32_t& hp, uint32_t& lp) {
    asm("cvt.rn.bf16x2.f32 %0, %1, %2;" : "=r"(hp) : "f"(y), "f"(x));
    float hx = __uint_as_float(hp << 16);
    float hy = __uint_as_float(hp & 0xffff0000u);
    asm("cvt.rn.bf16x2.f32 %0, %1, %2;" : "=r"(lp) : "f"(y - hy), "f"(x - hx));
}

// ---------------- conversion kernels -----------------------------------------
__global__ __launch_bounds__(256) void cvt_hilo(
    const float4* __restrict__ src, uint2* __restrict__ hi, uint2* __restrict__ lo, int n4)
{
    int i = blockIdx.x * 256 + threadIdx.x;
    if (i >= n4) return;
    float4 v = src[i];
    uint32_t h0, l0, h1, l1;
    pack_hilo(v.x, v.y, h0, l0);
    pack_hilo(v.z, v.w, h1, l1);
    hi[i] = make_uint2(h0, h1);
    lo[i] = make_uint2(l0, l1);
}

// W [K,N] fp32 -> Th/Tl [N,K] bf16 (transpose + hi/lo split)
__global__ __launch_bounds__(256) void trans_cvt(
    const float* __restrict__ W, __nv_bfloat16* __restrict__ Th,
    __nv_bfloat16* __restrict__ Tl, int K, int N)
{
    __shared__ float tile[32][33];
    const int n0 = blockIdx.x * 32, k0 = blockIdx.y * 32;
    const int tx = threadIdx.x & 31, ty4 = (threadIdx.x >> 5) * 4;
#pragma unroll
    for (int i = 0; i < 4; i++)
        tile[ty4 + i][tx] = W[(size_t)(k0 + ty4 + i) * N + n0 + tx];
    __syncthreads();
#pragma unroll
    for (int i = 0; i < 4; i++) {
        float v = tile[tx][ty4 + i];
        __nv_bfloat16 h = __float2bfloat16_rn(v);
        size_t o = (size_t)(n0 + ty4 + i) * K + k0 + tx;
        Th[o] = h;
        Tl[o] = __float2bfloat16_rn(v - __bfloat162float(h));
    }
}

// ---------------- 3xBF16 HMMA GEMM with ldmatrix ------------------------------
// C[M,N] = A[M,K] @ Bt[N,K]^T. 128x128 tile, KC=32, 256 threads (4x2 warps).
// Smem: swizzled rows of 64B (4 x 16B chunks), chunk' = c ^ ((r>>1)&3).
#define G_STAGE 32768
#define GEMM_SMEM (2 * G_STAGE)

__global__ __launch_bounds__(256) void mma_gemm(
    const __nv_bfloat16* __restrict__ Ahp, const __nv_bfloat16* __restrict__ Alp,
    const __nv_bfloat16* __restrict__ Bhp, const __nv_bfloat16* __restrict__ Blp,
    float* __restrict__ C, int M, int N, int K)
{
    extern __shared__ char smem[];
    const uint32_t sbase = smem_u32(smem);

    const int tid = threadIdx.x;
    const int lane = tid & 31, wid = tid >> 5;
    const int wm = wid >> 1, wn = wid & 1;
    const int bm = blockIdx.y * 128, bn = blockIdx.x * 128;
    const int NT = K / 32;

    float acc[2][8][4];
#pragma unroll
    for (int i = 0; i < 2; i++)
#pragma unroll
        for (int j = 0; j < 8; j++)
#pragma unroll
            for (int l = 0; l < 4; l++) acc[i][j][l] = 0.f;

    auto issue = [&](int it) {
        const int k0 = it * 32;
        const uint32_t sb = sbase + (it & 1) * G_STAGE;
#pragma unroll
        for (int i = 0; i < 8; i++) {
            int id = i * 256 + tid;          // 0..2047
            int arr = id >> 9;               // 0:Ah 1:Al 2:Bh 3:Bl
            int r = (id >> 2) & 127, c = id & 3;
            const __nv_bfloat16* src =
                (arr == 0) ? Ahp : (arr == 1) ? Alp : (arr == 2) ? Bhp : Blp;
            int grow = ((arr < 2) ? bm : bn) + r;
            uint32_t dst = sb + arr * 8192 + r * 64 + ((c ^ ((r >> 1) & 3)) << 4);
            CP16(dst, src + (size_t)grow * K + k0 + c * 8);
        }
    };

    issue(0);
    CP_COMMIT();

    for (int it = 0; it < NT; ++it) {
        if (it + 1 < NT) {
            issue(it + 1);
            CP_COMMIT();
            CP_WAIT(1);
        } else {
            CP_WAIT(0);
        }
        __syncthreads();

        const uint32_t sb = sbase + (it & 1) * G_STAGE;
        const int lrow = lane & 15, lc = lane >> 4;

#pragma unroll
        for (int ks = 0; ks < 2; ks++) {
            const int c = ks * 2 + lc;
            uint32_t ah[2][4], al[2][4];
#pragma unroll
            for (int mt = 0; mt < 2; mt++) {
                int r = wm * 32 + mt * 16 + lrow;
                uint32_t off = r * 64 + ((c ^ ((r >> 1) & 3)) << 4);
                LDSM_X4(ah[mt][0], ah[mt][1], ah[mt][2], ah[mt][3], sb + off);
                LDSM_X4(al[mt][0], al[mt][1], al[mt][2], al[mt][3], sb + 8192 + off);
            }
            uint32_t bh[16], bl[16];
#pragma unroll
            for (int j = 0; j < 4; j++) {
                int r = wn * 64 + 16 * j + lrow;
                uint32_t off = r * 64 + ((c ^ ((r >> 1) & 3)) << 4);
                LDSM_X4(bh[4 * j], bh[4 * j + 1], bh[4 * j + 2], bh[4 * j + 3],
                        sb + 16384 + off);
                LDSM_X4(bl[4 * j], bl[4 * j + 1], bl[4 * j + 2], bl[4 * j + 3],
                        sb + 24576 + off);
            }
#pragma unroll
            for (int nt = 0; nt < 8; nt++) {
                int bi = 4 * (nt >> 1) + (nt & 1);
                uint32_t b0h = bh[bi], b1h = bh[bi + 2];
                uint32_t b0l = bl[bi], b1l = bl[bi + 2];
#pragma unroll
                for (int mt = 0; mt < 2; mt++) {
                    mma_b(acc[mt][nt], ah[mt], b0h, b1h);
                    mma_b(acc[mt][nt], ah[mt], b0l, b1l);
                    mma_b(acc[mt][nt], al[mt], b0h, b1h);
                }
            }
        }
        __syncthreads();
    }

    const int g = lane >> 2, q = lane & 3;
#pragma unroll
    for (int mt = 0; mt < 2; mt++) {
#pragma unroll
        for (int nt = 0; nt < 8; nt++) {
            int row = bm + wm * 32 + mt * 16 + g;
            int col = bn + wn * 64 + nt * 8 + 2 * q;
            *(float2*)&C[(size_t)row * N + col] =
                make_float2(acc[mt][nt][0], acc[mt][nt][1]);
            *(float2*)&C[(size_t)(row + 8) * N + col] =
                make_float2(acc[mt][nt][2], acc[mt][nt][3]);
        }
    }
}

// ---------------- fused RMSNorm + RoPE -> bf16 hi/lo --------------------------
__global__ __launch_bounds__(128) void rmsnorm_rope_split(
    const float* __restrict__ x, const float* __restrict__ scale,
    const float* __restrict__ cosT, const float* __restrict__ sinT, int heads,
    float prescale, __nv_bfloat16* __restrict__ oh, __nv_bfloat16* __restrict__ ol)
{
    const int row = blockIdx.x;
    const int t = (row / heads) % T_LEN;
    const int d = threadIdx.x;

    float v = x[(size_t)row * HD + d];
    float ss = v * v;
#pragma unroll
    for (int m = 16; m > 0; m >>= 1)
        ss += __shfl_xor_sync(0xffffffffu, ss, m);
    __shared__ float wsum[4];
    if ((d & 31) == 0) wsum[d >> 5] = ss;
    __syncthreads();
    float tot = wsum[0] + wsum[1] + wsum[2] + wsum[3];
    float r = rsqrtf(tot * (1.0f / HD) + EPS);

    float xn = v * r * scale[d];
    float part = __shfl_xor_sync(0xffffffffu, xn, 1);
    float rot = (d & 1) ? part : -part;
    float outv = (xn * cosT[t * HD + d] + rot * sinT[t * HD + d]) * prescale;

    float other = __shfl_xor_sync(0xffffffffu, outv, 1);
    if ((d & 1) == 0) {
        uint32_t hp, lp;
        pack_hilo(outv, other, hp, lp);
        ((uint32_t*)oh)[(size_t)row * 64 + (d >> 1)] = hp;
        ((uint32_t*)ol)[(size_t)row * 64 + (d >> 1)] = lp;
    }
}

// ---------------- 3xBF16 HMMA causal GQA flash attention ----------------------
// BQ=128 (8 warps x m16), BK=64, HD=128. Q persistent smem (64KB) +
// double-buffered K/V hi/lo (2 x 64KB). 256 threads.
#define FA_KV_STAGE 65536
#define FA_SMEM (65536 + 2 * FA_KV_STAGE)
// 256B rows, 16 chunks/row, swizzle chunk' = c ^ (r & 7)
#define SWZ256(r, c) ((uint32_t)((r) * 256 + (((c) ^ ((r) & 7)) << 4)))

__global__ __launch_bounds__(256, 1) void flash_mma(
    const __nv_bfloat16* __restrict__ qh, const __nv_bfloat16* __restrict__ ql,
    const __nv_bfloat16* __restrict__ kh, const __nv_bfloat16* __restrict__ kl,
    const __nv_bfloat16* __restrict__ vh, const __nv_bfloat16* __restrict__ vl,
    float* __restrict__ o)
{
    extern __shared__ char fsm[];
    const uint32_t sb = smem_u32(fsm);
    const uint32_t Qh_s = sb, Ql_s = sb + 32768;
    const uint32_t ST = sb + 65536;  // per stage: Kh(16K) Kl Vh Vl

    const int qb = blockIdx.x, h = blockIdx.y, b = blockIdx.z;
    const int kvh = h >> 2;
    const int tid = threadIdx.x;
    const int lane = tid & 31, wid = tid >> 5;
    const int g = lane >> 2, qq = lane & 3;
    const int q0 = qb * 128;
    const int q0w = q0 + wid * 16;
    const int nkv = 2 * qb + 2;

    // ---- load Q (128 rows x 256B x 2 halves = 4096 chunks) ----
#pragma unroll
    for (int i = 0; i < 16; i++) {
        int id = i * 256 + tid;
        int c = id & 15, r = (id >> 4) & 127, half = id >> 11;
        const __nv_bfloat16* src = half ? ql : qh;
        uint32_t dst = (half ? Ql_s : Qh_s) + SWZ256(r, c);
        CP16(dst, src + ((size_t)(b * T_LEN + q0 + r) * NH + h) * HD + c * 8);
    }
    CP_COMMIT();

    auto issue_kv = [&](int stage, int kt) {
        const int kv0 = kt * 64;
        const uint32_t sbs = ST + stage * FA_KV_STAGE;
#pragma unroll
        for (int i = 0; i < 16; i++) {
            int id = i * 256 + tid;
            int c = id & 15, r = (id >> 4) & 63, arr = id >> 10;  // kh,kl,vh,vl
            const __nv_bfloat16* src =
                (arr == 0) ? kh : (arr == 1) ? kl : (arr == 2) ? vh : vl;
            uint32_t dst = sbs + arr * 16384 + SWZ256(r, c);
            CP16(dst, src + ((size_t)(b * T_LEN + kv0 + r) * NKV + kvh) * HD + c * 8);
        }
    };

    issue_kv(0, 0);
    CP_COMMIT();

    float m0 = -1e30f, m1 = -1e30f, l0 = 0.f, l1 = 0.f;
    float Oacc[16][4];
#pragma unroll
    for (int nt = 0; nt < 16; nt++)
#pragma unroll
        for (int e = 0; e < 4; e++) Oacc[nt][e] = 0.f;

    const int lrow = lane & 15, lc = lane >> 4;

    for (int kt = 0; kt < nkv; kt++) {
        if (kt + 1 < nkv) {
            issue_kv((kt + 1) & 1, kt + 1);
            CP_COMMIT();
            CP_WAIT(1);
        } else {
            CP_WAIT(0);
        }
        __syncthreads();

        const int kv0 = kt * 64;
        const uint32_t sbs = ST + (kt & 1) * FA_KV_STAGE;

        if (kv0 <= q0w + 15) {  // tile not fully masked for this warp
            // ---- S = Q K^T ----
            float S[8][4];
#pragma unroll
            for (int nt = 0; nt < 8; nt++)
#pragma unroll
                for (int e = 0; e < 4; e++) S[nt][e] = 0.f;

#pragma unroll
            for (int ks = 0; ks < 8; ks++) {
                const int c = ks * 2 + lc;
                int qr = wid * 16 + lrow;
                uint32_t qoff = SWZ256(qr, c);
                uint32_t aqh[4], aql[4];
                LDSM_X4(aqh[0], aqh[1], aqh[2], aqh[3], Qh_s + qoff);
                LDSM_X4(aql[0], aql[1], aql[2], aql[3], Ql_s + qoff);
                uint32_t bh[16], bl[16];
#pragma unroll
                for (int j = 0; j < 4; j++) {
                    int r = 16 * j + lrow;
                    uint32_t off = SWZ256(r, c);
                    LDSM_X4(bh[4 * j], bh[4 * j + 1], bh[4 * j + 2], bh[4 * j + 3],
                            sbs + off);
                    LDSM_X4(bl[4 * j], bl[4 * j + 1], bl[4 * j + 2], bl[4 * j + 3],
                            sbs + 16384 + off);
                }
#pragma unroll
                for (int nt = 0; nt < 8; nt++) {
                    int bi = 4 * (nt >> 1) + (nt & 1);
                    mma_b(S[nt], aqh, bh[bi], bh[bi + 2]);
                    mma_b(S[nt], aqh, bl[bi], bl[bi + 2]);
                    mma_b(S[nt], aql, bh[bi], bh[bi + 2]);
                }
            }

            // ---- causal mask (diagonal region) ----
            if (kv0 + 63 > q0w) {
#pragma unroll
                for (int nt = 0; nt < 8; nt++) {
                    int col = kv0 + nt * 8 + qq * 2;
                    int r0 = q0w + g, r1 = q0w + g + 8;
                    if (col > r0) S[nt][0] = -1e30f;
                    if (col + 1 > r0) S[nt][1] = -1e30f;
                    if (col > r1) S[nt][2] = -1e30f;
                    if (col + 1 > r1) S[nt][3] = -1e30f;
                }
            }

            // ---- online softmax (exp2 domain; rows g and g+8) ----
            float mx0 = -1e30f, mx1 = -1e30f;
#pragma unroll
            for (int nt = 0; nt < 8; nt++) {
                mx0 = fmaxf(mx0, fmaxf(S[nt][0], S[nt][1]));
                mx1 = fmaxf(mx1, fmaxf(S[nt][2], S[nt][3]));
            }
            mx0 = fmaxf(mx0, __shfl_xor_sync(0xffffffffu, mx0, 1));
            mx0 = fmaxf(mx0, __shfl_xor_sync(0xffffffffu, mx0, 2));
            mx1 = fmaxf(mx1, __shfl_xor_sync(0xffffffffu, mx1, 1));
            mx1 = fmaxf(mx1, __shfl_xor_sync(0xffffffffu, mx1, 2));
            float mn0 = fmaxf(m0, mx0), mn1 = fmaxf(m1, mx1);
            float al0 = exp2f(m0 - mn0), al1 = exp2f(m1 - mn1);
            m0 = mn0; m1 = mn1;
            float sum0 = 0.f, sum1 = 0.f;
#pragma unroll
            for (int nt = 0; nt < 8; nt++) {
                S[nt][0] = exp2f(S[nt][0] - mn0);
                S[nt][1] = exp2f(S[nt][1] - mn0);
                S[nt][2] = exp2f(S[nt][2] - mn1);
                S[nt][3] = exp2f(S[nt][3] - mn1);
                sum0 += S[nt][0] + S[nt][1];
                sum1 += S[nt][2] + S[nt][3];
            }
            sum0 += __shfl_xor_sync(0xffffffffu, sum0, 1);
            sum0 += __shfl_xor_sync(0xffffffffu, sum0, 2);
            sum1 += __shfl_xor_sync(0xffffffffu, sum1, 1);
            sum1 += __shfl_xor_sync(0xffffffffu, sum1, 2);
            l0 = l0 * al0 + sum0;
            l1 = l1 * al1 + sum1;
#pragma unroll
            for (int nt = 0; nt < 16; nt++) {
                Oacc[nt][0] *= al0; Oacc[nt][1] *= al0;
                Oacc[nt][2] *= al1; Oacc[nt][3] *= al1;
            }

            // ---- split P into bf16 hi/lo A-fragments ----
            uint32_t Ph[4][4], Pl[4][4];
#pragma unroll
            for (int ktp = 0; ktp < 4; ktp++) {
                pack_hilo(S[2 * ktp][0], S[2 * ktp][1], Ph[ktp][0], Pl[ktp][0]);
                pack_hilo(S[2 * ktp][2], S[2 * ktp][3], Ph[ktp][1], Pl[ktp][1]);
                pack_hilo(S[2 * ktp + 1][0], S[2 * ktp + 1][1], Ph[ktp][2], Pl[ktp][2]);
                pack_hilo(S[2 * ktp + 1][2], S[2 * ktp + 1][3], Ph[ktp][3], Pl[ktp][3]);
            }

            // ---- O += P V ----
#pragma unroll
            for (int ktp = 0; ktp < 4; ktp++) {
#pragma unroll
                for (int j = 0; j < 8; j++) {
                    int r = ktp * 16 + lrow;
                    int c = 2 * j + lc;
                    uint32_t off = SWZ256(r, c);
                    uint32_t v0, v1, v2, v3, w0, w1, w2, w3;
                    LDSM_X4_T(v0, v1, v2, v3, sbs + 32768 + off);
                    LDSM_X4_T(w0, w1, w2, w3, sbs + 49152 + off);
                    mma_b(Oacc[2 * j], Ph[ktp], v0, v1);
                    mma_b(Oacc[2 * j], Ph[ktp], w0, w1);
                    mma_b(Oacc[2 * j], Pl[ktp], v0, v1);
                    mma_b(Oacc[2 * j + 1], Ph[ktp], v2, v3);
                    mma_b(Oacc[2 * j + 1], Ph[ktp], w2, w3);
                    mma_b(Oacc[2 * j + 1], Pl[ktp], v2, v3);
                }
            }
        }
        __syncthreads();
    }

    // ---- write O ----
    float inv0 = 1.f / l0, inv1 = 1.f / l1;
    const size_t base0 = ((size_t)(b * T_LEN + q0w + g) * NH + h) * HD;
    const size_t base1 = base0 + (size_t)8 * NH * HD;
#pragma unroll
    for (int nt = 0; nt < 16; nt++) {
        int col = nt * 8 + qq * 2;
        *(float2*)&o[base0 + col] = make_float2(Oacc[nt][0] * inv0, Oacc[nt][1] * inv0);
        *(float2*)&o[base1 + col] = make_float2(Oacc[nt][2] * inv1, Oacc[nt][3] * inv1);
    }
}

// ---------------- launcher ---------------------------------------------------
extern "C" void kernel_launch(void* const* d_in, const int* in_sizes, int n_in,
                              void* d_out, int out_size)
{
    const float* x       = (const float*)d_in[0];
    const float* Wq      = (const float*)d_in[1];
    const float* Wk      = (const float*)d_in[2];
    const float* Wv      = (const float*)d_in[3];
    const float* Wo      = (const float*)d_in[4];
    const float* q_scale = (const float*)d_in[5];
    const float* k_scale = (const float*)d_in[6];
    const float* cosT    = (const float*)d_in[7];
    const float* sinT    = (const float*)d_in[8];
    float* out = (float*)d_out;

    float *pq, *pk, *pv, *patt;
    cudaGetSymbolAddress((void**)&pq,   g_q);
    cudaGetSymbolAddress((void**)&pk,   g_k);
    cudaGetSymbolAddress((void**)&pv,   g_v);
    cudaGetSymbolAddress((void**)&patt, g_att);
    __nv_bfloat16 *xh, *xl, *ah, *al, *wqh, *wql, *wkh, *wkl, *wvh, *wvl, *woh, *wol;
    __nv_bfloat16 *qh, *ql, *khp, *klp, *vhp, *vlp;
    cudaGetSymbolAddress((void**)&xh, g_xh);  cudaGetSymbolAddress((void**)&xl, g_xl);
    cudaGetSymbolAddress((void**)&ah, g_ah);  cudaGetSymbolAddress((void**)&al, g_al);
    cudaGetSymbolAddress((void**)&wqh, g_wqh); cudaGetSymbolAddress((void**)&wql, g_wql);
    cudaGetSymbolAddress((void**)&wkh, g_wkh); cudaGetSymbolAddress((void**)&wkl, g_wkl);
    cudaGetSymbolAddress((void**)&wvh, g_wvh); cudaGetSymbolAddress((void**)&wvl, g_wvl);
    cudaGetSymbolAddress((void**)&woh, g_woh); cudaGetSymbolAddress((void**)&wol, g_wol);
    cudaGetSymbolAddress((void**)&qh, g_qh);   cudaGetSymbolAddress((void**)&ql, g_ql);
    cudaGetSymbolAddress((void**)&khp, g_kh);  cudaGetSymbolAddress((void**)&klp, g_kl);
    cudaGetSymbolAddress((void**)&vhp, g_vh);  cudaGetSymbolAddress((void**)&vlp, g_vl);

    static bool attr_set = false;
    if (!attr_set) {
        cudaFuncSetAttribute(mma_gemm, cudaFuncAttributeMaxDynamicSharedMemorySize, GEMM_SMEM);
        cudaFuncSetAttribute(flash_mma, cudaFuncAttributeMaxDynamicSharedMemorySize, FA_SMEM);
        attr_set = true;
    }

    const int M = M_ROWS;  // 4096

    // one-time conversions
    cvt_hilo<<<(M * D_MODEL / 4 + 255) / 256, 256>>>((const float4*)x, (uint2*)xh, (uint2*)xl, M * D_MODEL / 4);
    trans_cvt<<<dim3(D_MODEL / 32, D_MODEL / 32), 256>>>(Wq, wqh, wql, D_MODEL, D_MODEL);
    trans_cvt<<<dim3(NKV * HD / 32, D_MODEL / 32), 256>>>(Wk, wkh, wkl, D_MODEL, NKV * HD);
    trans_cvt<<<dim3(NKV * HD / 32, D_MODEL / 32), 256>>>(Wv, wvh, wvl, D_MODEL, NKV * HD);
    trans_cvt<<<dim3(D_MODEL / 32, D_MODEL / 32), 256>>>(Wo, woh, wol, NH * HD, D_MODEL);

    // projections (tensor cores, 3xBF16)
    mma_gemm<<<dim3(NH * HD / 128, M / 128), 256, GEMM_SMEM>>>(xh, xl, wqh, wql, pq, M, NH * HD, D_MODEL);
    mma_gemm<<<dim3(NKV * HD / 128, M / 128), 256, GEMM_SMEM>>>(xh, xl, wkh, wkl, pk, M, NKV * HD, D_MODEL);
    mma_gemm<<<dim3(NKV * HD / 128, M / 128), 256, GEMM_SMEM>>>(xh, xl, wvh, wvl, pv, M, NKV * HD, D_MODEL);

    // RMSNorm + RoPE -> bf16 hi/lo (q pre-scaled by log2(e)/sqrt(HD))
    const float qk_scale = 1.4426950408889634f * 0.08838834764831845f;
    rmsnorm_rope_split<<<M * NH, 128>>>(pq, q_scale, cosT, sinT, NH, qk_scale, qh, ql);
    rmsnorm_rope_split<<<M * NKV, 128>>>(pk, k_scale, cosT, sinT, NKV, 1.0f, khp, klp);
    cvt_hilo<<<(M * NKV * HD / 4 + 255) / 256, 256>>>((const float4*)pv, (uint2*)vhp, (uint2*)vlp, M * NKV * HD / 4);

    // flash attention (tensor cores)
    flash_mma<<<dim3(T_LEN / 128, NH, BATCH), 256, FA_SMEM>>>(qh, ql, khp, klp, vhp, vlp, patt);

    // output projection
    cvt_hilo<<<(M * D_MODEL / 4 + 255) / 256, 256>>>((const float4*)patt, (uint2*)ah, (uint2*)al, M * D_MODEL / 4);
    mma_gemm<<<dim3(D_MODEL / 128, M / 128), 256, GEMM_SMEM>>>(ah, al, woh, wol, out, M, D_MODEL, D_MODEL);
}

// round 6
// speedup vs baseline: 4.3452x; 1.0611x over previous
#include <cuda_runtime.h>
#include <cuda_bf16.h>
#include <math.h>
#include <stdint.h>

// Problem constants
#define BATCH 2
#define T_LEN 2048
#define D_MODEL 2048
#define NH 16
#define NKV 4
#define HD 128
#define EPS 1e-6f
#define M_ROWS (BATCH * T_LEN)  // 4096

// ---------------- scratch (device globals; no allocation allowed) ----------
__device__ float g_q[M_ROWS * NH * HD];
__device__ float g_k[M_ROWS * NKV * HD];

__device__ __nv_bfloat16 g_xh[M_ROWS * D_MODEL], g_xl[M_ROWS * D_MODEL];
__device__ __nv_bfloat16 g_ah[M_ROWS * D_MODEL], g_al[M_ROWS * D_MODEL];
__device__ __nv_bfloat16 g_wqh[D_MODEL * D_MODEL], g_wql[D_MODEL * D_MODEL];  // [N,K]
__device__ __nv_bfloat16 g_wkh[NKV * HD * D_MODEL], g_wkl[NKV * HD * D_MODEL];
__device__ __nv_bfloat16 g_wvh[NKV * HD * D_MODEL], g_wvl[NKV * HD * D_MODEL];
__device__ __nv_bfloat16 g_woh[D_MODEL * D_MODEL], g_wol[D_MODEL * D_MODEL];

__device__ __nv_bfloat16 g_qh[M_ROWS * NH * HD], g_ql[M_ROWS * NH * HD];
__device__ __nv_bfloat16 g_kh[M_ROWS * NKV * HD], g_kl[M_ROWS * NKV * HD];
__device__ __nv_bfloat16 g_vh[M_ROWS * NKV * HD], g_vl[M_ROWS * NKV * HD];

// ---------------- helpers -----------------------------------------------------
__device__ __forceinline__ uint32_t smem_u32(const void* p) {
    uint32_t a;
    asm("{ .reg .u64 t; cvta.to.shared.u64 t, %1; cvt.u32.u64 %0, t; }"
        : "=r"(a) : "l"(p));
    return a;
}

#define CP16(dst, src) \
    asm volatile("cp.async.cg.shared.global [%0], [%1], 16;" :: "r"(dst), "l"(src))
#define CP_COMMIT() asm volatile("cp.async.commit_group;" ::: "memory")
#define CP_WAIT(n)  asm volatile("cp.async.wait_group %0;" :: "n"(n) : "memory")

#define LDSM_X4(r0, r1, r2, r3, addr) \
    asm volatile("ldmatrix.sync.aligned.m8n8.x4.shared.b16 {%0,%1,%2,%3}, [%4];" \
                 : "=r"(r0), "=r"(r1), "=r"(r2), "=r"(r3) : "r"(addr))
#define LDSM_X4_T(r0, r1, r2, r3, addr) \
    asm volatile("ldmatrix.sync.aligned.m8n8.x4.trans.shared.b16 {%0,%1,%2,%3}, [%4];" \
                 : "=r"(r0), "=r"(r1), "=r"(r2), "=r"(r3) : "r"(addr))

__device__ __forceinline__ void mma_b(float* c, const uint32_t* a, uint32_t b0, uint32_t b1) {
    asm volatile(
        "mma.sync.aligned.m16n8k16.row.col.f32.bf16.bf16.f32 "
        "{%0,%1,%2,%3}, {%4,%5,%6,%7}, {%8,%9}, {%0,%1,%2,%3};"
        : "+f"(c[0]), "+f"(c[1]), "+f"(c[2]), "+f"(c[3])
        : "r"(a[0]), "r"(a[1]), "r"(a[2]), "r"(a[3]), "r"(b0), "r"(b1));
}

// pack two fp32 (x -> low half, y -> high half) into bf16x2 hi + residual lo
__device__ __forceinline__ void pack_hilo(float x, float y, uint32_t& hp, uint32_t& lp) {
    asm("cvt.rn.bf16x2.f32 %0, %1, %2;" : "=r"(hp) : "f"(y), "f"(x));
    float hx = __uint_as_float(hp << 16);
    float hy = __uint_as_float(hp & 0xffff0000u);
    asm("cvt.rn.bf16x2.f32 %0, %1, %2;" : "=r"(lp) : "f"(y - hy), "f"(x - hx));
}

// ---------------- conversion kernels -----------------------------------------
__global__ __launch_bounds__(256) void cvt_hilo(
    const float4* __restrict__ src, uint2* __restrict__ hi, uint2* __restrict__ lo, int n4)
{
    int i = blockIdx.x * 256 + threadIdx.x;
    if (i >= n4) return;
    float4 v = src[i];
    uint32_t h0, l0, h1, l1;
    pack_hilo(v.x, v.y, h0, l0);
    pack_hilo(v.z, v.w, h1, l1);
    hi[i] = make_uint2(h0, h1);
    lo[i] = make_uint2(l0, l1);
}

// W [K,N] fp32 -> Th/Tl [N,K] bf16 (transpose + hi/lo split)
__global__ __launch_bounds__(256) void trans_cvt(
    const float* __restrict__ W, __nv_bfloat16* __restrict__ Th,
    __nv_bfloat16* __restrict__ Tl, int K, int N)
{
    __shared__ float tile[32][33];
    const int n0 = blockIdx.x * 32, k0 = blockIdx.y * 32;
    const int tx = threadIdx.x & 31, ty4 = (threadIdx.x >> 5) * 4;
#pragma unroll
    for (int i = 0; i < 4; i++)
        tile[ty4 + i][tx] = W[(size_t)(k0 + ty4 + i) * N + n0 + tx];
    __syncthreads();
#pragma unroll
    for (int i = 0; i < 4; i++) {
        float v = tile[tx][ty4 + i];
        __nv_bfloat16 h = __float2bfloat16_rn(v);
        size_t o = (size_t)(n0 + ty4 + i) * K + k0 + tx;
        Th[o] = h;
        Tl[o] = __float2bfloat16_rn(v - __bfloat162float(h));
    }
}

// ---------------- 3xBF16 HMMA GEMM, 128x256 tile, 3-stage cp.async ------------
// C[M,N] = A[M,K] @ Bt[N,K]^T. 256 threads, warp grid 2x4, warp tile 64x64.
// Two B regions: blocks with blockIdx.x < nx0 compute region0 (fp32 out C0),
// the rest compute region1 (bf16 hi/lo out C1h/C1l). Smem rows of 64B,
// swizzle chunk' = c ^ ((r>>1)&3).
#define G_STAGE 49152
#define GEMM_SMEM (3 * G_STAGE)

__global__ __launch_bounds__(256) void mma_gemm(
    const __nv_bfloat16* __restrict__ Ahp, const __nv_bfloat16* __restrict__ Alp,
    const __nv_bfloat16* __restrict__ B0h, const __nv_bfloat16* __restrict__ B0l,
    const __nv_bfloat16* __restrict__ B1h, const __nv_bfloat16* __restrict__ B1l,
    float* __restrict__ C0, __nv_bfloat16* __restrict__ C1h,
    __nv_bfloat16* __restrict__ C1l,
    int K, int nx0, int N0, int N1)
{
    extern __shared__ char smem[];
    const uint32_t sbase = smem_u32(smem);

    const int tid = threadIdx.x;
    const int lane = tid & 31, wid = tid >> 5;
    const int wm = wid >> 2, wn = wid & 3;
    const bool regB = ((int)blockIdx.x >= nx0);
    const int bn = (regB ? (blockIdx.x - nx0) : blockIdx.x) * 256;
    const int bm = blockIdx.y * 128;
    const __nv_bfloat16* Bh = regB ? B1h : B0h;
    const __nv_bfloat16* Bl = regB ? B1l : B0l;
    const int N = regB ? N1 : N0;
    const int NT = K / 32;

    float acc[4][8][4];
#pragma unroll
    for (int i = 0; i < 4; i++)
#pragma unroll
        for (int j = 0; j < 8; j++)
#pragma unroll
            for (int l = 0; l < 4; l++) acc[i][j][l] = 0.f;

    auto issue = [&](int it) {
        const int k0 = it * 32;
        const uint32_t sb = sbase + (it % 3) * G_STAGE;
#pragma unroll
        for (int i = 0; i < 12; i++) {
            int id = i * 256 + tid;          // 0..3071
            if (id < 1024) {                 // A: 128 rows x 4 chunks x 2 halves
                int half = id >> 9, r = (id >> 2) & 127, c = id & 3;
                const __nv_bfloat16* src = half ? Alp : Ahp;
                uint32_t dst = sb + half * 8192 + r * 64 + ((c ^ ((r >> 1) & 3)) << 4);
                CP16(dst, src + (size_t)(bm + r) * K + k0 + c * 8);
            } else {                         // B: 256 rows x 4 chunks x 2 halves
                int idb = id - 1024;
                int half = idb >> 10, r = (idb >> 2) & 255, c = idb & 3;
                const __nv_bfloat16* src = half ? Bl : Bh;
                uint32_t dst = sb + 16384 + half * 16384 +
                               r * 64 + ((c ^ ((r >> 1) & 3)) << 4);
                CP16(dst, src + (size_t)(bn + r) * K + k0 + c * 8);
            }
        }
    };

    issue(0); CP_COMMIT();
    issue(1); CP_COMMIT();

    const int lrow = lane & 15, lc = lane >> 4;

    for (int it = 0; it < NT; ++it) {
        if (it + 1 < NT) { CP_WAIT(1); } else { CP_WAIT(0); }
        __syncthreads();
        if (it + 2 < NT) { issue(it + 2); CP_COMMIT(); }

        const uint32_t sb = sbase + (it % 3) * G_STAGE;
#pragma unroll
        for (int ks = 0; ks < 2; ks++) {
            const int c = ks * 2 + lc;
            uint32_t ah[4][4], al[4][4];
#pragma unroll
            for (int mt = 0; mt < 4; mt++) {
                int r = wm * 64 + mt * 16 + lrow;
                uint32_t off = r * 64 + ((c ^ ((r >> 1) & 3)) << 4);
                LDSM_X4(ah[mt][0], ah[mt][1], ah[mt][2], ah[mt][3], sb + off);
                LDSM_X4(al[mt][0], al[mt][1], al[mt][2], al[mt][3], sb + 8192 + off);
            }
#pragma unroll
            for (int j = 0; j < 4; j++) {
                int r = wn * 64 + 16 * j + lrow;
                uint32_t off = r * 64 + ((c ^ ((r >> 1) & 3)) << 4);
                uint32_t bh4[4], bl4[4];
                LDSM_X4(bh4[0], bh4[1], bh4[2], bh4[3], sb + 16384 + off);
                LDSM_X4(bl4[0], bl4[1], bl4[2], bl4[3], sb + 32768 + off);
#pragma unroll
                for (int half = 0; half < 2; half++) {
                    int nt = 2 * j + half;
#pragma unroll
                    for (int mt = 0; mt < 4; mt++) {
                        mma_b(acc[mt][nt], ah[mt], bh4[half], bh4[half + 2]);
                        mma_b(acc[mt][nt], ah[mt], bl4[half], bl4[half + 2]);
                        mma_b(acc[mt][nt], al[mt], bh4[half], bh4[half + 2]);
                    }
                }
            }
        }
        __syncthreads();
    }

    // ---- epilogue ----
    const int g = lane >> 2, q = lane & 3;
#pragma unroll
    for (int mt = 0; mt < 4; mt++) {
#pragma unroll
        for (int nt = 0; nt < 8; nt++) {
            int row = bm + wm * 64 + mt * 16 + g;
            int col = bn + wn * 64 + nt * 8 + 2 * q;
            if (!regB) {
                *(float2*)&C0[(size_t)row * N + col] =
                    make_float2(acc[mt][nt][0], acc[mt][nt][1]);
                *(float2*)&C0[(size_t)(row + 8) * N + col] =
                    make_float2(acc[mt][nt][2], acc[mt][nt][3]);
            } else {
                uint32_t hp, lp;
                pack_hilo(acc[mt][nt][0], acc[mt][nt][1], hp, lp);
                ((uint32_t*)C1h)[((size_t)row * N + col) >> 1] = hp;
                ((uint32_t*)C1l)[((size_t)row * N + col) >> 1] = lp;
                pack_hilo(acc[mt][nt][2], acc[mt][nt][3], hp, lp);
                ((uint32_t*)C1h)[((size_t)(row + 8) * N + col) >> 1] = hp;
                ((uint32_t*)C1l)[((size_t)(row + 8) * N + col) >> 1] = lp;
            }
        }
    }
}

// ---------------- fused RMSNorm + RoPE -> bf16 hi/lo (warp per row) ----------
__global__ __launch_bounds__(256) void rmsnorm_rope_split(
    const float* __restrict__ x, const float* __restrict__ scale,
    const float* __restrict__ cosT, const float* __restrict__ sinT, int heads,
    float prescale, __nv_bfloat16* __restrict__ oh, __nv_bfloat16* __restrict__ ol)
{
    const int row = blockIdx.x * 8 + (threadIdx.x >> 5);
    const int lane = threadIdx.x & 31;
    const int t = (row / heads) % T_LEN;

    float4 v = ((const float4*)x)[(size_t)row * 32 + lane];
    float ss = v.x * v.x + v.y * v.y + v.z * v.z + v.w * v.w;
#pragma unroll
    for (int m = 16; m > 0; m >>= 1)
        ss += __shfl_xor_sync(0xffffffffu, ss, m);
    float r = rsqrtf(ss * (1.0f / HD) + EPS);

    float4 sc = ((const float4*)scale)[lane];
    float x0 = v.x * r * sc.x, x1 = v.y * r * sc.y;
    float x2 = v.z * r * sc.z, x3 = v.w * r * sc.w;

    float4 cs = ((const float4*)cosT)[t * 32 + lane];
    float4 sn = ((const float4*)sinT)[t * 32 + lane];
    float o0 = (x0 * cs.x - x1 * sn.x) * prescale;
    float o1 = (x1 * cs.y + x0 * sn.y) * prescale;
    float o2 = (x2 * cs.z - x3 * sn.z) * prescale;
    float o3 = (x3 * cs.w + x2 * sn.w) * prescale;

    uint32_t h0, l0, h1, l1;
    pack_hilo(o0, o1, h0, l0);
    pack_hilo(o2, o3, h1, l1);
    ((uint2*)oh)[(size_t)row * 32 + lane] = make_uint2(h0, h1);
    ((uint2*)ol)[(size_t)row * 32 + lane] = make_uint2(l0, l1);
}

// ---------------- 3xBF16 HMMA causal GQA flash attention ----------------------
// BQ=128 (8 warps x m16), BK=64, HD=128. Q persistent smem (64KB) +
// double-buffered K/V hi/lo (2 x 64KB). 256 threads. Output bf16 hi/lo.
#define FA_KV_STAGE 65536
#define FA_SMEM (65536 + 2 * FA_KV_STAGE)
#define SWZ256(r, c) ((uint32_t)((r) * 256 + (((c) ^ ((r) & 7)) << 4)))

__global__ __launch_bounds__(256, 1) void flash_mma(
    const __nv_bfloat16* __restrict__ qh, const __nv_bfloat16* __restrict__ ql,
    const __nv_bfloat16* __restrict__ kh, const __nv_bfloat16* __restrict__ kl,
    const __nv_bfloat16* __restrict__ vh, const __nv_bfloat16* __restrict__ vl,
    __nv_bfloat16* __restrict__ ohp, __nv_bfloat16* __restrict__ olp)
{
    extern __shared__ char fsm[];
    const uint32_t sb = smem_u32(fsm);
    const uint32_t Qh_s = sb, Ql_s = sb + 32768;
    const uint32_t ST = sb + 65536;  // per stage: Kh(16K) Kl Vh Vl

    const int qb = blockIdx.x, h = blockIdx.y, b = blockIdx.z;
    const int kvh = h >> 2;
    const int tid = threadIdx.x;
    const int lane = tid & 31, wid = tid >> 5;
    const int g = lane >> 2, qq = lane & 3;
    const int q0 = qb * 128;
    const int q0w = q0 + wid * 16;
    const int nkv = 2 * qb + 2;

#pragma unroll
    for (int i = 0; i < 16; i++) {
        int id = i * 256 + tid;
        int c = id & 15, r = (id >> 4) & 127, half = id >> 11;
        const __nv_bfloat16* src = half ? ql : qh;
        uint32_t dst = (half ? Ql_s : Qh_s) + SWZ256(r, c);
        CP16(dst, src + ((size_t)(b * T_LEN + q0 + r) * NH + h) * HD + c * 8);
    }
    CP_COMMIT();

    auto issue_kv = [&](int stage, int kt) {
        const int kv0 = kt * 64;
        const uint32_t sbs = ST + stage * FA_KV_STAGE;
#pragma unroll
        for (int i = 0; i < 16; i++) {
            int id = i * 256 + tid;
            int c = id & 15, r = (id >> 4) & 63, arr = id >> 10;  // kh,kl,vh,vl
            const __nv_bfloat16* src =
                (arr == 0) ? kh : (arr == 1) ? kl : (arr == 2) ? vh : vl;
            uint32_t dst = sbs + arr * 16384 + SWZ256(r, c);
            CP16(dst, src + ((size_t)(b * T_LEN + kv0 + r) * NKV + kvh) * HD + c * 8);
        }
    };

    issue_kv(0, 0);
    CP_COMMIT();

    float m0 = -1e30f, m1 = -1e30f, l0 = 0.f, l1 = 0.f;
    float Oacc[16][4];
#pragma unroll
    for (int nt = 0; nt < 16; nt++)
#pragma unroll
        for (int e = 0; e < 4; e++) Oacc[nt][e] = 0.f;

    const int lrow = lane & 15, lc = lane >> 4;

    for (int kt = 0; kt < nkv; kt++) {
        if (kt + 1 < nkv) {
            issue_kv((kt + 1) & 1, kt + 1);
            CP_COMMIT();
            CP_WAIT(1);
        } else {
            CP_WAIT(0);
        }
        __syncthreads();

        const int kv0 = kt * 64;
        const uint32_t sbs = ST + (kt & 1) * FA_KV_STAGE;

        if (kv0 <= q0w + 15) {
            float S[8][4];
#pragma unroll
            for (int nt = 0; nt < 8; nt++)
#pragma unroll
                for (int e = 0; e < 4; e++) S[nt][e] = 0.f;

#pragma unroll
            for (int ks = 0; ks < 8; ks++) {
                const int c = ks * 2 + lc;
                int qr = wid * 16 + lrow;
                uint32_t qoff = SWZ256(qr, c);
                uint32_t aqh[4], aql[4];
                LDSM_X4(aqh[0], aqh[1], aqh[2], aqh[3], Qh_s + qoff);
                LDSM_X4(aql[0], aql[1], aql[2], aql[3], Ql_s + qoff);
#pragma unroll
                for (int j = 0; j < 4; j++) {
                    int r = 16 * j + lrow;
                    uint32_t off = SWZ256(r, c);
                    uint32_t bh4[4], bl4[4];
                    LDSM_X4(bh4[0], bh4[1], bh4[2], bh4[3], sbs + off);
                    LDSM_X4(bl4[0], bl4[1], bl4[2], bl4[3], sbs + 16384 + off);
#pragma unroll
                    for (int half = 0; half < 2; half++) {
                        int nt = 2 * j + half;
                        mma_b(S[nt], aqh, bh4[half], bh4[half + 2]);
                        mma_b(S[nt], aqh, bl4[half], bl4[half + 2]);
                        mma_b(S[nt], aql, bh4[half], bh4[half + 2]);
                    }
                }
            }

            if (kv0 + 63 > q0w) {
#pragma unroll
                for (int nt = 0; nt < 8; nt++) {
                    int col = kv0 + nt * 8 + qq * 2;
                    int r0 = q0w + g, r1 = q0w + g + 8;
                    if (col > r0) S[nt][0] = -1e30f;
                    if (col + 1 > r0) S[nt][1] = -1e30f;
                    if (col > r1) S[nt][2] = -1e30f;
                    if (col + 1 > r1) S[nt][3] = -1e30f;
                }
            }

            float mx0 = -1e30f, mx1 = -1e30f;
#pragma unroll
            for (int nt = 0; nt < 8; nt++) {
                mx0 = fmaxf(mx0, fmaxf(S[nt][0], S[nt][1]));
                mx1 = fmaxf(mx1, fmaxf(S[nt][2], S[nt][3]));
            }
            mx0 = fmaxf(mx0, __shfl_xor_sync(0xffffffffu, mx0, 1));
            mx0 = fmaxf(mx0, __shfl_xor_sync(0xffffffffu, mx0, 2));
            mx1 = fmaxf(mx1, __shfl_xor_sync(0xffffffffu, mx1, 1));
            mx1 = fmaxf(mx1, __shfl_xor_sync(0xffffffffu, mx1, 2));
            float mn0 = fmaxf(m0, mx0), mn1 = fmaxf(m1, mx1);
            float al0 = exp2f(m0 - mn0), al1 = exp2f(m1 - mn1);
            m0 = mn0; m1 = mn1;
            float sum0 = 0.f, sum1 = 0.f;
#pragma unroll
            for (int nt = 0; nt < 8; nt++) {
                S[nt][0] = exp2f(S[nt][0] - mn0);
                S[nt][1] = exp2f(S[nt][1] - mn0);
                S[nt][2] = exp2f(S[nt][2] - mn1);
                S[nt][3] = exp2f(S[nt][3] - mn1);
                sum0 += S[nt][0] + S[nt][1];
                sum1 += S[nt][2] + S[nt][3];
            }
            sum0 += __shfl_xor_sync(0xffffffffu, sum0, 1);
            sum0 += __shfl_xor_sync(0xffffffffu, sum0, 2);
            sum1 += __shfl_xor_sync(0xffffffffu, sum1, 1);
            sum1 += __shfl_xor_sync(0xffffffffu, sum1, 2);
            l0 = l0 * al0 + sum0;
            l1 = l1 * al1 + sum1;
#pragma unroll
            for (int nt = 0; nt < 16; nt++) {
                Oacc[nt][0] *= al0; Oacc[nt][1] *= al0;
                Oacc[nt][2] *= al1; Oacc[nt][3] *= al1;
            }

            uint32_t Ph[4][4], Pl[4][4];
#pragma unroll
            for (int ktp = 0; ktp < 4; ktp++) {
                pack_hilo(S[2 * ktp][0], S[2 * ktp][1], Ph[ktp][0], Pl[ktp][0]);
                pack_hilo(S[2 * ktp][2], S[2 * ktp][3], Ph[ktp][1], Pl[ktp][1]);
                pack_hilo(S[2 * ktp + 1][0], S[2 * ktp + 1][1], Ph[ktp][2], Pl[ktp][2]);
                pack_hilo(S[2 * ktp + 1][2], S[2 * ktp + 1][3], Ph[ktp][3], Pl[ktp][3]);
            }

#pragma unroll
            for (int ktp = 0; ktp < 4; ktp++) {
#pragma unroll
                for (int j = 0; j < 8; j++) {
                    int r = ktp * 16 + lrow;
                    int c = 2 * j + lc;
                    uint32_t off = SWZ256(r, c);
                    uint32_t v0, v1, v2, v3, w0, w1, w2, w3;
                    LDSM_X4_T(v0, v1, v2, v3, sbs + 32768 + off);
                    LDSM_X4_T(w0, w1, w2, w3, sbs + 49152 + off);
                    mma_b(Oacc[2 * j], Ph[ktp], v0, v1);
                    mma_b(Oacc[2 * j], Ph[ktp], w0, w1);
                    mma_b(Oacc[2 * j], Pl[ktp], v0, v1);
                    mma_b(Oacc[2 * j + 1], Ph[ktp], v2, v3);
                    mma_b(Oacc[2 * j + 1], Ph[ktp], w2, w3);
                    mma_b(Oacc[2 * j + 1], Pl[ktp], v2, v3);
                }
            }
        }
        __syncthreads();
    }

    // ---- write O as bf16 hi/lo (att layout [b*T, NH*HD]) ----
    float inv0 = 1.f / l0, inv1 = 1.f / l1;
    const size_t base0 = (size_t)(b * T_LEN + q0w + g) * (NH * HD) + h * HD;
    const size_t base1 = base0 + (size_t)8 * NH * HD;
#pragma unroll
    for (int nt = 0; nt < 16; nt++) {
        int col = nt * 8 + qq * 2;
        uint32_t hp, lp;
        pack_hilo(Oacc[nt][0] * inv0, Oacc[nt][1] * inv0, hp, lp);
        ((uint32_t*)ohp)[(base0 + col) >> 1] = hp;
        ((uint32_t*)olp)[(base0 + col) >> 1] = lp;
        pack_hilo(Oacc[nt][2] * inv1, Oacc[nt][3] * inv1, hp, lp);
        ((uint32_t*)ohp)[(base1 + col) >> 1] = hp;
        ((uint32_t*)olp)[(base1 + col) >> 1] = lp;
    }
}

// ---------------- launcher ---------------------------------------------------
extern "C" void kernel_launch(void* const* d_in, const int* in_sizes, int n_in,
                              void* d_out, int out_size)
{
    const float* x       = (const float*)d_in[0];
    const float* Wq      = (const float*)d_in[1];
    const float* Wk      = (const float*)d_in[2];
    const float* Wv      = (const float*)d_in[3];
    const float* Wo      = (const float*)d_in[4];
    const float* q_scale = (const float*)d_in[5];
    const float* k_scale = (const float*)d_in[6];
    const float* cosT    = (const float*)d_in[7];
    const float* sinT    = (const float*)d_in[8];
    float* out = (float*)d_out;

    float *pq, *pk;
    cudaGetSymbolAddress((void**)&pq, g_q);
    cudaGetSymbolAddress((void**)&pk, g_k);
    __nv_bfloat16 *xh, *xl, *ah, *al, *wqh, *wql, *wkh, *wkl, *wvh, *wvl, *woh, *wol;
    __nv_bfloat16 *qh, *ql, *khp, *klp, *vhp, *vlp;
    cudaGetSymbolAddress((void**)&xh, g_xh);  cudaGetSymbolAddress((void**)&xl, g_xl);
    cudaGetSymbolAddress((void**)&ah, g_ah);  cudaGetSymbolAddress((void**)&al, g_al);
    cudaGetSymbolAddress((void**)&wqh, g_wqh); cudaGetSymbolAddress((void**)&wql, g_wql);
    cudaGetSymbolAddress((void**)&wkh, g_wkh); cudaGetSymbolAddress((void**)&wkl, g_wkl);
    cudaGetSymbolAddress((void**)&wvh, g_wvh); cudaGetSymbolAddress((void**)&wvl, g_wvl);
    cudaGetSymbolAddress((void**)&woh, g_woh); cudaGetSymbolAddress((void**)&wol, g_wol);
    cudaGetSymbolAddress((void**)&qh, g_qh);   cudaGetSymbolAddress((void**)&ql, g_ql);
    cudaGetSymbolAddress((void**)&khp, g_kh);  cudaGetSymbolAddress((void**)&klp, g_kl);
    cudaGetSymbolAddress((void**)&vhp, g_vh);  cudaGetSymbolAddress((void**)&vlp, g_vl);

    static bool attr_set = false;
    if (!attr_set) {
        cudaFuncSetAttribute(mma_gemm, cudaFuncAttributeMaxDynamicSharedMemorySize, GEMM_SMEM);
        cudaFuncSetAttribute(flash_mma, cudaFuncAttributeMaxDynamicSharedMemorySize, FA_SMEM);
        attr_set = true;
    }

    const int M = M_ROWS;  // 4096

    // one-time conversions
    cvt_hilo<<<(M * D_MODEL / 4 + 255) / 256, 256>>>((const float4*)x, (uint2*)xh, (uint2*)xl, M * D_MODEL / 4);
    trans_cvt<<<dim3(D_MODEL / 32, D_MODEL / 32), 256>>>(Wq, wqh, wql, D_MODEL, D_MODEL);
    trans_cvt<<<dim3(NKV * HD / 32, D_MODEL / 32), 256>>>(Wk, wkh, wkl, D_MODEL, NKV * HD);
    trans_cvt<<<dim3(NKV * HD / 32, D_MODEL / 32), 256>>>(Wv, wvh, wvl, D_MODEL, NKV * HD);
    trans_cvt<<<dim3(D_MODEL / 32, D_MODEL / 32), 256>>>(Wo, woh, wol, NH * HD, D_MODEL);

    // Q projection: fp32 out (rmsnorm follows)
    mma_gemm<<<dim3(8, M / 128), 256, GEMM_SMEM>>>(
        xh, xl, wqh, wql, nullptr, nullptr, pq, nullptr, nullptr,
        D_MODEL, 8, D_MODEL, 0);
    // K (fp32 out) + V (bf16 hi/lo out) merged
    mma_gemm<<<dim3(4, M / 128), 256, GEMM_SMEM>>>(
        xh, xl, wkh, wkl, wvh, wvl, pk, vhp, vlp,
        D_MODEL, 2, NKV * HD, NKV * HD);

    // RMSNorm + RoPE -> bf16 hi/lo (q pre-scaled by log2(e)/sqrt(HD))
    const float qk_scale = 1.4426950408889634f * 0.08838834764831845f;
    rmsnorm_rope_split<<<M * NH / 8, 256>>>(pq, q_scale, cosT, sinT, NH, qk_scale, qh, ql);
    rmsnorm_rope_split<<<M * NKV / 8, 256>>>(pk, k_scale, cosT, sinT, NKV, 1.0f, khp, klp);

    // flash attention -> bf16 hi/lo
    flash_mma<<<dim3(T_LEN / 128, NH, BATCH), 256, FA_SMEM>>>(
        qh, ql, khp, klp, vhp, vlp, ah, al);

    // output projection (fp32 out)
    mma_gemm<<<dim3(8, M / 128), 256, GEMM_SMEM>>>(
        ah, al, woh, wol, nullptr, nullptr, out, nullptr, nullptr,
        D_MODEL, 8, D_MODEL, 0);
}

// round 7
// speedup vs baseline: 5.8844x; 1.3542x over previous
#include <cuda_runtime.h>
#include <cuda_fp16.h>
#include <math.h>
#include <stdint.h>

// Problem constants
#define BATCH 2
#define T_LEN 2048
#define D_MODEL 2048
#define NH 16
#define NKV 4
#define HD 128
#define EPS 1e-6f
#define M_ROWS (BATCH * T_LEN)  // 4096

// ---------------- scratch (device globals; no allocation allowed) ----------
__device__ float g_q[M_ROWS * NH * HD];
__device__ float g_k[M_ROWS * NKV * HD];

__device__ __half g_xh[M_ROWS * D_MODEL], g_xl[M_ROWS * D_MODEL];
__device__ __half g_ah[M_ROWS * D_MODEL], g_al[M_ROWS * D_MODEL];
__device__ __half g_wq[D_MODEL * D_MODEL];      // [N,K] transposed
__device__ __half g_wk[NKV * HD * D_MODEL];
__device__ __half g_wv[NKV * HD * D_MODEL];
__device__ __half g_wo[D_MODEL * D_MODEL];

__device__ __half g_qh[M_ROWS * NH * HD], g_ql[M_ROWS * NH * HD];
__device__ __half g_kh[M_ROWS * NKV * HD];
__device__ __half g_vh[M_ROWS * NKV * HD];

// ---------------- helpers -----------------------------------------------------
__device__ __forceinline__ uint32_t smem_u32(const void* p) {
    uint32_t a;
    asm("{ .reg .u64 t; cvta.to.shared.u64 t, %1; cvt.u32.u64 %0, t; }"
        : "=r"(a) : "l"(p));
    return a;
}

#define CP16(dst, src) \
    asm volatile("cp.async.cg.shared.global [%0], [%1], 16;" :: "r"(dst), "l"(src))
#define CP_COMMIT() asm volatile("cp.async.commit_group;" ::: "memory")
#define CP_WAIT(n)  asm volatile("cp.async.wait_group %0;" :: "n"(n) : "memory")

#define LDSM_X4(r0, r1, r2, r3, addr) \
    asm volatile("ldmatrix.sync.aligned.m8n8.x4.shared.b16 {%0,%1,%2,%3}, [%4];" \
                 : "=r"(r0), "=r"(r1), "=r"(r2), "=r"(r3) : "r"(addr))
#define LDSM_X4_T(r0, r1, r2, r3, addr) \
    asm volatile("ldmatrix.sync.aligned.m8n8.x4.trans.shared.b16 {%0,%1,%2,%3}, [%4];" \
                 : "=r"(r0), "=r"(r1), "=r"(r2), "=r"(r3) : "r"(addr))

__device__ __forceinline__ void mma_h(float* c, const uint32_t* a, uint32_t b0, uint32_t b1) {
    asm volatile(
        "mma.sync.aligned.m16n8k16.row.col.f32.f16.f16.f32 "
        "{%0,%1,%2,%3}, {%4,%5,%6,%7}, {%8,%9}, {%0,%1,%2,%3};"
        : "+f"(c[0]), "+f"(c[1]), "+f"(c[2]), "+f"(c[3])
        : "r"(a[0]), "r"(a[1]), "r"(a[2]), "r"(a[3]), "r"(b0), "r"(b1));
}

// pack two fp32 (x -> low half, y -> high half) into f16x2 hi + residual lo
__device__ __forceinline__ void pack_hilo(float x, float y, uint32_t& hp, uint32_t& lp) {
    __half2 h = __floats2half2_rn(x, y);
    hp = *reinterpret_cast<uint32_t*>(&h);
    float lx = x - __half2float(__low2half(h));
    float ly = y - __half2float(__high2half(h));
    __half2 l = __floats2half2_rn(lx, ly);
    lp = *reinterpret_cast<uint32_t*>(&l);
}

__device__ __forceinline__ uint32_t pack_h2(float x, float y) {
    __half2 h = __floats2half2_rn(x, y);
    return *reinterpret_cast<uint32_t*>(&h);
}

// ---------------- conversion kernels -----------------------------------------
__global__ __launch_bounds__(256) void cvt_hilo(
    const float4* __restrict__ src, uint2* __restrict__ hi, uint2* __restrict__ lo, int n4)
{
    int i = blockIdx.x * 256 + threadIdx.x;
    if (i >= n4) return;
    float4 v = src[i];
    uint32_t h0, l0, h1, l1;
    pack_hilo(v.x, v.y, h0, l0);
    pack_hilo(v.z, v.w, h1, l1);
    hi[i] = make_uint2(h0, h1);
    lo[i] = make_uint2(l0, l1);
}

// W [K,N] fp32 -> T [N,K] fp16 (transpose + round)
__global__ __launch_bounds__(256) void trans_cvt(
    const float* __restrict__ W, __half* __restrict__ T, int K, int N)
{
    __shared__ float tile[32][33];
    const int n0 = blockIdx.x * 32, k0 = blockIdx.y * 32;
    const int tx = threadIdx.x & 31, ty4 = (threadIdx.x >> 5) * 4;
#pragma unroll
    for (int i = 0; i < 4; i++)
        tile[ty4 + i][tx] = W[(size_t)(k0 + ty4 + i) * N + n0 + tx];
    __syncthreads();
#pragma unroll
    for (int i = 0; i < 4; i++)
        T[(size_t)(n0 + ty4 + i) * K + k0 + tx] = __float2half_rn(tile[tx][ty4 + i]);
}

// ---------------- 2xFP16 HMMA GEMM, 128x256 tile, 3-stage cp.async ------------
// C[M,N] = (Ah+Al)[M,K] @ Bt[N,K]^T, B single fp16. 256 threads, warps 2x4,
// warp tile 64x64. Up to 3 B-regions selected by blockIdx.x.
// Smem rows 64B, swizzle chunk' = c ^ ((r>>1)&3).
#define G_STAGE 32768
#define GEMM_SMEM (3 * G_STAGE)

__global__ __launch_bounds__(256) void mma_gemm(
    const __half* __restrict__ Ahp, const __half* __restrict__ Alp,
    const __half* __restrict__ B0, const __half* __restrict__ B1,
    const __half* __restrict__ B2,
    float* __restrict__ C0, float* __restrict__ C1, __half* __restrict__ C2,
    int K, int n0, int n1, int N0, int N1, int N2)
{
    extern __shared__ char smem[];
    const uint32_t sbase = smem_u32(smem);

    const int tid = threadIdx.x;
    const int lane = tid & 31, wid = tid >> 5;
    const int wm = wid >> 2, wn = wid & 3;
    const int bx = blockIdx.x;
    int region, bn, N;
    const __half* B;
    if (bx < n0)           { region = 0; bn = bx * 256;            B = B0; N = N0; }
    else if (bx < n0 + n1) { region = 1; bn = (bx - n0) * 256;     B = B1; N = N1; }
    else                   { region = 2; bn = (bx - n0 - n1) * 256; B = B2; N = N2; }
    const int bm = blockIdx.y * 128;
    const int NT = K / 32;

    float acc[4][8][4];
#pragma unroll
    for (int i = 0; i < 4; i++)
#pragma unroll
        for (int j = 0; j < 8; j++)
#pragma unroll
            for (int l = 0; l < 4; l++) acc[i][j][l] = 0.f;

    auto issue = [&](int it) {
        const int k0 = it * 32;
        const uint32_t sb = sbase + (it % 3) * G_STAGE;
#pragma unroll
        for (int i = 0; i < 8; i++) {
            int id = i * 256 + tid;          // 0..2047
            if (id < 1024) {                 // A: 128 rows x 4 chunks x 2 halves
                int half = id >> 9, r = (id >> 2) & 127, c = id & 3;
                const __half* src = half ? Alp : Ahp;
                uint32_t dst = sb + half * 8192 + r * 64 + ((c ^ ((r >> 1) & 3)) << 4);
                CP16(dst, src + (size_t)(bm + r) * K + k0 + c * 8);
            } else {                         // B: 256 rows x 4 chunks
                int idb = id - 1024;
                int r = (idb >> 2) & 255, c = idb & 3;
                uint32_t dst = sb + 16384 + r * 64 + ((c ^ ((r >> 1) & 3)) << 4);
                CP16(dst, B + (size_t)(bn + r) * K + k0 + c * 8);
            }
        }
    };

    issue(0); CP_COMMIT();
    issue(1); CP_COMMIT();

    const int lrow = lane & 15, lc = lane >> 4;

    for (int it = 0; it < NT; ++it) {
        if (it + 1 < NT) { CP_WAIT(1); } else { CP_WAIT(0); }
        __syncthreads();
        if (it + 2 < NT) { issue(it + 2); CP_COMMIT(); }

        const uint32_t sb = sbase + (it % 3) * G_STAGE;
#pragma unroll
        for (int ks = 0; ks < 2; ks++) {
            const int c = ks * 2 + lc;
            uint32_t ah[4][4], al[4][4];
#pragma unroll
            for (int mt = 0; mt < 4; mt++) {
                int r = wm * 64 + mt * 16 + lrow;
                uint32_t off = r * 64 + ((c ^ ((r >> 1) & 3)) << 4);
                LDSM_X4(ah[mt][0], ah[mt][1], ah[mt][2], ah[mt][3], sb + off);
                LDSM_X4(al[mt][0], al[mt][1], al[mt][2], al[mt][3], sb + 8192 + off);
            }
#pragma unroll
            for (int j = 0; j < 4; j++) {
                int r = wn * 64 + 16 * j + lrow;
                uint32_t off = r * 64 + ((c ^ ((r >> 1) & 3)) << 4);
                uint32_t b4[4];
                LDSM_X4(b4[0], b4[1], b4[2], b4[3], sb + 16384 + off);
#pragma unroll
                for (int half = 0; half < 2; half++) {
                    int nt = 2 * j + half;
#pragma unroll
                    for (int mt = 0; mt < 4; mt++) {
                        mma_h(acc[mt][nt], ah[mt], b4[half], b4[half + 2]);
                        mma_h(acc[mt][nt], al[mt], b4[half], b4[half + 2]);
                    }
                }
            }
        }
        __syncthreads();
    }

    // ---- epilogue ----
    const int g = lane >> 2, q = lane & 3;
    float* Cf = (region == 0) ? C0 : C1;
#pragma unroll
    for (int mt = 0; mt < 4; mt++) {
#pragma unroll
        for (int nt = 0; nt < 8; nt++) {
            int row = bm + wm * 64 + mt * 16 + g;
            int col = bn + wn * 64 + nt * 8 + 2 * q;
            if (region < 2) {
                *(float2*)&Cf[(size_t)row * N + col] =
                    make_float2(acc[mt][nt][0], acc[mt][nt][1]);
                *(float2*)&Cf[(size_t)(row + 8) * N + col] =
                    make_float2(acc[mt][nt][2], acc[mt][nt][3]);
            } else {
                ((uint32_t*)C2)[((size_t)row * N + col) >> 1] =
                    pack_h2(acc[mt][nt][0], acc[mt][nt][1]);
                ((uint32_t*)C2)[((size_t)(row + 8) * N + col) >> 1] =
                    pack_h2(acc[mt][nt][2], acc[mt][nt][3]);
            }
        }
    }
}

// ---------------- fused RMSNorm + RoPE -> fp16 hi(/lo) (warp per row) --------
__global__ __launch_bounds__(256) void rmsnorm_rope_split(
    const float* __restrict__ x, const float* __restrict__ scale,
    const float* __restrict__ cosT, const float* __restrict__ sinT, int heads,
    float prescale, __half* __restrict__ oh, __half* __restrict__ ol)
{
    const int row = blockIdx.x * 8 + (threadIdx.x >> 5);
    const int lane = threadIdx.x & 31;
    const int t = (row / heads) % T_LEN;

    float4 v = ((const float4*)x)[(size_t)row * 32 + lane];
    float ss = v.x * v.x + v.y * v.y + v.z * v.z + v.w * v.w;
#pragma unroll
    for (int m = 16; m > 0; m >>= 1)
        ss += __shfl_xor_sync(0xffffffffu, ss, m);
    float r = rsqrtf(ss * (1.0f / HD) + EPS);

    float4 sc = ((const float4*)scale)[lane];
    float x0 = v.x * r * sc.x, x1 = v.y * r * sc.y;
    float x2 = v.z * r * sc.z, x3 = v.w * r * sc.w;

    float4 cs = ((const float4*)cosT)[t * 32 + lane];
    float4 sn = ((const float4*)sinT)[t * 32 + lane];
    float o0 = (x0 * cs.x - x1 * sn.x) * prescale;
    float o1 = (x1 * cs.y + x0 * sn.y) * prescale;
    float o2 = (x2 * cs.z - x3 * sn.z) * prescale;
    float o3 = (x3 * cs.w + x2 * sn.w) * prescale;

    uint32_t h0, l0, h1, l1;
    pack_hilo(o0, o1, h0, l0);
    pack_hilo(o2, o3, h1, l1);
    ((uint2*)oh)[(size_t)row * 32 + lane] = make_uint2(h0, h1);
    if (ol)
        ((uint2*)ol)[(size_t)row * 32 + lane] = make_uint2(l0, l1);
}

// ---------------- 2xFP16 HMMA causal GQA flash attention ----------------------
// BQ=128 (8 warps x m16), BK=64, HD=128. Q hi/lo persistent (64KB) +
// double-buffered K/V single fp16 (2 x 32KB). 256 threads. Output fp16 hi/lo.
#define FA_KV_STAGE 32768
#define FA_SMEM (65536 + 2 * FA_KV_STAGE)
#define SWZ256(r, c) ((uint32_t)((r) * 256 + (((c) ^ ((r) & 7)) << 4)))

__global__ __launch_bounds__(256, 1) void flash_mma(
    const __half* __restrict__ qh, const __half* __restrict__ ql,
    const __half* __restrict__ kh, const __half* __restrict__ vh,
    __half* __restrict__ ohp, __half* __restrict__ olp)
{
    extern __shared__ char fsm[];
    const uint32_t sb = smem_u32(fsm);
    const uint32_t Qh_s = sb, Ql_s = sb + 32768;
    const uint32_t ST = sb + 65536;  // per stage: Kh(16K) Vh(16K)

    const int qb = (int)gridDim.x - 1 - (int)blockIdx.x;  // heavy tiles first
    const int h = blockIdx.y, b = blockIdx.z;
    const int kvh = h >> 2;
    const int tid = threadIdx.x;
    const int lane = tid & 31, wid = tid >> 5;
    const int g = lane >> 2, qq = lane & 3;
    const int q0 = qb * 128;
    const int q0w = q0 + wid * 16;
    const int nkv = 2 * qb + 2;

#pragma unroll
    for (int i = 0; i < 16; i++) {
        int id = i * 256 + tid;
        int c = id & 15, r = (id >> 4) & 127, half = id >> 11;
        const __half* src = half ? ql : qh;
        uint32_t dst = (half ? Ql_s : Qh_s) + SWZ256(r, c);
        CP16(dst, src + ((size_t)(b * T_LEN + q0 + r) * NH + h) * HD + c * 8);
    }
    CP_COMMIT();

    auto issue_kv = [&](int stage, int kt) {
        const int kv0 = kt * 64;
        const uint32_t sbs = ST + stage * FA_KV_STAGE;
#pragma unroll
        for (int i = 0; i < 8; i++) {
            int id = i * 256 + tid;
            int c = id & 15, r = (id >> 4) & 63, arr = id >> 10;  // kh, vh
            const __half* src = arr ? vh : kh;
            uint32_t dst = sbs + arr * 16384 + SWZ256(r, c);
            CP16(dst, src + ((size_t)(b * T_LEN + kv0 + r) * NKV + kvh) * HD + c * 8);
        }
    };

    issue_kv(0, 0);
    CP_COMMIT();

    float m0 = -1e30f, m1 = -1e30f, l0 = 0.f, l1 = 0.f;
    float Oacc[16][4];
#pragma unroll
    for (int nt = 0; nt < 16; nt++)
#pragma unroll
        for (int e = 0; e < 4; e++) Oacc[nt][e] = 0.f;

    const int lrow = lane & 15, lc = lane >> 4;

    for (int kt = 0; kt < nkv; kt++) {
        if (kt + 1 < nkv) {
            issue_kv((kt + 1) & 1, kt + 1);
            CP_COMMIT();
            CP_WAIT(1);
        } else {
            CP_WAIT(0);
        }
        __syncthreads();

        const int kv0 = kt * 64;
        const uint32_t sbs = ST + (kt & 1) * FA_KV_STAGE;

        if (kv0 <= q0w + 15) {
            float S[8][4];
#pragma unroll
            for (int nt = 0; nt < 8; nt++)
#pragma unroll
                for (int e = 0; e < 4; e++) S[nt][e] = 0.f;

#pragma unroll
            for (int ks = 0; ks < 8; ks++) {
                const int c = ks * 2 + lc;
                int qr = wid * 16 + lrow;
                uint32_t qoff = SWZ256(qr, c);
                uint32_t aqh[4], aql[4];
                LDSM_X4(aqh[0], aqh[1], aqh[2], aqh[3], Qh_s + qoff);
                LDSM_X4(aql[0], aql[1], aql[2], aql[3], Ql_s + qoff);
#pragma unroll
                for (int j = 0; j < 4; j++) {
                    int r = 16 * j + lrow;
                    uint32_t off = SWZ256(r, c);
                    uint32_t b4[4];
                    LDSM_X4(b4[0], b4[1], b4[2], b4[3], sbs + off);
#pragma unroll
                    for (int half = 0; half < 2; half++) {
                        int nt = 2 * j + half;
                        mma_h(S[nt], aqh, b4[half], b4[half + 2]);
                        mma_h(S[nt], aql, b4[half], b4[half + 2]);
                    }
                }
            }

            if (kv0 + 63 > q0w) {
#pragma unroll
                for (int nt = 0; nt < 8; nt++) {
                    int col = kv0 + nt * 8 + qq * 2;
                    int r0 = q0w + g, r1 = q0w + g + 8;
                    if (col > r0) S[nt][0] = -1e30f;
                    if (col + 1 > r0) S[nt][1] = -1e30f;
                    if (col > r1) S[nt][2] = -1e30f;
                    if (col + 1 > r1) S[nt][3] = -1e30f;
                }
            }

            float mx0 = -1e30f, mx1 = -1e30f;
#pragma unroll
            for (int nt = 0; nt < 8; nt++) {
                mx0 = fmaxf(mx0, fmaxf(S[nt][0], S[nt][1]));
                mx1 = fmaxf(mx1, fmaxf(S[nt][2], S[nt][3]));
            }
            mx0 = fmaxf(mx0, __shfl_xor_sync(0xffffffffu, mx0, 1));
            mx0 = fmaxf(mx0, __shfl_xor_sync(0xffffffffu, mx0, 2));
            mx1 = fmaxf(mx1, __shfl_xor_sync(0xffffffffu, mx1, 1));
            mx1 = fmaxf(mx1, __shfl_xor_sync(0xffffffffu, mx1, 2));
            float mn0 = fmaxf(m0, mx0), mn1 = fmaxf(m1, mx1);
            float al0 = exp2f(m0 - mn0), al1 = exp2f(m1 - mn1);
            m0 = mn0; m1 = mn1;
            float sum0 = 0.f, sum1 = 0.f;
#pragma unroll
            for (int nt = 0; nt < 8; nt++) {
                S[nt][0] = exp2f(S[nt][0] - mn0);
                S[nt][1] = exp2f(S[nt][1] - mn0);
                S[nt][2] = exp2f(S[nt][2] - mn1);
                S[nt][3] = exp2f(S[nt][3] - mn1);
                sum0 += S[nt][0] + S[nt][1];
                sum1 += S[nt][2] + S[nt][3];
            }
            sum0 += __shfl_xor_sync(0xffffffffu, sum0, 1);
            sum0 += __shfl_xor_sync(0xffffffffu, sum0, 2);
            sum1 += __shfl_xor_sync(0xffffffffu, sum1, 1);
            sum1 += __shfl_xor_sync(0xffffffffu, sum1, 2);
            l0 = l0 * al0 + sum0;
            l1 = l1 * al1 + sum1;
#pragma unroll
            for (int nt = 0; nt < 16; nt++) {
                Oacc[nt][0] *= al0; Oacc[nt][1] *= al0;
                Oacc[nt][2] *= al1; Oacc[nt][3] *= al1;
            }

            uint32_t Ph[4][4], Pl[4][4];
#pragma unroll
            for (int ktp = 0; ktp < 4; ktp++) {
                pack_hilo(S[2 * ktp][0], S[2 * ktp][1], Ph[ktp][0], Pl[ktp][0]);
                pack_hilo(S[2 * ktp][2], S[2 * ktp][3], Ph[ktp][1], Pl[ktp][1]);
                pack_hilo(S[2 * ktp + 1][0], S[2 * ktp + 1][1], Ph[ktp][2], Pl[ktp][2]);
                pack_hilo(S[2 * ktp + 1][2], S[2 * ktp + 1][3], Ph[ktp][3], Pl[ktp][3]);
            }

#pragma unroll
            for (int ktp = 0; ktp < 4; ktp++) {
#pragma unroll
                for (int j = 0; j < 8; j++) {
                    int r = ktp * 16 + lrow;
                    int c = 2 * j + lc;
                    uint32_t off = SWZ256(r, c);
                    uint32_t v0, v1, v2, v3;
                    LDSM_X4_T(v0, v1, v2, v3, sbs + 16384 + off);
                    mma_h(Oacc[2 * j], Ph[ktp], v0, v1);
                    mma_h(Oacc[2 * j], Pl[ktp], v0, v1);
                    mma_h(Oacc[2 * j + 1], Ph[ktp], v2, v3);
                    mma_h(Oacc[2 * j + 1], Pl[ktp], v2, v3);
                }
            }
        }
        __syncthreads();
    }

    // ---- write O as fp16 hi/lo (att layout [b*T, NH*HD]) ----
    float inv0 = 1.f / l0, inv1 = 1.f / l1;
    const size_t base0 = (size_t)(b * T_LEN + q0w + g) * (NH * HD) + h * HD;
    const size_t base1 = base0 + (size_t)8 * NH * HD;
#pragma unroll
    for (int nt = 0; nt < 16; nt++) {
        int col = nt * 8 + qq * 2;
        uint32_t hp, lp;
        pack_hilo(Oacc[nt][0] * inv0, Oacc[nt][1] * inv0, hp, lp);
        ((uint32_t*)ohp)[(base0 + col) >> 1] = hp;
        ((uint32_t*)olp)[(base0 + col) >> 1] = lp;
        pack_hilo(Oacc[nt][2] * inv1, Oacc[nt][3] * inv1, hp, lp);
        ((uint32_t*)ohp)[(base1 + col) >> 1] = hp;
        ((uint32_t*)olp)[(base1 + col) >> 1] = lp;
    }
}

// ---------------- launcher ---------------------------------------------------
extern "C" void kernel_launch(void* const* d_in, const int* in_sizes, int n_in,
                              void* d_out, int out_size)
{
    const float* x       = (const float*)d_in[0];
    const float* Wq      = (const float*)d_in[1];
    const float* Wk      = (const float*)d_in[2];
    const float* Wv      = (const float*)d_in[3];
    const float* Wo      = (const float*)d_in[4];
    const float* q_scale = (const float*)d_in[5];
    const float* k_scale = (const float*)d_in[6];
    const float* cosT    = (const float*)d_in[7];
    const float* sinT    = (const float*)d_in[8];
    float* out = (float*)d_out;

    float *pq, *pk;
    cudaGetSymbolAddress((void**)&pq, g_q);
    cudaGetSymbolAddress((void**)&pk, g_k);
    __half *xh, *xl, *ah, *al, *wq, *wk, *wv, *wo, *qh, *ql, *kh, *vh;
    cudaGetSymbolAddress((void**)&xh, g_xh);  cudaGetSymbolAddress((void**)&xl, g_xl);
    cudaGetSymbolAddress((void**)&ah, g_ah);  cudaGetSymbolAddress((void**)&al, g_al);
    cudaGetSymbolAddress((void**)&wq, g_wq);  cudaGetSymbolAddress((void**)&wk, g_wk);
    cudaGetSymbolAddress((void**)&wv, g_wv);  cudaGetSymbolAddress((void**)&wo, g_wo);
    cudaGetSymbolAddress((void**)&qh, g_qh);  cudaGetSymbolAddress((void**)&ql, g_ql);
    cudaGetSymbolAddress((void**)&kh, g_kh);  cudaGetSymbolAddress((void**)&vh, g_vh);

    static bool attr_set = false;
    if (!attr_set) {
        cudaFuncSetAttribute(mma_gemm, cudaFuncAttributeMaxDynamicSharedMemorySize, GEMM_SMEM);
        cudaFuncSetAttribute(flash_mma, cudaFuncAttributeMaxDynamicSharedMemorySize, FA_SMEM);
        attr_set = true;
    }

    const int M = M_ROWS;  // 4096

    // one-time conversions
    cvt_hilo<<<(M * D_MODEL / 4 + 255) / 256, 256>>>((const float4*)x, (uint2*)xh, (uint2*)xl, M * D_MODEL / 4);
    trans_cvt<<<dim3(D_MODEL / 32, D_MODEL / 32), 256>>>(Wq, wq, D_MODEL, D_MODEL);
    trans_cvt<<<dim3(NKV * HD / 32, D_MODEL / 32), 256>>>(Wk, wk, D_MODEL, NKV * HD);
    trans_cvt<<<dim3(NKV * HD / 32, D_MODEL / 32), 256>>>(Wv, wv, D_MODEL, NKV * HD);
    trans_cvt<<<dim3(D_MODEL / 32, D_MODEL / 32), 256>>>(Wo, wo, NH * HD, D_MODEL);

    // merged Q + K + V projections (one launch, 3 B-regions)
    mma_gemm<<<dim3(12, M / 128), 256, GEMM_SMEM>>>(
        xh, xl, wq, wk, wv, pq, pk, vh,
        D_MODEL, 8, 2, D_MODEL, NKV * HD, NKV * HD);

    // RMSNorm + RoPE (q pre-scaled by log2(e)/sqrt(HD); k -> hi only)
    const float qk_scale = 1.4426950408889634f * 0.08838834764831845f;
    rmsnorm_rope_split<<<M * NH / 8, 256>>>(pq, q_scale, cosT, sinT, NH, qk_scale, qh, ql);
    rmsnorm_rope_split<<<M * NKV / 8, 256>>>(pk, k_scale, cosT, sinT, NKV, 1.0f, kh, nullptr);

    // flash attention -> fp16 hi/lo
    flash_mma<<<dim3(T_LEN / 128, NH, BATCH), 256, FA_SMEM>>>(qh, ql, kh, vh, ah, al);

    // output projection (fp32 out)
    mma_gemm<<<dim3(8, M / 128), 256, GEMM_SMEM>>>(
        ah, al, wo, nullptr, nullptr, out, nullptr, nullptr,
        D_MODEL, 8, 0, D_MODEL, 0, 0);
}

// round 8
// speedup vs baseline: 6.0919x; 1.0353x over previous
#include <cuda_runtime.h>
#include <cuda_fp16.h>
#include <math.h>
#include <stdint.h>

// Problem constants
#define BATCH 2
#define T_LEN 2048
#define D_MODEL 2048
#define NH 16
#define NKV 4
#define HD 128
#define EPS 1e-6f
#define M_ROWS (BATCH * T_LEN)  // 4096

// ---------------- scratch (device globals; no allocation allowed) ----------
__device__ float g_q[M_ROWS * NH * HD];
__device__ float g_k[M_ROWS * NKV * HD];

__device__ __half g_xh[M_ROWS * D_MODEL], g_xl[M_ROWS * D_MODEL];
__device__ __half g_ah[M_ROWS * D_MODEL], g_al[M_ROWS * D_MODEL];
__device__ __half g_wq[D_MODEL * D_MODEL];      // [N,K] transposed
__device__ __half g_wk[NKV * HD * D_MODEL];
__device__ __half g_wv[NKV * HD * D_MODEL];
__device__ __half g_wo[D_MODEL * D_MODEL];

__device__ __half g_qh[M_ROWS * NH * HD], g_ql[M_ROWS * NH * HD];
__device__ __half g_kh[M_ROWS * NKV * HD];
__device__ __half g_vh[M_ROWS * NKV * HD];

// ---------------- helpers -----------------------------------------------------
__device__ __forceinline__ uint32_t smem_u32(const void* p) {
    uint32_t a;
    asm("{ .reg .u64 t; cvta.to.shared.u64 t, %1; cvt.u32.u64 %0, t; }"
        : "=r"(a) : "l"(p));
    return a;
}

#define CP16(dst, src) \
    asm volatile("cp.async.cg.shared.global [%0], [%1], 16;" :: "r"(dst), "l"(src))
#define CP_COMMIT() asm volatile("cp.async.commit_group;" ::: "memory")
#define CP_WAIT(n)  asm volatile("cp.async.wait_group %0;" :: "n"(n) : "memory")

#define LDSM_X4(r0, r1, r2, r3, addr) \
    asm volatile("ldmatrix.sync.aligned.m8n8.x4.shared.b16 {%0,%1,%2,%3}, [%4];" \
                 : "=r"(r0), "=r"(r1), "=r"(r2), "=r"(r3) : "r"(addr))
#define LDSM_X4_T(r0, r1, r2, r3, addr) \
    asm volatile("ldmatrix.sync.aligned.m8n8.x4.trans.shared.b16 {%0,%1,%2,%3}, [%4];" \
                 : "=r"(r0), "=r"(r1), "=r"(r2), "=r"(r3) : "r"(addr))

// fp16 inputs, fp32 accumulator (half-rate on sm_103a legacy path)
__device__ __forceinline__ void mma_h(float* c, const uint32_t* a, uint32_t b0, uint32_t b1) {
    asm volatile(
        "mma.sync.aligned.m16n8k16.row.col.f32.f16.f16.f32 "
        "{%0,%1,%2,%3}, {%4,%5,%6,%7}, {%8,%9}, {%0,%1,%2,%3};"
        : "+f"(c[0]), "+f"(c[1]), "+f"(c[2]), "+f"(c[3])
        : "r"(a[0]), "r"(a[1]), "r"(a[2]), "r"(a[3]), "r"(b0), "r"(b1));
}

// fp16 inputs, fp16 accumulator (full-rate) — for small lo-correction terms
__device__ __forceinline__ void mma_h16(uint32_t* c, const uint32_t* a, uint32_t b0, uint32_t b1) {
    asm volatile(
        "mma.sync.aligned.m16n8k16.row.col.f16.f16.f16.f16 "
        "{%0,%1}, {%2,%3,%4,%5}, {%6,%7}, {%0,%1};"
        : "+r"(c[0]), "+r"(c[1])
        : "r"(a[0]), "r"(a[1]), "r"(a[2]), "r"(a[3]), "r"(b0), "r"(b1));
}

// pack two fp32 (x -> low half, y -> high half) into f16x2 hi + residual lo
__device__ __forceinline__ void pack_hilo(float x, float y, uint32_t& hp, uint32_t& lp) {
    __half2 h = __floats2half2_rn(x, y);
    hp = *reinterpret_cast<uint32_t*>(&h);
    float lx = x - __half2float(__low2half(h));
    float ly = y - __half2float(__high2half(h));
    __half2 l = __floats2half2_rn(lx, ly);
    lp = *reinterpret_cast<uint32_t*>(&l);
}

__device__ __forceinline__ uint32_t pack_h2(float x, float y) {
    __half2 h = __floats2half2_rn(x, y);
    return *reinterpret_cast<uint32_t*>(&h);
}

// ---------------- conversion kernels -----------------------------------------
__global__ __launch_bounds__(256) void cvt_hilo(
    const float4* __restrict__ src, uint2* __restrict__ hi, uint2* __restrict__ lo, int n4)
{
    int i = blockIdx.x * 256 + threadIdx.x;
    if (i >= n4) return;
    float4 v = src[i];
    uint32_t h0, l0, h1, l1;
    pack_hilo(v.x, v.y, h0, l0);
    pack_hilo(v.z, v.w, h1, l1);
    hi[i] = make_uint2(h0, h1);
    lo[i] = make_uint2(l0, l1);
}

// W [K,N] fp32 -> T [N,K] fp16 (transpose + round)
__global__ __launch_bounds__(256) void trans_cvt(
    const float* __restrict__ W, __half* __restrict__ T, int K, int N)
{
    __shared__ float tile[32][33];
    const int n0 = blockIdx.x * 32, k0 = blockIdx.y * 32;
    const int tx = threadIdx.x & 31, ty4 = (threadIdx.x >> 5) * 4;
#pragma unroll
    for (int i = 0; i < 4; i++)
        tile[ty4 + i][tx] = W[(size_t)(k0 + ty4 + i) * N + n0 + tx];
    __syncthreads();
#pragma unroll
    for (int i = 0; i < 4; i++)
        T[(size_t)(n0 + ty4 + i) * K + k0 + tx] = __float2half_rn(tile[tx][ty4 + i]);
}

// ---------------- 2-term FP16 HMMA GEMM, 128x256 tile, 3-stage cp.async -------
// C[M,N] = (Ah+Al)[M,K] @ Bt[N,K]^T. hi-term -> fp32 acc, lo-term -> fp16 acc.
// 256 threads, warps 2x4, warp tile 64x64. Up to 3 B-regions by blockIdx.x.
#define G_STAGE 32768
#define GEMM_SMEM (3 * G_STAGE)

__global__ __launch_bounds__(256) void mma_gemm(
    const __half* __restrict__ Ahp, const __half* __restrict__ Alp,
    const __half* __restrict__ B0, const __half* __restrict__ B1,
    const __half* __restrict__ B2,
    float* __restrict__ C0, float* __restrict__ C1, __half* __restrict__ C2,
    int K, int n0, int n1, int N0, int N1, int N2)
{
    extern __shared__ char smem[];
    const uint32_t sbase = smem_u32(smem);

    const int tid = threadIdx.x;
    const int lane = tid & 31, wid = tid >> 5;
    const int wm = wid >> 2, wn = wid & 3;
    const int bx = blockIdx.x;
    int region, bn, N;
    const __half* B;
    if (bx < n0)           { region = 0; bn = bx * 256;             B = B0; N = N0; }
    else if (bx < n0 + n1) { region = 1; bn = (bx - n0) * 256;      B = B1; N = N1; }
    else                   { region = 2; bn = (bx - n0 - n1) * 256; B = B2; N = N2; }
    const int bm = blockIdx.y * 128;
    const int NT = K / 32;

    float acc[4][8][4];
    uint32_t accl[4][8][2];
#pragma unroll
    for (int i = 0; i < 4; i++)
#pragma unroll
        for (int j = 0; j < 8; j++) {
#pragma unroll
            for (int l = 0; l < 4; l++) acc[i][j][l] = 0.f;
            accl[i][j][0] = 0u; accl[i][j][1] = 0u;
        }

    auto issue = [&](int it) {
        const int k0 = it * 32;
        const uint32_t sb = sbase + (it % 3) * G_STAGE;
#pragma unroll
        for (int i = 0; i < 8; i++) {
            int id = i * 256 + tid;          // 0..2047
            if (id < 1024) {                 // A: 128 rows x 4 chunks x 2 halves
                int half = id >> 9, r = (id >> 2) & 127, c = id & 3;
                const __half* src = half ? Alp : Ahp;
                uint32_t dst = sb + half * 8192 + r * 64 + ((c ^ ((r >> 1) & 3)) << 4);
                CP16(dst, src + (size_t)(bm + r) * K + k0 + c * 8);
            } else {                         // B: 256 rows x 4 chunks
                int idb = id - 1024;
                int r = (idb >> 2) & 255, c = idb & 3;
                uint32_t dst = sb + 16384 + r * 64 + ((c ^ ((r >> 1) & 3)) << 4);
                CP16(dst, B + (size_t)(bn + r) * K + k0 + c * 8);
            }
        }
    };

    issue(0); CP_COMMIT();
    issue(1); CP_COMMIT();

    const int lrow = lane & 15, lc = lane >> 4;

    for (int it = 0; it < NT; ++it) {
        if (it + 1 < NT) { CP_WAIT(1); } else { CP_WAIT(0); }
        __syncthreads();
        if (it + 2 < NT) { issue(it + 2); CP_COMMIT(); }

        const uint32_t sb = sbase + (it % 3) * G_STAGE;
#pragma unroll
        for (int ks = 0; ks < 2; ks++) {
            const int c = ks * 2 + lc;
            uint32_t ah[4][4], al[4][4];
#pragma unroll
            for (int mt = 0; mt < 4; mt++) {
                int r = wm * 64 + mt * 16 + lrow;
                uint32_t off = r * 64 + ((c ^ ((r >> 1) & 3)) << 4);
                LDSM_X4(ah[mt][0], ah[mt][1], ah[mt][2], ah[mt][3], sb + off);
                LDSM_X4(al[mt][0], al[mt][1], al[mt][2], al[mt][3], sb + 8192 + off);
            }
#pragma unroll
            for (int j = 0; j < 4; j++) {
                int r = wn * 64 + 16 * j + lrow;
                uint32_t off = r * 64 + ((c ^ ((r >> 1) & 3)) << 4);
                uint32_t b4[4];
                LDSM_X4(b4[0], b4[1], b4[2], b4[3], sb + 16384 + off);
#pragma unroll
                for (int half = 0; half < 2; half++) {
                    int nt = 2 * j + half;
#pragma unroll
                    for (int mt = 0; mt < 4; mt++) {
                        mma_h(acc[mt][nt], ah[mt], b4[half], b4[half + 2]);
                        mma_h16(accl[mt][nt], al[mt], b4[half], b4[half + 2]);
                    }
                }
            }
        }
        __syncthreads();
    }

    // ---- epilogue: fold fp16 lo-accumulator into fp32, then store ----
    const int g = lane >> 2, q = lane & 3;
    float* Cf = (region == 0) ? C0 : C1;
#pragma unroll
    for (int mt = 0; mt < 4; mt++) {
#pragma unroll
        for (int nt = 0; nt < 8; nt++) {
            float2 f0 = __half22float2(*reinterpret_cast<__half2*>(&accl[mt][nt][0]));
            float2 f1 = __half22float2(*reinterpret_cast<__half2*>(&accl[mt][nt][1]));
            float c0 = acc[mt][nt][0] + f0.x, c1 = acc[mt][nt][1] + f0.y;
            float c2 = acc[mt][nt][2] + f1.x, c3 = acc[mt][nt][3] + f1.y;
            int row = bm + wm * 64 + mt * 16 + g;
            int col = bn + wn * 64 + nt * 8 + 2 * q;
            if (region < 2) {
                *(float2*)&Cf[(size_t)row * N + col] = make_float2(c0, c1);
                *(float2*)&Cf[(size_t)(row + 8) * N + col] = make_float2(c2, c3);
            } else {
                ((uint32_t*)C2)[((size_t)row * N + col) >> 1] = pack_h2(c0, c1);
                ((uint32_t*)C2)[((size_t)(row + 8) * N + col) >> 1] = pack_h2(c2, c3);
            }
        }
    }
}

// ---------------- fused RMSNorm + RoPE -> fp16 hi(/lo) (warp per row) --------
__global__ __launch_bounds__(256) void rmsnorm_rope_split(
    const float* __restrict__ x, const float* __restrict__ scale,
    const float* __restrict__ cosT, const float* __restrict__ sinT, int heads,
    float prescale, __half* __restrict__ oh, __half* __restrict__ ol)
{
    const int row = blockIdx.x * 8 + (threadIdx.x >> 5);
    const int lane = threadIdx.x & 31;
    const int t = (row / heads) % T_LEN;

    float4 v = ((const float4*)x)[(size_t)row * 32 + lane];
    float ss = v.x * v.x + v.y * v.y + v.z * v.z + v.w * v.w;
#pragma unroll
    for (int m = 16; m > 0; m >>= 1)
        ss += __shfl_xor_sync(0xffffffffu, ss, m);
    float r = rsqrtf(ss * (1.0f / HD) + EPS);

    float4 sc = ((const float4*)scale)[lane];
    float x0 = v.x * r * sc.x, x1 = v.y * r * sc.y;
    float x2 = v.z * r * sc.z, x3 = v.w * r * sc.w;

    float4 cs = ((const float4*)cosT)[t * 32 + lane];
    float4 sn = ((const float4*)sinT)[t * 32 + lane];
    float o0 = (x0 * cs.x - x1 * sn.x) * prescale;
    float o1 = (x1 * cs.y + x0 * sn.y) * prescale;
    float o2 = (x2 * cs.z - x3 * sn.z) * prescale;
    float o3 = (x3 * cs.w + x2 * sn.w) * prescale;

    uint32_t h0, l0, h1, l1;
    pack_hilo(o0, o1, h0, l0);
    pack_hilo(o2, o3, h1, l1);
    ((uint2*)oh)[(size_t)row * 32 + lane] = make_uint2(h0, h1);
    if (ol)
        ((uint2*)ol)[(size_t)row * 32 + lane] = make_uint2(l0, l1);
}

// ---------------- 2-term FP16 HMMA causal GQA flash attention -----------------
// BQ=128 (8 warps x m16), BK=64, HD=128. Q hi/lo persistent (64KB) +
// double-buffered K/V single fp16 (2 x 32KB). lo-terms use fp16 accumulators.
#define FA_KV_STAGE 32768
#define FA_SMEM (65536 + 2 * FA_KV_STAGE)
#define SWZ256(r, c) ((uint32_t)((r) * 256 + (((c) ^ ((r) & 7)) << 4)))

__global__ __launch_bounds__(256, 1) void flash_mma(
    const __half* __restrict__ qh, const __half* __restrict__ ql,
    const __half* __restrict__ kh, const __half* __restrict__ vh,
    __half* __restrict__ ohp, __half* __restrict__ olp)
{
    extern __shared__ char fsm[];
    const uint32_t sb = smem_u32(fsm);
    const uint32_t Qh_s = sb, Ql_s = sb + 32768;
    const uint32_t ST = sb + 65536;  // per stage: Kh(16K) Vh(16K)

    const int qb = (int)gridDim.x - 1 - (int)blockIdx.x;  // heavy tiles first
    const int h = blockIdx.y, b = blockIdx.z;
    const int kvh = h >> 2;
    const int tid = threadIdx.x;
    const int lane = tid & 31, wid = tid >> 5;
    const int g = lane >> 2, qq = lane & 3;
    const int q0 = qb * 128;
    const int q0w = q0 + wid * 16;
    const int nkv = 2 * qb + 2;

#pragma unroll
    for (int i = 0; i < 16; i++) {
        int id = i * 256 + tid;
        int c = id & 15, r = (id >> 4) & 127, half = id >> 11;
        const __half* src = half ? ql : qh;
        uint32_t dst = (half ? Ql_s : Qh_s) + SWZ256(r, c);
        CP16(dst, src + ((size_t)(b * T_LEN + q0 + r) * NH + h) * HD + c * 8);
    }
    CP_COMMIT();

    auto issue_kv = [&](int stage, int kt) {
        const int kv0 = kt * 64;
        const uint32_t sbs = ST + stage * FA_KV_STAGE;
#pragma unroll
        for (int i = 0; i < 8; i++) {
            int id = i * 256 + tid;
            int c = id & 15, r = (id >> 4) & 63, arr = id >> 10;  // kh, vh
            const __half* src = arr ? vh : kh;
            uint32_t dst = sbs + arr * 16384 + SWZ256(r, c);
            CP16(dst, src + ((size_t)(b * T_LEN + kv0 + r) * NKV + kvh) * HD + c * 8);
        }
    };

    issue_kv(0, 0);
    CP_COMMIT();

    float m0 = -1e30f, m1 = -1e30f, l0 = 0.f, l1 = 0.f;
    float Oacc[16][4];
    uint32_t Oaccl[16][2];
#pragma unroll
    for (int nt = 0; nt < 16; nt++) {
#pragma unroll
        for (int e = 0; e < 4; e++) Oacc[nt][e] = 0.f;
        Oaccl[nt][0] = 0u; Oaccl[nt][1] = 0u;
    }

    const int lrow = lane & 15, lc = lane >> 4;

    for (int kt = 0; kt < nkv; kt++) {
        if (kt + 1 < nkv) {
            issue_kv((kt + 1) & 1, kt + 1);
            CP_COMMIT();
            CP_WAIT(1);
        } else {
            CP_WAIT(0);
        }
        __syncthreads();

        const int kv0 = kt * 64;
        const uint32_t sbs = ST + (kt & 1) * FA_KV_STAGE;

        if (kv0 <= q0w + 15) {
            float S[8][4];
            uint32_t Sl[8][2];
#pragma unroll
            for (int nt = 0; nt < 8; nt++) {
#pragma unroll
                for (int e = 0; e < 4; e++) S[nt][e] = 0.f;
                Sl[nt][0] = 0u; Sl[nt][1] = 0u;
            }

#pragma unroll
            for (int ks = 0; ks < 8; ks++) {
                const int c = ks * 2 + lc;
                int qr = wid * 16 + lrow;
                uint32_t qoff = SWZ256(qr, c);
                uint32_t aqh[4], aql[4];
                LDSM_X4(aqh[0], aqh[1], aqh[2], aqh[3], Qh_s + qoff);
                LDSM_X4(aql[0], aql[1], aql[2], aql[3], Ql_s + qoff);
#pragma unroll
                for (int j = 0; j < 4; j++) {
                    int r = 16 * j + lrow;
                    uint32_t off = SWZ256(r, c);
                    uint32_t b4[4];
                    LDSM_X4(b4[0], b4[1], b4[2], b4[3], sbs + off);
#pragma unroll
                    for (int half = 0; half < 2; half++) {
                        int nt = 2 * j + half;
                        mma_h(S[nt], aqh, b4[half], b4[half + 2]);
                        mma_h16(Sl[nt], aql, b4[half], b4[half + 2]);
                    }
                }
            }
            // fold fp16 lo-scores into fp32 scores
#pragma unroll
            for (int nt = 0; nt < 8; nt++) {
                float2 f0 = __half22float2(*reinterpret_cast<__half2*>(&Sl[nt][0]));
                float2 f1 = __half22float2(*reinterpret_cast<__half2*>(&Sl[nt][1]));
                S[nt][0] += f0.x; S[nt][1] += f0.y;
                S[nt][2] += f1.x; S[nt][3] += f1.y;
            }

            if (kv0 + 63 > q0w) {
#pragma unroll
                for (int nt = 0; nt < 8; nt++) {
                    int col = kv0 + nt * 8 + qq * 2;
                    int r0 = q0w + g, r1 = q0w + g + 8;
                    if (col > r0) S[nt][0] = -1e30f;
                    if (col + 1 > r0) S[nt][1] = -1e30f;
                    if (col > r1) S[nt][2] = -1e30f;
                    if (col + 1 > r1) S[nt][3] = -1e30f;
                }
            }

            float mx0 = -1e30f, mx1 = -1e30f;
#pragma unroll
            for (int nt = 0; nt < 8; nt++) {
                mx0 = fmaxf(mx0, fmaxf(S[nt][0], S[nt][1]));
                mx1 = fmaxf(mx1, fmaxf(S[nt][2], S[nt][3]));
            }
            mx0 = fmaxf(mx0, __shfl_xor_sync(0xffffffffu, mx0, 1));
            mx0 = fmaxf(mx0, __shfl_xor_sync(0xffffffffu, mx0, 2));
            mx1 = fmaxf(mx1, __shfl_xor_sync(0xffffffffu, mx1, 1));
            mx1 = fmaxf(mx1, __shfl_xor_sync(0xffffffffu, mx1, 2));
            float mn0 = fmaxf(m0, mx0), mn1 = fmaxf(m1, mx1);
            float al0 = exp2f(m0 - mn0), al1 = exp2f(m1 - mn1);
            m0 = mn0; m1 = mn1;
            float sum0 = 0.f, sum1 = 0.f;
#pragma unroll
            for (int nt = 0; nt < 8; nt++) {
                S[nt][0] = exp2f(S[nt][0] - mn0);
                S[nt][1] = exp2f(S[nt][1] - mn0);
                S[nt][2] = exp2f(S[nt][2] - mn1);
                S[nt][3] = exp2f(S[nt][3] - mn1);
                sum0 += S[nt][0] + S[nt][1];
                sum1 += S[nt][2] + S[nt][3];
            }
            sum0 += __shfl_xor_sync(0xffffffffu, sum0, 1);
            sum0 += __shfl_xor_sync(0xffffffffu, sum0, 2);
            sum1 += __shfl_xor_sync(0xffffffffu, sum1, 1);
            sum1 += __shfl_xor_sync(0xffffffffu, sum1, 2);
            l0 = l0 * al0 + sum0;
            l1 = l1 * al1 + sum1;
            __half2 ha0 = __float2half2_rn(al0);
            __half2 ha1 = __float2half2_rn(al1);
#pragma unroll
            for (int nt = 0; nt < 16; nt++) {
                Oacc[nt][0] *= al0; Oacc[nt][1] *= al0;
                Oacc[nt][2] *= al1; Oacc[nt][3] *= al1;
                *reinterpret_cast<__half2*>(&Oaccl[nt][0]) =
                    __hmul2(*reinterpret_cast<__half2*>(&Oaccl[nt][0]), ha0);
                *reinterpret_cast<__half2*>(&Oaccl[nt][1]) =
                    __hmul2(*reinterpret_cast<__half2*>(&Oaccl[nt][1]), ha1);
            }

            uint32_t Ph[4][4], Pl[4][4];
#pragma unroll
            for (int ktp = 0; ktp < 4; ktp++) {
                pack_hilo(S[2 * ktp][0], S[2 * ktp][1], Ph[ktp][0], Pl[ktp][0]);
                pack_hilo(S[2 * ktp][2], S[2 * ktp][3], Ph[ktp][1], Pl[ktp][1]);
                pack_hilo(S[2 * ktp + 1][0], S[2 * ktp + 1][1], Ph[ktp][2], Pl[ktp][2]);
                pack_hilo(S[2 * ktp + 1][2], S[2 * ktp + 1][3], Ph[ktp][3], Pl[ktp][3]);
            }

#pragma unroll
            for (int ktp = 0; ktp < 4; ktp++) {
#pragma unroll
                for (int j = 0; j < 8; j++) {
                    int r = ktp * 16 + lrow;
                    int c = 2 * j + lc;
                    uint32_t off = SWZ256(r, c);
                    uint32_t v0, v1, v2, v3;
                    LDSM_X4_T(v0, v1, v2, v3, sbs + 16384 + off);
                    mma_h(Oacc[2 * j], Ph[ktp], v0, v1);
                    mma_h16(Oaccl[2 * j], Pl[ktp], v0, v1);
                    mma_h(Oacc[2 * j + 1], Ph[ktp], v2, v3);
                    mma_h16(Oaccl[2 * j + 1], Pl[ktp], v2, v3);
                }
            }
        }
        __syncthreads();
    }

    // ---- write O as fp16 hi/lo (att layout [b*T, NH*HD]) ----
    float inv0 = 1.f / l0, inv1 = 1.f / l1;
    const size_t base0 = (size_t)(b * T_LEN + q0w + g) * (NH * HD) + h * HD;
    const size_t base1 = base0 + (size_t)8 * NH * HD;
#pragma unroll
    for (int nt = 0; nt < 16; nt++) {
        int col = nt * 8 + qq * 2;
        float2 f0 = __half22float2(*reinterpret_cast<__half2*>(&Oaccl[nt][0]));
        float2 f1 = __half22float2(*reinterpret_cast<__half2*>(&Oaccl[nt][1]));
        uint32_t hp, lp;
        pack_hilo((Oacc[nt][0] + f0.x) * inv0, (Oacc[nt][1] + f0.y) * inv0, hp, lp);
        ((uint32_t*)ohp)[(base0 + col) >> 1] = hp;
        ((uint32_t*)olp)[(base0 + col) >> 1] = lp;
        pack_hilo((Oacc[nt][2] + f1.x) * inv1, (Oacc[nt][3] + f1.y) * inv1, hp, lp);
        ((uint32_t*)ohp)[(base1 + col) >> 1] = hp;
        ((uint32_t*)olp)[(base1 + col) >> 1] = lp;
    }
}

// ---------------- launcher ---------------------------------------------------
extern "C" void kernel_launch(void* const* d_in, const int* in_sizes, int n_in,
                              void* d_out, int out_size)
{
    const float* x       = (const float*)d_in[0];
    const float* Wq      = (const float*)d_in[1];
    const float* Wk      = (const float*)d_in[2];
    const float* Wv      = (const float*)d_in[3];
    const float* Wo      = (const float*)d_in[4];
    const float* q_scale = (const float*)d_in[5];
    const float* k_scale = (const float*)d_in[6];
    const float* cosT    = (const float*)d_in[7];
    const float* sinT    = (const float*)d_in[8];
    float* out = (float*)d_out;

    float *pq, *pk;
    cudaGetSymbolAddress((void**)&pq, g_q);
    cudaGetSymbolAddress((void**)&pk, g_k);
    __half *xh, *xl, *ah, *al, *wq, *wk, *wv, *wo, *qh, *ql, *kh, *vh;
    cudaGetSymbolAddress((void**)&xh, g_xh);  cudaGetSymbolAddress((void**)&xl, g_xl);
    cudaGetSymbolAddress((void**)&ah, g_ah);  cudaGetSymbolAddress((void**)&al, g_al);
    cudaGetSymbolAddress((void**)&wq, g_wq);  cudaGetSymbolAddress((void**)&wk, g_wk);
    cudaGetSymbolAddress((void**)&wv, g_wv);  cudaGetSymbolAddress((void**)&wo, g_wo);
    cudaGetSymbolAddress((void**)&qh, g_qh);  cudaGetSymbolAddress((void**)&ql, g_ql);
    cudaGetSymbolAddress((void**)&kh, g_kh);  cudaGetSymbolAddress((void**)&vh, g_vh);

    static bool attr_set = false;
    if (!attr_set) {
        cudaFuncSetAttribute(mma_gemm, cudaFuncAttributeMaxDynamicSharedMemorySize, GEMM_SMEM);
        cudaFuncSetAttribute(flash_mma, cudaFuncAttributeMaxDynamicSharedMemorySize, FA_SMEM);
        attr_set = true;
    }

    const int M = M_ROWS;  // 4096

    // one-time conversions
    cvt_hilo<<<(M * D_MODEL / 4 + 255) / 256, 256>>>((const float4*)x, (uint2*)xh, (uint2*)xl, M * D_MODEL / 4);
    trans_cvt<<<dim3(D_MODEL / 32, D_MODEL / 32), 256>>>(Wq, wq, D_MODEL, D_MODEL);
    trans_cvt<<<dim3(NKV * HD / 32, D_MODEL / 32), 256>>>(Wk, wk, D_MODEL, NKV * HD);
    trans_cvt<<<dim3(NKV * HD / 32, D_MODEL / 32), 256>>>(Wv, wv, D_MODEL, NKV * HD);
    trans_cvt<<<dim3(D_MODEL / 32, D_MODEL / 32), 256>>>(Wo, wo, NH * HD, D_MODEL);

    // merged Q + K + V projections (one launch, 3 B-regions)
    mma_gemm<<<dim3(12, M / 128), 256, GEMM_SMEM>>>(
        xh, xl, wq, wk, wv, pq, pk, vh,
        D_MODEL, 8, 2, D_MODEL, NKV * HD, NKV * HD);

    // RMSNorm + RoPE (q pre-scaled by log2(e)/sqrt(HD); k -> hi only)
    const float qk_scale = 1.4426950408889634f * 0.08838834764831845f;
    rmsnorm_rope_split<<<M * NH / 8, 256>>>(pq, q_scale, cosT, sinT, NH, qk_scale, qh, ql);
    rmsnorm_rope_split<<<M * NKV / 8, 256>>>(pk, k_scale, cosT, sinT, NKV, 1.0f, kh, nullptr);

    // flash attention -> fp16 hi/lo
    flash_mma<<<dim3(T_LEN / 128, NH, BATCH), 256, FA_SMEM>>>(qh, ql, kh, vh, ah, al);

    // output projection (fp32 out)
    mma_gemm<<<dim3(8, M / 128), 256, GEMM_SMEM>>>(
        ah, al, wo, nullptr, nullptr, out, nullptr, nullptr,
        D_MODEL, 8, 0, D_MODEL, 0, 0);
}

// round 9
// speedup vs baseline: 9.6466x; 1.5835x over previous
#include <cuda_runtime.h>
#include <cuda_fp16.h>
#include <math.h>
#include <stdint.h>

// Problem constants
#define BATCH 2
#define T_LEN 2048
#define D_MODEL 2048
#define NH 16
#define NKV 4
#define HD 128
#define EPS 1e-6f
#define M_ROWS (BATCH * T_LEN)  // 4096

// ---------------- scratch (device globals; no allocation allowed) ----------
__device__ float g_q[M_ROWS * NH * HD];
__device__ float g_k[M_ROWS * NKV * HD];

__device__ __half g_xh[M_ROWS * D_MODEL];
__device__ __half g_ah[M_ROWS * D_MODEL];
__device__ __half g_wq[D_MODEL * D_MODEL];      // [N,K] transposed
__device__ __half g_wk[NKV * HD * D_MODEL];
__device__ __half g_wv[NKV * HD * D_MODEL];
__device__ __half g_wo[D_MODEL * D_MODEL];

__device__ __half g_qh[M_ROWS * NH * HD];
__device__ __half g_kh[M_ROWS * NKV * HD];
__device__ __half g_vh[M_ROWS * NKV * HD];

// ---------------- helpers -----------------------------------------------------
__device__ __forceinline__ uint32_t smem_u32(const void* p) {
    uint32_t a;
    asm("{ .reg .u64 t; cvta.to.shared.u64 t, %1; cvt.u32.u64 %0, t; }"
        : "=r"(a) : "l"(p));
    return a;
}

#define CP16(dst, src) \
    asm volatile("cp.async.cg.shared.global [%0], [%1], 16;" :: "r"(dst), "l"(src))
#define CP_COMMIT() asm volatile("cp.async.commit_group;" ::: "memory")
#define CP_WAIT(n)  asm volatile("cp.async.wait_group %0;" :: "n"(n) : "memory")

#define LDSM_X4(r0, r1, r2, r3, addr) \
    asm volatile("ldmatrix.sync.aligned.m8n8.x4.shared.b16 {%0,%1,%2,%3}, [%4];" \
                 : "=r"(r0), "=r"(r1), "=r"(r2), "=r"(r3) : "r"(addr))
#define LDSM_X4_T(r0, r1, r2, r3, addr) \
    asm volatile("ldmatrix.sync.aligned.m8n8.x4.trans.shared.b16 {%0,%1,%2,%3}, [%4];" \
                 : "=r"(r0), "=r"(r1), "=r"(r2), "=r"(r3) : "r"(addr))

// fp16 inputs, fp32 accumulator
__device__ __forceinline__ void mma_h(float* c, const uint32_t* a, uint32_t b0, uint32_t b1) {
    asm volatile(
        "mma.sync.aligned.m16n8k16.row.col.f32.f16.f16.f32 "
        "{%0,%1,%2,%3}, {%4,%5,%6,%7}, {%8,%9}, {%0,%1,%2,%3};"
        : "+f"(c[0]), "+f"(c[1]), "+f"(c[2]), "+f"(c[3])
        : "r"(a[0]), "r"(a[1]), "r"(a[2]), "r"(a[3]), "r"(b0), "r"(b1));
}

__device__ __forceinline__ uint32_t pack_h2(float x, float y) {
    __half2 h = __floats2half2_rn(x, y);
    return *reinterpret_cast<uint32_t*>(&h);
}

// ---------------- conversion kernels -----------------------------------------
__global__ __launch_bounds__(256) void cvt_h(
    const float4* __restrict__ src, uint2* __restrict__ dst, int n4)
{
    int i = blockIdx.x * 256 + threadIdx.x;
    if (i >= n4) return;
    float4 v = src[i];
    dst[i] = make_uint2(pack_h2(v.x, v.y), pack_h2(v.z, v.w));
}

// W [K,N] fp32 -> T [N,K] fp16 (transpose + round)
__global__ __launch_bounds__(256) void trans_cvt(
    const float* __restrict__ W, __half* __restrict__ T, int K, int N)
{
    __shared__ float tile[32][33];
    const int n0 = blockIdx.x * 32, k0 = blockIdx.y * 32;
    const int tx = threadIdx.x & 31, ty4 = (threadIdx.x >> 5) * 4;
#pragma unroll
    for (int i = 0; i < 4; i++)
        tile[ty4 + i][tx] = W[(size_t)(k0 + ty4 + i) * N + n0 + tx];
    __syncthreads();
#pragma unroll
    for (int i = 0; i < 4; i++)
        T[(size_t)(n0 + ty4 + i) * K + k0 + tx] = __float2half_rn(tile[tx][ty4 + i]);
}

// ---------------- FP16 HMMA GEMM, 128x256 tile, 3-stage cp.async --------------
// C[M,N] = A[M,K] @ Bt[N,K]^T. 256 threads, warps 2x4, warp tile 64x64.
// Up to 3 B-regions selected by blockIdx.x. Smem rows 64B,
// swizzle chunk' = c ^ ((r>>1)&3).
#define G_STAGE 24576
#define GEMM_SMEM (3 * G_STAGE)

__global__ __launch_bounds__(256) void mma_gemm(
    const __half* __restrict__ Ahp,
    const __half* __restrict__ B0, const __half* __restrict__ B1,
    const __half* __restrict__ B2,
    float* __restrict__ C0, float* __restrict__ C1, __half* __restrict__ C2,
    int K, int n0, int n1, int N0, int N1, int N2)
{
    extern __shared__ char smem[];
    const uint32_t sbase = smem_u32(smem);

    const int tid = threadIdx.x;
    const int lane = tid & 31, wid = tid >> 5;
    const int wm = wid >> 2, wn = wid & 3;
    const int bx = blockIdx.x;
    int region, bn, N;
    const __half* B;
    if (bx < n0)           { region = 0; bn = bx * 256;             B = B0; N = N0; }
    else if (bx < n0 + n1) { region = 1; bn = (bx - n0) * 256;      B = B1; N = N1; }
    else                   { region = 2; bn = (bx - n0 - n1) * 256; B = B2; N = N2; }
    const int bm = blockIdx.y * 128;
    const int NT = K / 32;

    float acc[4][8][4];
#pragma unroll
    for (int i = 0; i < 4; i++)
#pragma unroll
        for (int j = 0; j < 8; j++)
#pragma unroll
            for (int l = 0; l < 4; l++) acc[i][j][l] = 0.f;

    auto issue = [&](int it) {
        const int k0 = it * 32;
        const uint32_t sb = sbase + (it % 3) * G_STAGE;
#pragma unroll
        for (int i = 0; i < 6; i++) {
            int id = i * 256 + tid;          // 0..1535
            if (id < 512) {                  // A: 128 rows x 4 chunks
                int r = id >> 2, c = id & 3;
                uint32_t dst = sb + r * 64 + ((c ^ ((r >> 1) & 3)) << 4);
                CP16(dst, Ahp + (size_t)(bm + r) * K + k0 + c * 8);
            } else {                         // B: 256 rows x 4 chunks
                int idb = id - 512;
                int r = idb >> 2, c = idb & 3;
                uint32_t dst = sb + 8192 + r * 64 + ((c ^ ((r >> 1) & 3)) << 4);
                CP16(dst, B + (size_t)(bn + r) * K + k0 + c * 8);
            }
        }
    };

    issue(0); CP_COMMIT();
    issue(1); CP_COMMIT();

    const int lrow = lane & 15, lc = lane >> 4;

    for (int it = 0; it < NT; ++it) {
        if (it + 1 < NT) { CP_WAIT(1); } else { CP_WAIT(0); }
        __syncthreads();
        if (it + 2 < NT) { issue(it + 2); CP_COMMIT(); }

        const uint32_t sb = sbase + (it % 3) * G_STAGE;
#pragma unroll
        for (int ks = 0; ks < 2; ks++) {
            const int c = ks * 2 + lc;
            uint32_t ah[4][4];
#pragma unroll
            for (int mt = 0; mt < 4; mt++) {
                int r = wm * 64 + mt * 16 + lrow;
                uint32_t off = r * 64 + ((c ^ ((r >> 1) & 3)) << 4);
                LDSM_X4(ah[mt][0], ah[mt][1], ah[mt][2], ah[mt][3], sb + off);
            }
#pragma unroll
            for (int j = 0; j < 4; j++) {
                int r = wn * 64 + 16 * j + lrow;
                uint32_t off = r * 64 + ((c ^ ((r >> 1) & 3)) << 4);
                uint32_t b4[4];
                LDSM_X4(b4[0], b4[1], b4[2], b4[3], sb + 8192 + off);
#pragma unroll
                for (int half = 0; half < 2; half++) {
                    int nt = 2 * j + half;
#pragma unroll
                    for (int mt = 0; mt < 4; mt++)
                        mma_h(acc[mt][nt], ah[mt], b4[half], b4[half + 2]);
                }
            }
        }
        __syncthreads();
    }

    // ---- epilogue ----
    const int g = lane >> 2, q = lane & 3;
    float* Cf = (region == 0) ? C0 : C1;
#pragma unroll
    for (int mt = 0; mt < 4; mt++) {
#pragma unroll
        for (int nt = 0; nt < 8; nt++) {
            int row = bm + wm * 64 + mt * 16 + g;
            int col = bn + wn * 64 + nt * 8 + 2 * q;
            if (region < 2) {
                *(float2*)&Cf[(size_t)row * N + col] =
                    make_float2(acc[mt][nt][0], acc[mt][nt][1]);
                *(float2*)&Cf[(size_t)(row + 8) * N + col] =
                    make_float2(acc[mt][nt][2], acc[mt][nt][3]);
            } else {
                ((uint32_t*)C2)[((size_t)row * N + col) >> 1] =
                    pack_h2(acc[mt][nt][0], acc[mt][nt][1]);
                ((uint32_t*)C2)[((size_t)(row + 8) * N + col) >> 1] =
                    pack_h2(acc[mt][nt][2], acc[mt][nt][3]);
            }
        }
    }
}

// ---------------- fused RMSNorm + RoPE -> fp16 (warp per row) -----------------
__global__ __launch_bounds__(256) void rmsnorm_rope_h(
    const float* __restrict__ x, const float* __restrict__ scale,
    const float* __restrict__ cosT, const float* __restrict__ sinT, int heads,
    float prescale, __half* __restrict__ oh)
{
    const int row = blockIdx.x * 8 + (threadIdx.x >> 5);
    const int lane = threadIdx.x & 31;
    const int t = (row / heads) % T_LEN;

    float4 v = ((const float4*)x)[(size_t)row * 32 + lane];
    float ss = v.x * v.x + v.y * v.y + v.z * v.z + v.w * v.w;
#pragma unroll
    for (int m = 16; m > 0; m >>= 1)
        ss += __shfl_xor_sync(0xffffffffu, ss, m);
    float r = rsqrtf(ss * (1.0f / HD) + EPS);

    float4 sc = ((const float4*)scale)[lane];
    float x0 = v.x * r * sc.x, x1 = v.y * r * sc.y;
    float x2 = v.z * r * sc.z, x3 = v.w * r * sc.w;

    float4 cs = ((const float4*)cosT)[t * 32 + lane];
    float4 sn = ((const float4*)sinT)[t * 32 + lane];
    float o0 = (x0 * cs.x - x1 * sn.x) * prescale;
    float o1 = (x1 * cs.y + x0 * sn.y) * prescale;
    float o2 = (x2 * cs.z - x3 * sn.z) * prescale;
    float o3 = (x3 * cs.w + x2 * sn.w) * prescale;

    ((uint2*)oh)[(size_t)row * 32 + lane] = make_uint2(pack_h2(o0, o1), pack_h2(o2, o3));
}

// ---------------- FP16 HMMA causal GQA flash attention ------------------------
// BQ=128 (8 warps x m16), BK=64, HD=128. Q persistent (32KB) +
// double-buffered K/V (2 x 32KB). 256 threads. Output fp16.
#define FA_KV_STAGE 32768
#define FA_SMEM (32768 + 2 * FA_KV_STAGE)
#define SWZ256(r, c) ((uint32_t)((r) * 256 + (((c) ^ ((r) & 7)) << 4)))

__global__ __launch_bounds__(256, 1) void flash_mma(
    const __half* __restrict__ qh, const __half* __restrict__ kh,
    const __half* __restrict__ vh, __half* __restrict__ ohp)
{
    extern __shared__ char fsm[];
    const uint32_t sb = smem_u32(fsm);
    const uint32_t Qh_s = sb;
    const uint32_t ST = sb + 32768;  // per stage: Kh(16K) Vh(16K)

    const int qb = (int)gridDim.x - 1 - (int)blockIdx.x;  // heavy tiles first
    const int h = blockIdx.y, b = blockIdx.z;
    const int kvh = h >> 2;
    const int tid = threadIdx.x;
    const int lane = tid & 31, wid = tid >> 5;
    const int g = lane >> 2, qq = lane & 3;
    const int q0 = qb * 128;
    const int q0w = q0 + wid * 16;
    const int nkv = 2 * qb + 2;

#pragma unroll
    for (int i = 0; i < 8; i++) {
        int id = i * 256 + tid;
        int c = id & 15, r = id >> 4;
        CP16(Qh_s + SWZ256(r, c),
             qh + ((size_t)(b * T_LEN + q0 + r) * NH + h) * HD + c * 8);
    }
    CP_COMMIT();

    auto issue_kv = [&](int stage, int kt) {
        const int kv0 = kt * 64;
        const uint32_t sbs = ST + stage * FA_KV_STAGE;
#pragma unroll
        for (int i = 0; i < 8; i++) {
            int id = i * 256 + tid;
            int c = id & 15, r = (id >> 4) & 63, arr = id >> 10;  // k, v
            const __half* src = arr ? vh : kh;
            uint32_t dst = sbs + arr * 16384 + SWZ256(r, c);
            CP16(dst, src + ((size_t)(b * T_LEN + kv0 + r) * NKV + kvh) * HD + c * 8);
        }
    };

    issue_kv(0, 0);
    CP_COMMIT();

    float m0 = -1e30f, m1 = -1e30f, l0 = 0.f, l1 = 0.f;
    float Oacc[16][4];
#pragma unroll
    for (int nt = 0; nt < 16; nt++)
#pragma unroll
        for (int e = 0; e < 4; e++) Oacc[nt][e] = 0.f;

    const int lrow = lane & 15, lc = lane >> 4;

    for (int kt = 0; kt < nkv; kt++) {
        if (kt + 1 < nkv) {
            issue_kv((kt + 1) & 1, kt + 1);
            CP_COMMIT();
            CP_WAIT(1);
        } else {
            CP_WAIT(0);
        }
        __syncthreads();

        const int kv0 = kt * 64;
        const uint32_t sbs = ST + (kt & 1) * FA_KV_STAGE;

        if (kv0 <= q0w + 15) {
            float S[8][4];
#pragma unroll
            for (int nt = 0; nt < 8; nt++)
#pragma unroll
                for (int e = 0; e < 4; e++) S[nt][e] = 0.f;

#pragma unroll
            for (int ks = 0; ks < 8; ks++) {
                const int c = ks * 2 + lc;
                int qr = wid * 16 + lrow;
                uint32_t aq[4];
                LDSM_X4(aq[0], aq[1], aq[2], aq[3], Qh_s + SWZ256(qr, c));
#pragma unroll
                for (int j = 0; j < 4; j++) {
                    int r = 16 * j + lrow;
                    uint32_t b4[4];
                    LDSM_X4(b4[0], b4[1], b4[2], b4[3], sbs + SWZ256(r, c));
#pragma unroll
                    for (int half = 0; half < 2; half++)
                        mma_h(S[2 * j + half], aq, b4[half], b4[half + 2]);
                }
            }

            if (kv0 + 63 > q0w) {
#pragma unroll
                for (int nt = 0; nt < 8; nt++) {
                    int col = kv0 + nt * 8 + qq * 2;
                    int r0 = q0w + g, r1 = q0w + g + 8;
                    if (col > r0) S[nt][0] = -1e30f;
                    if (col + 1 > r0) S[nt][1] = -1e30f;
                    if (col > r1) S[nt][2] = -1e30f;
                    if (col + 1 > r1) S[nt][3] = -1e30f;
                }
            }

            float mx0 = -1e30f, mx1 = -1e30f;
#pragma unroll
            for (int nt = 0; nt < 8; nt++) {
                mx0 = fmaxf(mx0, fmaxf(S[nt][0], S[nt][1]));
                mx1 = fmaxf(mx1, fmaxf(S[nt][2], S[nt][3]));
            }
            mx0 = fmaxf(mx0, __shfl_xor_sync(0xffffffffu, mx0, 1));
            mx0 = fmaxf(mx0, __shfl_xor_sync(0xffffffffu, mx0, 2));
            mx1 = fmaxf(mx1, __shfl_xor_sync(0xffffffffu, mx1, 1));
            mx1 = fmaxf(mx1, __shfl_xor_sync(0xffffffffu, mx1, 2));
            float mn0 = fmaxf(m0, mx0), mn1 = fmaxf(m1, mx1);
            float al0 = exp2f(m0 - mn0), al1 = exp2f(m1 - mn1);
            m0 = mn0; m1 = mn1;
            float sum0 = 0.f, sum1 = 0.f;
#pragma unroll
            for (int nt = 0; nt < 8; nt++) {
                S[nt][0] = exp2f(S[nt][0] - mn0);
                S[nt][1] = exp2f(S[nt][1] - mn0);
                S[nt][2] = exp2f(S[nt][2] - mn1);
                S[nt][3] = exp2f(S[nt][3] - mn1);
                sum0 += S[nt][0] + S[nt][1];
                sum1 += S[nt][2] + S[nt][3];
            }
            sum0 += __shfl_xor_sync(0xffffffffu, sum0, 1);
            sum0 += __shfl_xor_sync(0xffffffffu, sum0, 2);
            sum1 += __shfl_xor_sync(0xffffffffu, sum1, 1);
            sum1 += __shfl_xor_sync(0xffffffffu, sum1, 2);
            l0 = l0 * al0 + sum0;
            l1 = l1 * al1 + sum1;
#pragma unroll
            for (int nt = 0; nt < 16; nt++) {
                Oacc[nt][0] *= al0; Oacc[nt][1] *= al0;
                Oacc[nt][2] *= al1; Oacc[nt][3] *= al1;
            }

            uint32_t Ph[4][4];
#pragma unroll
            for (int ktp = 0; ktp < 4; ktp++) {
                Ph[ktp][0] = pack_h2(S[2 * ktp][0], S[2 * ktp][1]);
                Ph[ktp][1] = pack_h2(S[2 * ktp][2], S[2 * ktp][3]);
                Ph[ktp][2] = pack_h2(S[2 * ktp + 1][0], S[2 * ktp + 1][1]);
                Ph[ktp][3] = pack_h2(S[2 * ktp + 1][2], S[2 * ktp + 1][3]);
            }

#pragma unroll
            for (int ktp = 0; ktp < 4; ktp++) {
#pragma unroll
                for (int j = 0; j < 8; j++) {
                    int r = ktp * 16 + lrow;
                    int c = 2 * j + lc;
                    uint32_t v0, v1, v2, v3;
                    LDSM_X4_T(v0, v1, v2, v3, sbs + 16384 + SWZ256(r, c));
                    mma_h(Oacc[2 * j], Ph[ktp], v0, v1);
                    mma_h(Oacc[2 * j + 1], Ph[ktp], v2, v3);
                }
            }
        }
        __syncthreads();
    }

    // ---- write O as fp16 (att layout [b*T, NH*HD]) ----
    float inv0 = 1.f / l0, inv1 = 1.f / l1;
    const size_t base0 = (size_t)(b * T_LEN + q0w + g) * (NH * HD) + h * HD;
    const size_t base1 = base0 + (size_t)8 * NH * HD;
#pragma unroll
    for (int nt = 0; nt < 16; nt++) {
        int col = nt * 8 + qq * 2;
        ((uint32_t*)ohp)[(base0 + col) >> 1] =
            pack_h2(Oacc[nt][0] * inv0, Oacc[nt][1] * inv0);
        ((uint32_t*)ohp)[(base1 + col) >> 1] =
            pack_h2(Oacc[nt][2] * inv1, Oacc[nt][3] * inv1);
    }
}

// ---------------- launcher ---------------------------------------------------
extern "C" void kernel_launch(void* const* d_in, const int* in_sizes, int n_in,
                              void* d_out, int out_size)
{
    const float* x       = (const float*)d_in[0];
    const float* Wq      = (const float*)d_in[1];
    const float* Wk      = (const float*)d_in[2];
    const float* Wv      = (const float*)d_in[3];
    const float* Wo      = (const float*)d_in[4];
    const float* q_scale = (const float*)d_in[5];
    const float* k_scale = (const float*)d_in[6];
    const float* cosT    = (const float*)d_in[7];
    const float* sinT    = (const float*)d_in[8];
    float* out = (float*)d_out;

    float *pq, *pk;
    cudaGetSymbolAddress((void**)&pq, g_q);
    cudaGetSymbolAddress((void**)&pk, g_k);
    __half *xh, *ah, *wq, *wk, *wv, *wo, *qh, *kh, *vh;
    cudaGetSymbolAddress((void**)&xh, g_xh);
    cudaGetSymbolAddress((void**)&ah, g_ah);
    cudaGetSymbolAddress((void**)&wq, g_wq);  cudaGetSymbolAddress((void**)&wk, g_wk);
    cudaGetSymbolAddress((void**)&wv, g_wv);  cudaGetSymbolAddress((void**)&wo, g_wo);
    cudaGetSymbolAddress((void**)&qh, g_qh);
    cudaGetSymbolAddress((void**)&kh, g_kh);  cudaGetSymbolAddress((void**)&vh, g_vh);

    static bool attr_set = false;
    if (!attr_set) {
        cudaFuncSetAttribute(mma_gemm, cudaFuncAttributeMaxDynamicSharedMemorySize, GEMM_SMEM);
        cudaFuncSetAttribute(flash_mma, cudaFuncAttributeMaxDynamicSharedMemorySize, FA_SMEM);
        attr_set = true;
    }

    const int M = M_ROWS;  // 4096

    // one-time conversions
    cvt_h<<<(M * D_MODEL / 4 + 255) / 256, 256>>>((const float4*)x, (uint2*)xh, M * D_MODEL / 4);
    trans_cvt<<<dim3(D_MODEL / 32, D_MODEL / 32), 256>>>(Wq, wq, D_MODEL, D_MODEL);
    trans_cvt<<<dim3(NKV * HD / 32, D_MODEL / 32), 256>>>(Wk, wk, D_MODEL, NKV * HD);
    trans_cvt<<<dim3(NKV * HD / 32, D_MODEL / 32), 256>>>(Wv, wv, D_MODEL, NKV * HD);
    trans_cvt<<<dim3(D_MODEL / 32, D_MODEL / 32), 256>>>(Wo, wo, NH * HD, D_MODEL);

    // merged Q + K + V projections (one launch, 3 B-regions)
    mma_gemm<<<dim3(12, M / 128), 256, GEMM_SMEM>>>(
        xh, wq, wk, wv, pq, pk, vh,
        D_MODEL, 8, 2, D_MODEL, NKV * HD, NKV * HD);

    // RMSNorm + RoPE (q pre-scaled by log2(e)/sqrt(HD))
    const float qk_scale = 1.4426950408889634f * 0.08838834764831845f;
    rmsnorm_rope_h<<<M * NH / 8, 256>>>(pq, q_scale, cosT, sinT, NH, qk_scale, qh);
    rmsnorm_rope_h<<<M * NKV / 8, 256>>>(pk, k_scale, cosT, sinT, NKV, 1.0f, kh);

    // flash attention -> fp16
    flash_mma<<<dim3(T_LEN / 128, NH, BATCH), 256, FA_SMEM>>>(qh, kh, vh, ah);

    // output projection (fp32 out)
    mma_gemm<<<dim3(8, M / 128), 256, GEMM_SMEM>>>(
        ah, wo, nullptr, nullptr, out, nullptr, nullptr,
        D_MODEL, 8, 0, D_MODEL, 0, 0);
}

// round 10
// speedup vs baseline: 10.2046x; 1.0578x over previous
#include <cuda_runtime.h>
#include <cuda_fp16.h>
#include <math.h>
#include <stdint.h>

// Problem constants
#define BATCH 2
#define T_LEN 2048
#define D_MODEL 2048
#define NH 16
#define NKV 4
#define HD 128
#define EPS 1e-6f
#define M_ROWS (BATCH * T_LEN)  // 4096

// ---------------- scratch (device globals; no allocation allowed) ----------
__device__ __half g_xh[M_ROWS * D_MODEL];
__device__ __half g_ah[M_ROWS * D_MODEL];
__device__ __half g_wq[D_MODEL * D_MODEL];      // [N,K] transposed
__device__ __half g_wk[NKV * HD * D_MODEL];
__device__ __half g_wv[NKV * HD * D_MODEL];
__device__ __half g_wo[D_MODEL * D_MODEL];

__device__ __half g_qh[M_ROWS * NH * HD];
__device__ __half g_kh[M_ROWS * NKV * HD];
__device__ __half g_vh[M_ROWS * NKV * HD];

// ---------------- helpers -----------------------------------------------------
__device__ __forceinline__ uint32_t smem_u32(const void* p) {
    uint32_t a;
    asm("{ .reg .u64 t; cvta.to.shared.u64 t, %1; cvt.u32.u64 %0, t; }"
        : "=r"(a) : "l"(p));
    return a;
}

#define CP16(dst, src) \
    asm volatile("cp.async.cg.shared.global [%0], [%1], 16;" :: "r"(dst), "l"(src))
#define CP_COMMIT() asm volatile("cp.async.commit_group;" ::: "memory")
#define CP_WAIT(n)  asm volatile("cp.async.wait_group %0;" :: "n"(n) : "memory")

#define LDSM_X4(r0, r1, r2, r3, addr) \
    asm volatile("ldmatrix.sync.aligned.m8n8.x4.shared.b16 {%0,%1,%2,%3}, [%4];" \
                 : "=r"(r0), "=r"(r1), "=r"(r2), "=r"(r3) : "r"(addr))
#define LDSM_X4_T(r0, r1, r2, r3, addr) \
    asm volatile("ldmatrix.sync.aligned.m8n8.x4.trans.shared.b16 {%0,%1,%2,%3}, [%4];" \
                 : "=r"(r0), "=r"(r1), "=r"(r2), "=r"(r3) : "r"(addr))

// fp16 inputs, fp32 accumulator
__device__ __forceinline__ void mma_h(float* c, const uint32_t* a, uint32_t b0, uint32_t b1) {
    asm volatile(
        "mma.sync.aligned.m16n8k16.row.col.f32.f16.f16.f32 "
        "{%0,%1,%2,%3}, {%4,%5,%6,%7}, {%8,%9}, {%0,%1,%2,%3};"
        : "+f"(c[0]), "+f"(c[1]), "+f"(c[2]), "+f"(c[3])
        : "r"(a[0]), "r"(a[1]), "r"(a[2]), "r"(a[3]), "r"(b0), "r"(b1));
}

__device__ __forceinline__ uint32_t pack_h2(float x, float y) {
    __half2 h = __floats2half2_rn(x, y);
    return *reinterpret_cast<uint32_t*>(&h);
}

// ---------------- conversion kernels -----------------------------------------
__global__ __launch_bounds__(256) void cvt_h(
    const float4* __restrict__ src, uint2* __restrict__ dst, int n4)
{
    int i = blockIdx.x * 256 + threadIdx.x;
    if (i >= n4) return;
    float4 v = src[i];
    dst[i] = make_uint2(pack_h2(v.x, v.y), pack_h2(v.z, v.w));
}

// W [K,N] fp32 -> T [N,K] fp16 (transpose + round)
__global__ __launch_bounds__(256) void trans_cvt(
    const float* __restrict__ W, __half* __restrict__ T, int K, int N)
{
    __shared__ float tile[32][33];
    const int n0 = blockIdx.x * 32, k0 = blockIdx.y * 32;
    const int tx = threadIdx.x & 31, ty4 = (threadIdx.x >> 5) * 4;
#pragma unroll
    for (int i = 0; i < 4; i++)
        tile[ty4 + i][tx] = W[(size_t)(k0 + ty4 + i) * N + n0 + tx];
    __syncthreads();
#pragma unroll
    for (int i = 0; i < 4; i++)
        T[(size_t)(n0 + ty4 + i) * K + k0 + tx] = __float2half_rn(tile[tx][ty4 + i]);
}

// ---------------- FP16 HMMA GEMM, 128x128 tile, 3-stage cp.async --------------
// C[M,N] = A[M,K] @ Bt[N,K]^T. 256 threads (warps 4x2), warp tile 32x64.
// Up to 3 B-regions selected by blockIdx.x; per-region epilogue mode:
//   0 = fp32 store, 1 = fp16 store, 2 = fused RMSNorm+RoPE -> fp16
// (mode 2 requires the 128-col block to cover exactly one head, HD=128.)
// Smem rows 64B, swizzle chunk' = c ^ ((r>>1)&3).
#define G_STAGE 16384
#define GEMM_SMEM (3 * G_STAGE + 1024)

__global__ __launch_bounds__(256, 2) void mma_gemm(
    const __half* __restrict__ Ahp,
    const __half* __restrict__ B0, const __half* __restrict__ B1,
    const __half* __restrict__ B2,
    void* __restrict__ O0, void* __restrict__ O1, void* __restrict__ O2,
    int mode0, int mode1, int mode2,
    const float* __restrict__ sv0, const float* __restrict__ sv1,
    const float* __restrict__ cosT, const float* __restrict__ sinT,
    float ps0, float ps1,
    int K, int n0, int n1, int N0, int N1, int N2)
{
    extern __shared__ char smem[];
    const uint32_t sbase = smem_u32(smem);

    const int tid = threadIdx.x;
    const int lane = tid & 31, wid = tid >> 5;
    const int wm = wid >> 1, wn = wid & 1;
    const int bx = blockIdx.x;
    int mode, bn, N;
    const __half* B;
    void* O;
    const float* scaleV;
    float prescale;
    if (bx < n0) {
        mode = mode0; bn = bx * 128; B = B0; N = N0; O = O0;
        scaleV = sv0; prescale = ps0;
    } else if (bx < n0 + n1) {
        mode = mode1; bn = (bx - n0) * 128; B = B1; N = N1; O = O1;
        scaleV = sv1; prescale = ps1;
    } else {
        mode = mode2; bn = (bx - n0 - n1) * 128; B = B2; N = N2; O = O2;
        scaleV = sv0; prescale = 1.f;
    }
    const int bm = blockIdx.y * 128;
    const int NT = K / 32;

    float acc[2][8][4];
#pragma unroll
    for (int i = 0; i < 2; i++)
#pragma unroll
        for (int j = 0; j < 8; j++)
#pragma unroll
            for (int l = 0; l < 4; l++) acc[i][j][l] = 0.f;

    auto issue = [&](int it) {
        const int k0 = it * 32;
        const uint32_t sb = sbase + (it % 3) * G_STAGE;
#pragma unroll
        for (int i = 0; i < 4; i++) {
            int id = i * 256 + tid;          // 0..1023
            if (id < 512) {                  // A: 128 rows x 4 chunks
                int r = id >> 2, c = id & 3;
                uint32_t dst = sb + r * 64 + ((c ^ ((r >> 1) & 3)) << 4);
                CP16(dst, Ahp + (size_t)(bm + r) * K + k0 + c * 8);
            } else {                         // B: 128 rows x 4 chunks
                int idb = id - 512;
                int r = idb >> 2, c = idb & 3;
                uint32_t dst = sb + 8192 + r * 64 + ((c ^ ((r >> 1) & 3)) << 4);
                CP16(dst, B + (size_t)(bn + r) * K + k0 + c * 8);
            }
        }
    };

    issue(0); CP_COMMIT();
    issue(1); CP_COMMIT();

    const int lrow = lane & 15, lc = lane >> 4;

    for (int it = 0; it < NT; ++it) {
        if (it + 1 < NT) { CP_WAIT(1); } else { CP_WAIT(0); }
        __syncthreads();
        if (it + 2 < NT) { issue(it + 2); CP_COMMIT(); }

        const uint32_t sb = sbase + (it % 3) * G_STAGE;
#pragma unroll
        for (int ks = 0; ks < 2; ks++) {
            const int c = ks * 2 + lc;
            uint32_t ah[2][4];
#pragma unroll
            for (int mt = 0; mt < 2; mt++) {
                int r = wm * 32 + mt * 16 + lrow;
                uint32_t off = r * 64 + ((c ^ ((r >> 1) & 3)) << 4);
                LDSM_X4(ah[mt][0], ah[mt][1], ah[mt][2], ah[mt][3], sb + off);
            }
#pragma unroll
            for (int j = 0; j < 4; j++) {
                int r = wn * 64 + 16 * j + lrow;
                uint32_t off = r * 64 + ((c ^ ((r >> 1) & 3)) << 4);
                uint32_t b4[4];
                LDSM_X4(b4[0], b4[1], b4[2], b4[3], sb + 8192 + off);
#pragma unroll
                for (int half = 0; half < 2; half++) {
                    int nt = 2 * j + half;
#pragma unroll
                    for (int mt = 0; mt < 2; mt++)
                        mma_h(acc[mt][nt], ah[mt], b4[half], b4[half + 2]);
                }
            }
        }
        __syncthreads();
    }

    // ---- epilogue ----
    const int g = lane >> 2, q = lane & 3;
    if (mode == 0) {
        float* Cf = (float*)O;
#pragma unroll
        for (int mt = 0; mt < 2; mt++)
#pragma unroll
            for (int nt = 0; nt < 8; nt++) {
                int row = bm + wm * 32 + mt * 16 + g;
                int col = bn + wn * 64 + nt * 8 + 2 * q;
                *(float2*)&Cf[(size_t)row * N + col] =
                    make_float2(acc[mt][nt][0], acc[mt][nt][1]);
                *(float2*)&Cf[(size_t)(row + 8) * N + col] =
                    make_float2(acc[mt][nt][2], acc[mt][nt][3]);
            }
    } else if (mode == 1) {
        uint32_t* Ch = (uint32_t*)O;
#pragma unroll
        for (int mt = 0; mt < 2; mt++)
#pragma unroll
            for (int nt = 0; nt < 8; nt++) {
                int row = bm + wm * 32 + mt * 16 + g;
                int col = bn + wn * 64 + nt * 8 + 2 * q;
                Ch[((size_t)row * N + col) >> 1] =
                    pack_h2(acc[mt][nt][0], acc[mt][nt][1]);
                Ch[((size_t)(row + 8) * N + col) >> 1] =
                    pack_h2(acc[mt][nt][2], acc[mt][nt][3]);
            }
    } else {
        // fused RMSNorm (over this block's 128 cols = one head) + RoPE -> fp16
        float* red = (float*)(smem + 3 * G_STAGE);  // [2 wn][128 rows]
#pragma unroll
        for (int mt = 0; mt < 2; mt++) {
            float s0 = 0.f, s1 = 0.f;
#pragma unroll
            for (int nt = 0; nt < 8; nt++) {
                s0 += acc[mt][nt][0] * acc[mt][nt][0] + acc[mt][nt][1] * acc[mt][nt][1];
                s1 += acc[mt][nt][2] * acc[mt][nt][2] + acc[mt][nt][3] * acc[mt][nt][3];
            }
            s0 += __shfl_xor_sync(0xffffffffu, s0, 1);
            s0 += __shfl_xor_sync(0xffffffffu, s0, 2);
            s1 += __shfl_xor_sync(0xffffffffu, s1, 1);
            s1 += __shfl_xor_sync(0xffffffffu, s1, 2);
            if (q == 0) {
                red[wn * 128 + wm * 32 + mt * 16 + g] = s0;
                red[wn * 128 + wm * 32 + mt * 16 + g + 8] = s1;
            }
        }
        __syncthreads();
        uint32_t* Ch = (uint32_t*)O;
#pragma unroll
        for (int mt = 0; mt < 2; mt++) {
#pragma unroll
            for (int rr = 0; rr < 2; rr++) {
                int r = wm * 32 + mt * 16 + g + rr * 8;
                float rinv = rsqrtf((red[r] + red[128 + r]) * (1.0f / HD) + EPS);
                int t = (bm + r) & (T_LEN - 1);
#pragma unroll
                for (int nt = 0; nt < 8; nt++) {
                    int d = wn * 64 + nt * 8 + 2 * q;
                    float2 sc = *(const float2*)&scaleV[d];
                    float2 cs = *(const float2*)&cosT[t * HD + d];
                    float2 sn = *(const float2*)&sinT[t * HD + d];
                    float v0 = acc[mt][nt][rr * 2 + 0] * rinv * sc.x;
                    float v1 = acc[mt][nt][rr * 2 + 1] * rinv * sc.y;
                    float o0 = (v0 * cs.x - v1 * sn.x) * prescale;
                    float o1 = (v1 * cs.y + v0 * sn.y) * prescale;
                    Ch[(((size_t)(bm + r)) * N + bn + d) >> 1] = pack_h2(o0, o1);
                }
            }
        }
    }
}

// ---------------- FP16 HMMA causal GQA flash attention ------------------------
// BQ=128 (8 warps x m16), BK=64, HD=128. Q persistent (32KB) +
// double-buffered K/V (2 x 32KB). 256 threads. Output fp16.
#define FA_KV_STAGE 32768
#define FA_SMEM (32768 + 2 * FA_KV_STAGE)
#define SWZ256(r, c) ((uint32_t)((r) * 256 + (((c) ^ ((r) & 7)) << 4)))

__global__ __launch_bounds__(256, 1) void flash_mma(
    const __half* __restrict__ qh, const __half* __restrict__ kh,
    const __half* __restrict__ vh, __half* __restrict__ ohp)
{
    extern __shared__ char fsm[];
    const uint32_t sb = smem_u32(fsm);
    const uint32_t Qh_s = sb;
    const uint32_t ST = sb + 32768;  // per stage: Kh(16K) Vh(16K)

    const int qb = (int)gridDim.x - 1 - (int)blockIdx.x;  // heavy tiles first
    const int h = blockIdx.y, b = blockIdx.z;
    const int kvh = h >> 2;
    const int tid = threadIdx.x;
    const int lane = tid & 31, wid = tid >> 5;
    const int g = lane >> 2, qq = lane & 3;
    const int q0 = qb * 128;
    const int q0w = q0 + wid * 16;
    const int nkv = 2 * qb + 2;

#pragma unroll
    for (int i = 0; i < 8; i++) {
        int id = i * 256 + tid;
        int c = id & 15, r = id >> 4;
        CP16(Qh_s + SWZ256(r, c),
             qh + ((size_t)(b * T_LEN + q0 + r) * NH + h) * HD + c * 8);
    }
    CP_COMMIT();

    auto issue_kv = [&](int stage, int kt) {
        const int kv0 = kt * 64;
        const uint32_t sbs = ST + stage * FA_KV_STAGE;
#pragma unroll
        for (int i = 0; i < 8; i++) {
            int id = i * 256 + tid;
            int c = id & 15, r = (id >> 4) & 63, arr = id >> 10;  // k, v
            const __half* src = arr ? vh : kh;
            uint32_t dst = sbs + arr * 16384 + SWZ256(r, c);
            CP16(dst, src + ((size_t)(b * T_LEN + kv0 + r) * NKV + kvh) * HD + c * 8);
        }
    };

    issue_kv(0, 0);
    CP_COMMIT();

    float m0 = -1e30f, m1 = -1e30f, l0 = 0.f, l1 = 0.f;
    float Oacc[16][4];
#pragma unroll
    for (int nt = 0; nt < 16; nt++)
#pragma unroll
        for (int e = 0; e < 4; e++) Oacc[nt][e] = 0.f;

    const int lrow = lane & 15, lc = lane >> 4;

    for (int kt = 0; kt < nkv; kt++) {
        if (kt + 1 < nkv) {
            issue_kv((kt + 1) & 1, kt + 1);
            CP_COMMIT();
            CP_WAIT(1);
        } else {
            CP_WAIT(0);
        }
        __syncthreads();

        const int kv0 = kt * 64;
        const uint32_t sbs = ST + (kt & 1) * FA_KV_STAGE;

        if (kv0 <= q0w + 15) {
            float S[8][4];
#pragma unroll
            for (int nt = 0; nt < 8; nt++)
#pragma unroll
                for (int e = 0; e < 4; e++) S[nt][e] = 0.f;

#pragma unroll
            for (int ks = 0; ks < 8; ks++) {
                const int c = ks * 2 + lc;
                int qr = wid * 16 + lrow;
                uint32_t aq[4];
                LDSM_X4(aq[0], aq[1], aq[2], aq[3], Qh_s + SWZ256(qr, c));
#pragma unroll
                for (int j = 0; j < 4; j++) {
                    int r = 16 * j + lrow;
                    uint32_t b4[4];
                    LDSM_X4(b4[0], b4[1], b4[2], b4[3], sbs + SWZ256(r, c));
#pragma unroll
                    for (int half = 0; half < 2; half++)
                        mma_h(S[2 * j + half], aq, b4[half], b4[half + 2]);
                }
            }

            if (kv0 + 63 > q0w) {
#pragma unroll
                for (int nt = 0; nt < 8; nt++) {
                    int col = kv0 + nt * 8 + qq * 2;
                    int r0 = q0w + g, r1 = q0w + g + 8;
                    if (col > r0) S[nt][0] = -1e30f;
                    if (col + 1 > r0) S[nt][1] = -1e30f;
                    if (col > r1) S[nt][2] = -1e30f;
                    if (col + 1 > r1) S[nt][3] = -1e30f;
                }
            }

            float mx0 = -1e30f, mx1 = -1e30f;
#pragma unroll
            for (int nt = 0; nt < 8; nt++) {
                mx0 = fmaxf(mx0, fmaxf(S[nt][0], S[nt][1]));
                mx1 = fmaxf(mx1, fmaxf(S[nt][2], S[nt][3]));
            }
            mx0 = fmaxf(mx0, __shfl_xor_sync(0xffffffffu, mx0, 1));
            mx0 = fmaxf(mx0, __shfl_xor_sync(0xffffffffu, mx0, 2));
            mx1 = fmaxf(mx1, __shfl_xor_sync(0xffffffffu, mx1, 1));
            mx1 = fmaxf(mx1, __shfl_xor_sync(0xffffffffu, mx1, 2));
            float mn0 = fmaxf(m0, mx0), mn1 = fmaxf(m1, mx1);
            float al0 = exp2f(m0 - mn0), al1 = exp2f(m1 - mn1);
            m0 = mn0; m1 = mn1;
            float sum0 = 0.f, sum1 = 0.f;
#pragma unroll
            for (int nt = 0; nt < 8; nt++) {
                S[nt][0] = exp2f(S[nt][0] - mn0);
                S[nt][1] = exp2f(S[nt][1] - mn0);
                S[nt][2] = exp2f(S[nt][2] - mn1);
                S[nt][3] = exp2f(S[nt][3] - mn1);
                sum0 += S[nt][0] + S[nt][1];
                sum1 += S[nt][2] + S[nt][3];
            }
            sum0 += __shfl_xor_sync(0xffffffffu, sum0, 1);
            sum0 += __shfl_xor_sync(0xffffffffu, sum0, 2);
            sum1 += __shfl_xor_sync(0xffffffffu, sum1, 1);
            sum1 += __shfl_xor_sync(0xffffffffu, sum1, 2);
            l0 = l0 * al0 + sum0;
            l1 = l1 * al1 + sum1;
#pragma unroll
            for (int nt = 0; nt < 16; nt++) {
                Oacc[nt][0] *= al0; Oacc[nt][1] *= al0;
                Oacc[nt][2] *= al1; Oacc[nt][3] *= al1;
            }

            uint32_t Ph[4][4];
#pragma unroll
            for (int ktp = 0; ktp < 4; ktp++) {
                Ph[ktp][0] = pack_h2(S[2 * ktp][0], S[2 * ktp][1]);
                Ph[ktp][1] = pack_h2(S[2 * ktp][2], S[2 * ktp][3]);
                Ph[ktp][2] = pack_h2(S[2 * ktp + 1][0], S[2 * ktp + 1][1]);
                Ph[ktp][3] = pack_h2(S[2 * ktp + 1][2], S[2 * ktp + 1][3]);
            }

#pragma unroll
            for (int ktp = 0; ktp < 4; ktp++) {
#pragma unroll
                for (int j = 0; j < 8; j++) {
                    int r = ktp * 16 + lrow;
                    int c = 2 * j + lc;
                    uint32_t v0, v1, v2, v3;
                    LDSM_X4_T(v0, v1, v2, v3, sbs + 16384 + SWZ256(r, c));
                    mma_h(Oacc[2 * j], Ph[ktp], v0, v1);
                    mma_h(Oacc[2 * j + 1], Ph[ktp], v2, v3);
                }
            }
        }
        __syncthreads();
    }

    // ---- write O as fp16 (att layout [b*T, NH*HD]) ----
    float inv0 = 1.f / l0, inv1 = 1.f / l1;
    const size_t base0 = (size_t)(b * T_LEN + q0w + g) * (NH * HD) + h * HD;
    const size_t base1 = base0 + (size_t)8 * NH * HD;
#pragma unroll
    for (int nt = 0; nt < 16; nt++) {
        int col = nt * 8 + qq * 2;
        ((uint32_t*)ohp)[(base0 + col) >> 1] =
            pack_h2(Oacc[nt][0] * inv0, Oacc[nt][1] * inv0);
        ((uint32_t*)ohp)[(base1 + col) >> 1] =
            pack_h2(Oacc[nt][2] * inv1, Oacc[nt][3] * inv1);
    }
}

// ---------------- launcher ---------------------------------------------------
extern "C" void kernel_launch(void* const* d_in, const int* in_sizes, int n_in,
                              void* d_out, int out_size)
{
    const float* x       = (const float*)d_in[0];
    const float* Wq      = (const float*)d_in[1];
    const float* Wk      = (const float*)d_in[2];
    const float* Wv      = (const float*)d_in[3];
    const float* Wo      = (const float*)d_in[4];
    const float* q_scale = (const float*)d_in[5];
    const float* k_scale = (const float*)d_in[6];
    const float* cosT    = (const float*)d_in[7];
    const float* sinT    = (const float*)d_in[8];
    float* out = (float*)d_out;

    __half *xh, *ah, *wq, *wk, *wv, *wo, *qh, *kh, *vh;
    cudaGetSymbolAddress((void**)&xh, g_xh);
    cudaGetSymbolAddress((void**)&ah, g_ah);
    cudaGetSymbolAddress((void**)&wq, g_wq);  cudaGetSymbolAddress((void**)&wk, g_wk);
    cudaGetSymbolAddress((void**)&wv, g_wv);  cudaGetSymbolAddress((void**)&wo, g_wo);
    cudaGetSymbolAddress((void**)&qh, g_qh);
    cudaGetSymbolAddress((void**)&kh, g_kh);  cudaGetSymbolAddress((void**)&vh, g_vh);

    static bool attr_set = false;
    if (!attr_set) {
        cudaFuncSetAttribute(mma_gemm, cudaFuncAttributeMaxDynamicSharedMemorySize, GEMM_SMEM);
        cudaFuncSetAttribute(flash_mma, cudaFuncAttributeMaxDynamicSharedMemorySize, FA_SMEM);
        attr_set = true;
    }

    const int M = M_ROWS;  // 4096
    const float qk_scale = 1.4426950408889634f * 0.08838834764831845f;  // log2e/sqrt(HD)

    // one-time conversions
    cvt_h<<<(M * D_MODEL / 4 + 255) / 256, 256>>>((const float4*)x, (uint2*)xh, M * D_MODEL / 4);
    trans_cvt<<<dim3(D_MODEL / 32, D_MODEL / 32), 256>>>(Wq, wq, D_MODEL, D_MODEL);
    trans_cvt<<<dim3(NKV * HD / 32, D_MODEL / 32), 256>>>(Wk, wk, D_MODEL, NKV * HD);
    trans_cvt<<<dim3(NKV * HD / 32, D_MODEL / 32), 256>>>(Wv, wv, D_MODEL, NKV * HD);
    trans_cvt<<<dim3(D_MODEL / 32, D_MODEL / 32), 256>>>(Wo, wo, NH * HD, D_MODEL);

    // merged Q+K+V projections with fused RMSNorm+RoPE epilogues (one launch)
    // region 0: Q (16 blocks, norm+rope, prescale)  region 1: K (4, norm+rope)
    // region 2: V (4, plain fp16)
    mma_gemm<<<dim3(24, M / 128), 256, GEMM_SMEM>>>(
        xh, wq, wk, wv, qh, kh, vh,
        2, 2, 1,
        q_scale, k_scale, cosT, sinT,
        qk_scale, 1.0f,
        D_MODEL, 16, 4, NH * HD, NKV * HD, NKV * HD);

    // flash attention -> fp16
    flash_mma<<<dim3(T_LEN / 128, NH, BATCH), 256, FA_SMEM>>>(qh, kh, vh, ah);

    // output projection (fp32 out)
    mma_gemm<<<dim3(16, M / 128), 256, GEMM_SMEM>>>(
        ah, wo, nullptr, nullptr, out, nullptr, nullptr,
        0, 0, 0,
        nullptr, nullptr, nullptr, nullptr,
        1.0f, 1.0f,
        D_MODEL, 16, 0, D_MODEL, 0, 0);
}

// round 11
// speedup vs baseline: 10.7483x; 1.0533x over previous
#include <cuda_runtime.h>
#include <cuda_fp16.h>
#include <math.h>
#include <stdint.h>

// Problem constants
#define BATCH 2
#define T_LEN 2048
#define D_MODEL 2048
#define NH 16
#define NKV 4
#define HD 128
#define EPS 1e-6f
#define M_ROWS (BATCH * T_LEN)  // 4096

// ---------------- scratch (device globals; no allocation allowed) ----------
__device__ __half g_xh[M_ROWS * D_MODEL];
__device__ __half g_ah[M_ROWS * D_MODEL];
__device__ __half g_wq[D_MODEL * D_MODEL];      // [N,K] transposed
__device__ __half g_wk[NKV * HD * D_MODEL];
__device__ __half g_wv[NKV * HD * D_MODEL];
__device__ __half g_wo[D_MODEL * D_MODEL];

__device__ __half g_qh[M_ROWS * NH * HD];
__device__ __half g_kh[M_ROWS * NKV * HD];
__device__ __half g_vh[M_ROWS * NKV * HD];

// ---------------- helpers -----------------------------------------------------
__device__ __forceinline__ uint32_t smem_u32(const void* p) {
    uint32_t a;
    asm("{ .reg .u64 t; cvta.to.shared.u64 t, %1; cvt.u32.u64 %0, t; }"
        : "=r"(a) : "l"(p));
    return a;
}

#define CP16(dst, src) \
    asm volatile("cp.async.cg.shared.global [%0], [%1], 16;" :: "r"(dst), "l"(src))
#define CP_COMMIT() asm volatile("cp.async.commit_group;" ::: "memory")
#define CP_WAIT(n)  asm volatile("cp.async.wait_group %0;" :: "n"(n) : "memory")

#define LDSM_X4(r0, r1, r2, r3, addr) \
    asm volatile("ldmatrix.sync.aligned.m8n8.x4.shared.b16 {%0,%1,%2,%3}, [%4];" \
                 : "=r"(r0), "=r"(r1), "=r"(r2), "=r"(r3) : "r"(addr))
#define LDSM_X4_T(r0, r1, r2, r3, addr) \
    asm volatile("ldmatrix.sync.aligned.m8n8.x4.trans.shared.b16 {%0,%1,%2,%3}, [%4];" \
                 : "=r"(r0), "=r"(r1), "=r"(r2), "=r"(r3) : "r"(addr))

// fp16 inputs, fp32 accumulator
__device__ __forceinline__ void mma_h(float* c, const uint32_t* a, uint32_t b0, uint32_t b1) {
    asm volatile(
        "mma.sync.aligned.m16n8k16.row.col.f32.f16.f16.f32 "
        "{%0,%1,%2,%3}, {%4,%5,%6,%7}, {%8,%9}, {%0,%1,%2,%3};"
        : "+f"(c[0]), "+f"(c[1]), "+f"(c[2]), "+f"(c[3])
        : "r"(a[0]), "r"(a[1]), "r"(a[2]), "r"(a[3]), "r"(b0), "r"(b1));
}

__device__ __forceinline__ uint32_t pack_h2(float x, float y) {
    __half2 h = __floats2half2_rn(x, y);
    return *reinterpret_cast<uint32_t*>(&h);
}

// ---------------- merged prep kernel: x cvt + 4 weight transposes -------------
// blocks [0,8192): x fp32 -> fp16 (float4 granularity)
// then Wq(4096) Wk(1024) Wv(1024) Wo(4096) 32x32 transpose+cvt tiles
__global__ __launch_bounds__(256) void prep(
    const float* __restrict__ x,
    const float* __restrict__ Wq, const float* __restrict__ Wk,
    const float* __restrict__ Wv, const float* __restrict__ Wo,
    __half* __restrict__ xh, __half* __restrict__ wq, __half* __restrict__ wk,
    __half* __restrict__ wv, __half* __restrict__ wo)
{
    __shared__ float tile[32][33];
    int bx = blockIdx.x;
    if (bx < 8192) {
        int i = bx * 256 + threadIdx.x;
        float4 v = ((const float4*)x)[i];
        ((uint2*)xh)[i] = make_uint2(pack_h2(v.x, v.y), pack_h2(v.z, v.w));
        return;
    }
    bx -= 8192;
    const float* W;
    __half* T;
    int N, t;
    if (bx < 4096)      { W = Wq; T = wq; N = 2048; t = bx; }
    else if (bx < 5120) { W = Wk; T = wk; N = 512;  t = bx - 4096; }
    else if (bx < 6144) { W = Wv; T = wv; N = 512;  t = bx - 5120; }
    else                { W = Wo; T = wo; N = 2048; t = bx - 6144; }
    const int K = 2048;
    const int ntn = N >> 5;
    const int n0 = (t % ntn) * 32, k0 = (t / ntn) * 32;
    const int tx = threadIdx.x & 31, ty4 = (threadIdx.x >> 5) * 4;
#pragma unroll
    for (int i = 0; i < 4; i++)
        tile[ty4 + i][tx] = W[(size_t)(k0 + ty4 + i) * N + n0 + tx];
    __syncthreads();
#pragma unroll
    for (int i = 0; i < 4; i++)
        T[(size_t)(n0 + ty4 + i) * K + k0 + tx] = __float2half_rn(tile[tx][ty4 + i]);
}

// ---------------- FP16 HMMA GEMM, 128x128 tile, 3-stage cp.async --------------
// C[M,N] = A[M,K] @ Bt[N,K]^T. 256 threads (warps 4x2), warp tile 32x64.
// Up to 3 B-regions selected by blockIdx.x; per-region epilogue mode:
//   0 = fp32 store, 1 = fp16 store, 2 = fused RMSNorm+RoPE -> fp16
#define G_STAGE 16384
#define GEMM_SMEM (3 * G_STAGE + 1024)

__global__ __launch_bounds__(256, 2) void mma_gemm(
    const __half* __restrict__ Ahp,
    const __half* __restrict__ B0, const __half* __restrict__ B1,
    const __half* __restrict__ B2,
    void* __restrict__ O0, void* __restrict__ O1, void* __restrict__ O2,
    int mode0, int mode1, int mode2,
    const float* __restrict__ sv0, const float* __restrict__ sv1,
    const float* __restrict__ cosT, const float* __restrict__ sinT,
    float ps0, float ps1,
    int K, int n0, int n1, int N0, int N1, int N2)
{
    extern __shared__ char smem[];
    const uint32_t sbase = smem_u32(smem);

    const int tid = threadIdx.x;
    const int lane = tid & 31, wid = tid >> 5;
    const int wm = wid >> 1, wn = wid & 1;
    const int bx = blockIdx.x;
    int mode, bn, N;
    const __half* B;
    void* O;
    const float* scaleV;
    float prescale;
    if (bx < n0) {
        mode = mode0; bn = bx * 128; B = B0; N = N0; O = O0;
        scaleV = sv0; prescale = ps0;
    } else if (bx < n0 + n1) {
        mode = mode1; bn = (bx - n0) * 128; B = B1; N = N1; O = O1;
        scaleV = sv1; prescale = ps1;
    } else {
        mode = mode2; bn = (bx - n0 - n1) * 128; B = B2; N = N2; O = O2;
        scaleV = sv0; prescale = 1.f;
    }
    const int bm = blockIdx.y * 128;
    const int NT = K / 32;

    float acc[2][8][4];
#pragma unroll
    for (int i = 0; i < 2; i++)
#pragma unroll
        for (int j = 0; j < 8; j++)
#pragma unroll
            for (int l = 0; l < 4; l++) acc[i][j][l] = 0.f;

    auto issue = [&](int it) {
        const int k0 = it * 32;
        const uint32_t sb = sbase + (it % 3) * G_STAGE;
#pragma unroll
        for (int i = 0; i < 4; i++) {
            int id = i * 256 + tid;          // 0..1023
            if (id < 512) {                  // A: 128 rows x 4 chunks
                int r = id >> 2, c = id & 3;
                uint32_t dst = sb + r * 64 + ((c ^ ((r >> 1) & 3)) << 4);
                CP16(dst, Ahp + (size_t)(bm + r) * K + k0 + c * 8);
            } else {                         // B: 128 rows x 4 chunks
                int idb = id - 512;
                int r = idb >> 2, c = idb & 3;
                uint32_t dst = sb + 8192 + r * 64 + ((c ^ ((r >> 1) & 3)) << 4);
                CP16(dst, B + (size_t)(bn + r) * K + k0 + c * 8);
            }
        }
    };

    issue(0); CP_COMMIT();
    issue(1); CP_COMMIT();

    const int lrow = lane & 15, lc = lane >> 4;

    for (int it = 0; it < NT; ++it) {
        if (it + 1 < NT) { CP_WAIT(1); } else { CP_WAIT(0); }
        __syncthreads();
        if (it + 2 < NT) { issue(it + 2); CP_COMMIT(); }

        const uint32_t sb = sbase + (it % 3) * G_STAGE;
#pragma unroll
        for (int ks = 0; ks < 2; ks++) {
            const int c = ks * 2 + lc;
            uint32_t ah[2][4];
#pragma unroll
            for (int mt = 0; mt < 2; mt++) {
                int r = wm * 32 + mt * 16 + lrow;
                uint32_t off = r * 64 + ((c ^ ((r >> 1) & 3)) << 4);
                LDSM_X4(ah[mt][0], ah[mt][1], ah[mt][2], ah[mt][3], sb + off);
            }
#pragma unroll
            for (int j = 0; j < 4; j++) {
                int r = wn * 64 + 16 * j + lrow;
                uint32_t off = r * 64 + ((c ^ ((r >> 1) & 3)) << 4);
                uint32_t b4[4];
                LDSM_X4(b4[0], b4[1], b4[2], b4[3], sb + 8192 + off);
#pragma unroll
                for (int half = 0; half < 2; half++) {
                    int nt = 2 * j + half;
#pragma unroll
                    for (int mt = 0; mt < 2; mt++)
                        mma_h(acc[mt][nt], ah[mt], b4[half], b4[half + 2]);
                }
            }
        }
        __syncthreads();
    }

    // ---- epilogue ----
    const int g = lane >> 2, q = lane & 3;
    if (mode == 0) {
        float* Cf = (float*)O;
#pragma unroll
        for (int mt = 0; mt < 2; mt++)
#pragma unroll
            for (int nt = 0; nt < 8; nt++) {
                int row = bm + wm * 32 + mt * 16 + g;
                int col = bn + wn * 64 + nt * 8 + 2 * q;
                *(float2*)&Cf[(size_t)row * N + col] =
                    make_float2(acc[mt][nt][0], acc[mt][nt][1]);
                *(float2*)&Cf[(size_t)(row + 8) * N + col] =
                    make_float2(acc[mt][nt][2], acc[mt][nt][3]);
            }
    } else if (mode == 1) {
        uint32_t* Ch = (uint32_t*)O;
#pragma unroll
        for (int mt = 0; mt < 2; mt++)
#pragma unroll
            for (int nt = 0; nt < 8; nt++) {
                int row = bm + wm * 32 + mt * 16 + g;
                int col = bn + wn * 64 + nt * 8 + 2 * q;
                Ch[((size_t)row * N + col) >> 1] =
                    pack_h2(acc[mt][nt][0], acc[mt][nt][1]);
                Ch[((size_t)(row + 8) * N + col) >> 1] =
                    pack_h2(acc[mt][nt][2], acc[mt][nt][3]);
            }
    } else {
        // fused RMSNorm (this block's 128 cols = one head) + RoPE -> fp16
        float* red = (float*)(smem + 3 * G_STAGE);  // [2 wn][128 rows]
#pragma unroll
        for (int mt = 0; mt < 2; mt++) {
            float s0 = 0.f, s1 = 0.f;
#pragma unroll
            for (int nt = 0; nt < 8; nt++) {
                s0 += acc[mt][nt][0] * acc[mt][nt][0] + acc[mt][nt][1] * acc[mt][nt][1];
                s1 += acc[mt][nt][2] * acc[mt][nt][2] + acc[mt][nt][3] * acc[mt][nt][3];
            }
            s0 += __shfl_xor_sync(0xffffffffu, s0, 1);
            s0 += __shfl_xor_sync(0xffffffffu, s0, 2);
            s1 += __shfl_xor_sync(0xffffffffu, s1, 1);
            s1 += __shfl_xor_sync(0xffffffffu, s1, 2);
            if (q == 0) {
                red[wn * 128 + wm * 32 + mt * 16 + g] = s0;
                red[wn * 128 + wm * 32 + mt * 16 + g + 8] = s1;
            }
        }
        __syncthreads();
        uint32_t* Ch = (uint32_t*)O;
#pragma unroll
        for (int mt = 0; mt < 2; mt++) {
#pragma unroll
            for (int rr = 0; rr < 2; rr++) {
                int r = wm * 32 + mt * 16 + g + rr * 8;
                float rinv = rsqrtf((red[r] + red[128 + r]) * (1.0f / HD) + EPS);
                int t = (bm + r) & (T_LEN - 1);
#pragma unroll
                for (int nt = 0; nt < 8; nt++) {
                    int d = wn * 64 + nt * 8 + 2 * q;
                    float2 sc = *(const float2*)&scaleV[d];
                    float2 cs = *(const float2*)&cosT[t * HD + d];
                    float2 sn = *(const float2*)&sinT[t * HD + d];
                    float v0 = acc[mt][nt][rr * 2 + 0] * rinv * sc.x;
                    float v1 = acc[mt][nt][rr * 2 + 1] * rinv * sc.y;
                    float o0 = (v0 * cs.x - v1 * sn.x) * prescale;
                    float o1 = (v1 * cs.y + v0 * sn.y) * prescale;
                    Ch[(((size_t)(bm + r)) * N + bn + d) >> 1] = pack_h2(o0, o1);
                }
            }
        }
    }
}

// ---------------- FP16 HMMA causal GQA flash attention ------------------------
// BQ=64 (4 warps x m16), BK=64, HD=128. Q persistent (16KB) +
// double-buffered K/V (2 x 32KB) = 80KB -> 2 CTAs/SM. 128 threads. fp16 out.
#define FA_KV_STAGE 32768
#define FA_SMEM (16384 + 2 * FA_KV_STAGE)
#define SWZ256(r, c) ((uint32_t)((r) * 256 + (((c) ^ ((r) & 7)) << 4)))

__global__ __launch_bounds__(128) void flash_mma(
    const __half* __restrict__ qh, const __half* __restrict__ kh,
    const __half* __restrict__ vh, __half* __restrict__ ohp)
{
    extern __shared__ char fsm[];
    const uint32_t sb = smem_u32(fsm);
    const uint32_t Qh_s = sb;
    const uint32_t ST = sb + 16384;  // per stage: Kh(16K) Vh(16K)

    const int qb = (int)gridDim.x - 1 - (int)blockIdx.x;  // heavy tiles first
    const int h = blockIdx.y, b = blockIdx.z;
    const int kvh = h >> 2;
    const int tid = threadIdx.x;
    const int lane = tid & 31, wid = tid >> 5;   // wid 0..3
    const int g = lane >> 2, qq = lane & 3;
    const int q0 = qb * 64;
    const int q0w = q0 + wid * 16;
    const int nkv = qb + 1;

    // ---- load Q (64 rows x 16 chunks = 1024) ----
#pragma unroll
    for (int i = 0; i < 8; i++) {
        int id = i * 128 + tid;
        int c = id & 15, r = id >> 4;
        CP16(Qh_s + SWZ256(r, c),
             qh + ((size_t)(b * T_LEN + q0 + r) * NH + h) * HD + c * 8);
    }
    CP_COMMIT();

    auto issue_kv = [&](int stage, int kt) {
        const int kv0 = kt * 64;
        const uint32_t sbs = ST + stage * FA_KV_STAGE;
#pragma unroll
        for (int i = 0; i < 16; i++) {
            int id = i * 128 + tid;
            int c = id & 15, r = (id >> 4) & 63, arr = id >> 10;  // k, v
            const __half* src = arr ? vh : kh;
            uint32_t dst = sbs + arr * 16384 + SWZ256(r, c);
            CP16(dst, src + ((size_t)(b * T_LEN + kv0 + r) * NKV + kvh) * HD + c * 8);
        }
    };

    issue_kv(0, 0);
    CP_COMMIT();

    float m0 = -1e30f, m1 = -1e30f, l0 = 0.f, l1 = 0.f;
    float Oacc[16][4];
#pragma unroll
    for (int nt = 0; nt < 16; nt++)
#pragma unroll
        for (int e = 0; e < 4; e++) Oacc[nt][e] = 0.f;

    const int lrow = lane & 15, lc = lane >> 4;

    for (int kt = 0; kt < nkv; kt++) {
        if (kt + 1 < nkv) {
            issue_kv((kt + 1) & 1, kt + 1);
            CP_COMMIT();
            CP_WAIT(1);
        } else {
            CP_WAIT(0);
        }
        __syncthreads();

        const int kv0 = kt * 64;
        const uint32_t sbs = ST + (kt & 1) * FA_KV_STAGE;

        {
            float S[8][4];
#pragma unroll
            for (int nt = 0; nt < 8; nt++)
#pragma unroll
                for (int e = 0; e < 4; e++) S[nt][e] = 0.f;

#pragma unroll
            for (int ks = 0; ks < 8; ks++) {
                const int c = ks * 2 + lc;
                int qr = wid * 16 + lrow;
                uint32_t aq[4];
                LDSM_X4(aq[0], aq[1], aq[2], aq[3], Qh_s + SWZ256(qr, c));
#pragma unroll
                for (int j = 0; j < 4; j++) {
                    int r = 16 * j + lrow;
                    uint32_t b4[4];
                    LDSM_X4(b4[0], b4[1], b4[2], b4[3], sbs + SWZ256(r, c));
#pragma unroll
                    for (int half = 0; half < 2; half++)
                        mma_h(S[2 * j + half], aq, b4[half], b4[half + 2]);
                }
            }

            if (kv0 + 63 > q0w) {  // diagonal region: mask
#pragma unroll
                for (int nt = 0; nt < 8; nt++) {
                    int col = kv0 + nt * 8 + qq * 2;
                    int r0 = q0w + g, r1 = q0w + g + 8;
                    if (col > r0) S[nt][0] = -1e30f;
                    if (col + 1 > r0) S[nt][1] = -1e30f;
                    if (col > r1) S[nt][2] = -1e30f;
                    if (col + 1 > r1) S[nt][3] = -1e30f;
                }
            }

            float mx0 = -1e30f, mx1 = -1e30f;
#pragma unroll
            for (int nt = 0; nt < 8; nt++) {
                mx0 = fmaxf(mx0, fmaxf(S[nt][0], S[nt][1]));
                mx1 = fmaxf(mx1, fmaxf(S[nt][2], S[nt][3]));
            }
            mx0 = fmaxf(mx0, __shfl_xor_sync(0xffffffffu, mx0, 1));
            mx0 = fmaxf(mx0, __shfl_xor_sync(0xffffffffu, mx0, 2));
            mx1 = fmaxf(mx1, __shfl_xor_sync(0xffffffffu, mx1, 1));
            mx1 = fmaxf(mx1, __shfl_xor_sync(0xffffffffu, mx1, 2));
            float mn0 = fmaxf(m0, mx0), mn1 = fmaxf(m1, mx1);
            float al0 = exp2f(m0 - mn0), al1 = exp2f(m1 - mn1);
            m0 = mn0; m1 = mn1;
            float sum0 = 0.f, sum1 = 0.f;
#pragma unroll
            for (int nt = 0; nt < 8; nt++) {
                S[nt][0] = exp2f(S[nt][0] - mn0);
                S[nt][1] = exp2f(S[nt][1] - mn0);
                S[nt][2] = exp2f(S[nt][2] - mn1);
                S[nt][3] = exp2f(S[nt][3] - mn1);
                sum0 += S[nt][0] + S[nt][1];
                sum1 += S[nt][2] + S[nt][3];
            }
            sum0 += __shfl_xor_sync(0xffffffffu, sum0, 1);
            sum0 += __shfl_xor_sync(0xffffffffu, sum0, 2);
            sum1 += __shfl_xor_sync(0xffffffffu, sum1, 1);
            sum1 += __shfl_xor_sync(0xffffffffu, sum1, 2);
            l0 = l0 * al0 + sum0;
            l1 = l1 * al1 + sum1;
#pragma unroll
            for (int nt = 0; nt < 16; nt++) {
                Oacc[nt][0] *= al0; Oacc[nt][1] *= al0;
                Oacc[nt][2] *= al1; Oacc[nt][3] *= al1;
            }

            uint32_t Ph[4][4];
#pragma unroll
            for (int ktp = 0; ktp < 4; ktp++) {
                Ph[ktp][0] = pack_h2(S[2 * ktp][0], S[2 * ktp][1]);
                Ph[ktp][1] = pack_h2(S[2 * ktp][2], S[2 * ktp][3]);
                Ph[ktp][2] = pack_h2(S[2 * ktp + 1][0], S[2 * ktp + 1][1]);
                Ph[ktp][3] = pack_h2(S[2 * ktp + 1][2], S[2 * ktp + 1][3]);
            }

#pragma unroll
            for (int ktp = 0; ktp < 4; ktp++) {
#pragma unroll
                for (int j = 0; j < 8; j++) {
                    int r = ktp * 16 + lrow;
                    int c = 2 * j + lc;
                    uint32_t v0, v1, v2, v3;
                    LDSM_X4_T(v0, v1, v2, v3, sbs + 16384 + SWZ256(r, c));
                    mma_h(Oacc[2 * j], Ph[ktp], v0, v1);
                    mma_h(Oacc[2 * j + 1], Ph[ktp], v2, v3);
                }
            }
        }
        __syncthreads();
    }

    // ---- write O as fp16 (att layout [b*T, NH*HD]) ----
    float inv0 = 1.f / l0, inv1 = 1.f / l1;
    const size_t base0 = (size_t)(b * T_LEN + q0w + g) * (NH * HD) + h * HD;
    const size_t base1 = base0 + (size_t)8 * NH * HD;
#pragma unroll
    for (int nt = 0; nt < 16; nt++) {
        int col = nt * 8 + qq * 2;
        ((uint32_t*)ohp)[(base0 + col) >> 1] =
            pack_h2(Oacc[nt][0] * inv0, Oacc[nt][1] * inv0);
        ((uint32_t*)ohp)[(base1 + col) >> 1] =
            pack_h2(Oacc[nt][2] * inv1, Oacc[nt][3] * inv1);
    }
}

// ---------------- launcher ---------------------------------------------------
extern "C" void kernel_launch(void* const* d_in, const int* in_sizes, int n_in,
                              void* d_out, int out_size)
{
    const float* x       = (const float*)d_in[0];
    const float* Wq      = (const float*)d_in[1];
    const float* Wk      = (const float*)d_in[2];
    const float* Wv      = (const float*)d_in[3];
    const float* Wo      = (const float*)d_in[4];
    const float* q_scale = (const float*)d_in[5];
    const float* k_scale = (const float*)d_in[6];
    const float* cosT    = (const float*)d_in[7];
    const float* sinT    = (const float*)d_in[8];
    float* out = (float*)d_out;

    __half *xh, *ah, *wq, *wk, *wv, *wo, *qh, *kh, *vh;
    cudaGetSymbolAddress((void**)&xh, g_xh);
    cudaGetSymbolAddress((void**)&ah, g_ah);
    cudaGetSymbolAddress((void**)&wq, g_wq);  cudaGetSymbolAddress((void**)&wk, g_wk);
    cudaGetSymbolAddress((void**)&wv, g_wv);  cudaGetSymbolAddress((void**)&wo, g_wo);
    cudaGetSymbolAddress((void**)&qh, g_qh);
    cudaGetSymbolAddress((void**)&kh, g_kh);  cudaGetSymbolAddress((void**)&vh, g_vh);

    static bool attr_set = false;
    if (!attr_set) {
        cudaFuncSetAttribute(mma_gemm, cudaFuncAttributeMaxDynamicSharedMemorySize, GEMM_SMEM);
        cudaFuncSetAttribute(flash_mma, cudaFuncAttributeMaxDynamicSharedMemorySize, FA_SMEM);
        attr_set = true;
    }

    const int M = M_ROWS;  // 4096
    const float qk_scale = 1.4426950408889634f * 0.08838834764831845f;  // log2e/sqrt(HD)

    // one merged conversion launch: x cvt (8192 blocks) + 4 transposes (10240)
    prep<<<18432, 256>>>(x, Wq, Wk, Wv, Wo, xh, wq, wk, wv, wo);

    // merged Q+K+V projections with fused RMSNorm+RoPE epilogues (one launch)
    mma_gemm<<<dim3(24, M / 128), 256, GEMM_SMEM>>>(
        xh, wq, wk, wv, qh, kh, vh,
        2, 2, 1,
        q_scale, k_scale, cosT, sinT,
        qk_scale, 1.0f,
        D_MODEL, 16, 4, NH * HD, NKV * HD, NKV * HD);

    // flash attention -> fp16 (BQ=64, 2 CTAs/SM)
    flash_mma<<<dim3(T_LEN / 64, NH, BATCH), 128, FA_SMEM>>>(qh, kh, vh, ah);

    // output projection (fp32 out)
    mma_gemm<<<dim3(16, M / 128), 256, GEMM_SMEM>>>(
        ah, wo, nullptr, nullptr, out, nullptr, nullptr,
        0, 0, 0,
        nullptr, nullptr, nullptr, nullptr,
        1.0f, 1.0f,
        D_MODEL, 16, 0, D_MODEL, 0, 0);
}

// round 12
// speedup vs baseline: 11.9700x; 1.1137x over previous
#include <cuda_runtime.h>
#include <cuda_fp16.h>
#include <math.h>
#include <stdint.h>

// Problem constants
#define BATCH 2
#define T_LEN 2048
#define D_MODEL 2048
#define NH 16
#define NKV 4
#define HD 128
#define EPS 1e-6f
#define M_ROWS (BATCH * T_LEN)  // 4096

// ---------------- scratch (device globals; no allocation allowed) ----------
__device__ __half g_xh[M_ROWS * D_MODEL];
__device__ __half g_ah[M_ROWS * D_MODEL];
__device__ __half g_wq[D_MODEL * D_MODEL];      // [N,K] transposed
__device__ __half g_wk[NKV * HD * D_MODEL];
__device__ __half g_wv[NKV * HD * D_MODEL];
__device__ __half g_wo[D_MODEL * D_MODEL];

__device__ __half g_qh[M_ROWS * NH * HD];
__device__ __half g_kh[M_ROWS * NKV * HD];
__device__ __half g_vh[M_ROWS * NKV * HD];

// ---------------- helpers -----------------------------------------------------
__device__ __forceinline__ uint32_t smem_u32(const void* p) {
    uint32_t a;
    asm("{ .reg .u64 t; cvta.to.shared.u64 t, %1; cvt.u32.u64 %0, t; }"
        : "=r"(a) : "l"(p));
    return a;
}

#define CP16(dst, src) \
    asm volatile("cp.async.cg.shared.global [%0], [%1], 16;" :: "r"(dst), "l"(src))
#define CP_COMMIT() asm volatile("cp.async.commit_group;" ::: "memory")
#define CP_WAIT(n)  asm volatile("cp.async.wait_group %0;" :: "n"(n) : "memory")

#define LDSM_X4(r0, r1, r2, r3, addr) \
    asm volatile("ldmatrix.sync.aligned.m8n8.x4.shared.b16 {%0,%1,%2,%3}, [%4];" \
                 : "=r"(r0), "=r"(r1), "=r"(r2), "=r"(r3) : "r"(addr))
#define LDSM_X4_T(r0, r1, r2, r3, addr) \
    asm volatile("ldmatrix.sync.aligned.m8n8.x4.trans.shared.b16 {%0,%1,%2,%3}, [%4];" \
                 : "=r"(r0), "=r"(r1), "=r"(r2), "=r"(r3) : "r"(addr))

// fp16 inputs, fp32 accumulator
__device__ __forceinline__ void mma_h(float* c, const uint32_t* a, uint32_t b0, uint32_t b1) {
    asm volatile(
        "mma.sync.aligned.m16n8k16.row.col.f32.f16.f16.f32 "
        "{%0,%1,%2,%3}, {%4,%5,%6,%7}, {%8,%9}, {%0,%1,%2,%3};"
        : "+f"(c[0]), "+f"(c[1]), "+f"(c[2]), "+f"(c[3])
        : "r"(a[0]), "r"(a[1]), "r"(a[2]), "r"(a[3]), "r"(b0), "r"(b1));
}

__device__ __forceinline__ uint32_t pack_h2(float x, float y) {
    __half2 h = __floats2half2_rn(x, y);
    return *reinterpret_cast<uint32_t*>(&h);
}

// ---------------- merged prep kernel: x cvt + 4 weight transposes -------------
__global__ __launch_bounds__(256) void prep(
    const float* __restrict__ x,
    const float* __restrict__ Wq, const float* __restrict__ Wk,
    const float* __restrict__ Wv, const float* __restrict__ Wo,
    __half* __restrict__ xh, __half* __restrict__ wq, __half* __restrict__ wk,
    __half* __restrict__ wv, __half* __restrict__ wo)
{
    __shared__ float tile[32][33];
    int bx = blockIdx.x;
    if (bx < 8192) {
        int i = bx * 256 + threadIdx.x;
        float4 v = ((const float4*)x)[i];
        ((uint2*)xh)[i] = make_uint2(pack_h2(v.x, v.y), pack_h2(v.z, v.w));
        return;
    }
    bx -= 8192;
    const float* W;
    __half* T;
    int N, t;
    if (bx < 4096)      { W = Wq; T = wq; N = 2048; t = bx; }
    else if (bx < 5120) { W = Wk; T = wk; N = 512;  t = bx - 4096; }
    else if (bx < 6144) { W = Wv; T = wv; N = 512;  t = bx - 5120; }
    else                { W = Wo; T = wo; N = 2048; t = bx - 6144; }
    const int K = 2048;
    const int ntn = N >> 5;
    const int n0 = (t % ntn) * 32, k0 = (t / ntn) * 32;
    const int tx = threadIdx.x & 31, ty4 = (threadIdx.x >> 5) * 4;
#pragma unroll
    for (int i = 0; i < 4; i++)
        tile[ty4 + i][tx] = W[(size_t)(k0 + ty4 + i) * N + n0 + tx];
    __syncthreads();
#pragma unroll
    for (int i = 0; i < 4; i++)
        T[(size_t)(n0 + ty4 + i) * K + k0 + tx] = __float2half_rn(tile[tx][ty4 + i]);
}

// ---------------- FP16 HMMA GEMM, 128x128 tile, BK=64, 3-stage cp.async -------
// C[M,N] = A[M,K] @ Bt[N,K]^T. 256 threads (warps 4x2), warp tile 32x64.
// Stage = 128x64 A (16KB) + 128x64 B (16KB); 128B rows, SW128 swizzle
// chunk' = c ^ (r&7). ONE barrier per 4 k16-steps.
// Epilogue modes: 0 = fp32 store, 1 = fp16 store, 2 = RMSNorm+RoPE -> fp16
#define G_STAGE 32768
#define GEMM_SMEM (3 * G_STAGE + 1024)
#define SWZG(r, c) ((uint32_t)((r) * 128 + (((c) ^ ((r) & 7)) << 4)))

__global__ __launch_bounds__(256, 2) void mma_gemm(
    const __half* __restrict__ Ahp,
    const __half* __restrict__ B0, const __half* __restrict__ B1,
    const __half* __restrict__ B2,
    void* __restrict__ O0, void* __restrict__ O1, void* __restrict__ O2,
    int mode0, int mode1, int mode2,
    const float* __restrict__ sv0, const float* __restrict__ sv1,
    const float* __restrict__ cosT, const float* __restrict__ sinT,
    float ps0, float ps1,
    int K, int n0, int n1, int N0, int N1, int N2)
{
    extern __shared__ char smem[];
    const uint32_t sbase = smem_u32(smem);

    const int tid = threadIdx.x;
    const int lane = tid & 31, wid = tid >> 5;
    const int wm = wid >> 1, wn = wid & 1;
    const int bx = blockIdx.x;
    int mode, bn, N;
    const __half* B;
    void* O;
    const float* scaleV;
    float prescale;
    if (bx < n0) {
        mode = mode0; bn = bx * 128; B = B0; N = N0; O = O0;
        scaleV = sv0; prescale = ps0;
    } else if (bx < n0 + n1) {
        mode = mode1; bn = (bx - n0) * 128; B = B1; N = N1; O = O1;
        scaleV = sv1; prescale = ps1;
    } else {
        mode = mode2; bn = (bx - n0 - n1) * 128; B = B2; N = N2; O = O2;
        scaleV = sv0; prescale = 1.f;
    }
    const int bm = blockIdx.y * 128;
    const int NT = K / 64;

    float acc[2][8][4];
#pragma unroll
    for (int i = 0; i < 2; i++)
#pragma unroll
        for (int j = 0; j < 8; j++)
#pragma unroll
            for (int l = 0; l < 4; l++) acc[i][j][l] = 0.f;

    auto issue = [&](int it) {
        const int k0 = it * 64;
        const uint32_t sb = sbase + (it % 3) * G_STAGE;
#pragma unroll
        for (int i = 0; i < 8; i++) {
            int id = i * 256 + tid;          // 0..2047
            int r = (id >> 3) & 127, c = id & 7;
            if (id < 1024) {                 // A: 128 rows x 8 chunks
                CP16(sb + SWZG(r, c), Ahp + (size_t)(bm + r) * K + k0 + c * 8);
            } else {                         // B: 128 rows x 8 chunks
                CP16(sb + 16384 + SWZG(r, c), B + (size_t)(bn + r) * K + k0 + c * 8);
            }
        }
    };

    issue(0); CP_COMMIT();
    issue(1); CP_COMMIT();

    const int lrow = lane & 15, lc = lane >> 4;

    for (int it = 0; it < NT; ++it) {
        if (it + 1 < NT) { CP_WAIT(1); } else { CP_WAIT(0); }
        __syncthreads();
        if (it + 2 < NT) { issue(it + 2); CP_COMMIT(); }

        const uint32_t sb = sbase + (it % 3) * G_STAGE;
#pragma unroll
        for (int ks = 0; ks < 4; ks++) {
            const int c = ks * 2 + lc;
            uint32_t ah[2][4];
#pragma unroll
            for (int mt = 0; mt < 2; mt++) {
                int r = wm * 32 + mt * 16 + lrow;
                LDSM_X4(ah[mt][0], ah[mt][1], ah[mt][2], ah[mt][3], sb + SWZG(r, c));
            }
#pragma unroll
            for (int j = 0; j < 4; j++) {
                int r = wn * 64 + 16 * j + lrow;
                uint32_t b4[4];
                LDSM_X4(b4[0], b4[1], b4[2], b4[3], sb + 16384 + SWZG(r, c));
#pragma unroll
                for (int half = 0; half < 2; half++) {
                    int nt = 2 * j + half;
#pragma unroll
                    for (int mt = 0; mt < 2; mt++)
                        mma_h(acc[mt][nt], ah[mt], b4[half], b4[half + 2]);
                }
            }
        }
        __syncthreads();
    }

    // ---- epilogue ----
    const int g = lane >> 2, q = lane & 3;
    if (mode == 0) {
        float* Cf = (float*)O;
#pragma unroll
        for (int mt = 0; mt < 2; mt++)
#pragma unroll
            for (int nt = 0; nt < 8; nt++) {
                int row = bm + wm * 32 + mt * 16 + g;
                int col = bn + wn * 64 + nt * 8 + 2 * q;
                *(float2*)&Cf[(size_t)row * N + col] =
                    make_float2(acc[mt][nt][0], acc[mt][nt][1]);
                *(float2*)&Cf[(size_t)(row + 8) * N + col] =
                    make_float2(acc[mt][nt][2], acc[mt][nt][3]);
            }
    } else if (mode == 1) {
        uint32_t* Ch = (uint32_t*)O;
#pragma unroll
        for (int mt = 0; mt < 2; mt++)
#pragma unroll
            for (int nt = 0; nt < 8; nt++) {
                int row = bm + wm * 32 + mt * 16 + g;
                int col = bn + wn * 64 + nt * 8 + 2 * q;
                Ch[((size_t)row * N + col) >> 1] =
                    pack_h2(acc[mt][nt][0], acc[mt][nt][1]);
                Ch[((size_t)(row + 8) * N + col) >> 1] =
                    pack_h2(acc[mt][nt][2], acc[mt][nt][3]);
            }
    } else {
        // fused RMSNorm (this block's 128 cols = one head) + RoPE -> fp16
        float* red = (float*)(smem + 3 * G_STAGE);  // [2 wn][128 rows]
#pragma unroll
        for (int mt = 0; mt < 2; mt++) {
            float s0 = 0.f, s1 = 0.f;
#pragma unroll
            for (int nt = 0; nt < 8; nt++) {
                s0 += acc[mt][nt][0] * acc[mt][nt][0] + acc[mt][nt][1] * acc[mt][nt][1];
                s1 += acc[mt][nt][2] * acc[mt][nt][2] + acc[mt][nt][3] * acc[mt][nt][3];
            }
            s0 += __shfl_xor_sync(0xffffffffu, s0, 1);
            s0 += __shfl_xor_sync(0xffffffffu, s0, 2);
            s1 += __shfl_xor_sync(0xffffffffu, s1, 1);
            s1 += __shfl_xor_sync(0xffffffffu, s1, 2);
            if (q == 0) {
                red[wn * 128 + wm * 32 + mt * 16 + g] = s0;
                red[wn * 128 + wm * 32 + mt * 16 + g + 8] = s1;
            }
        }
        __syncthreads();
        uint32_t* Ch = (uint32_t*)O;
#pragma unroll
        for (int mt = 0; mt < 2; mt++) {
#pragma unroll
            for (int rr = 0; rr < 2; rr++) {
                int r = wm * 32 + mt * 16 + g + rr * 8;
                float rinv = rsqrtf((red[r] + red[128 + r]) * (1.0f / HD) + EPS);
                int t = (bm + r) & (T_LEN - 1);
#pragma unroll
                for (int nt = 0; nt < 8; nt++) {
                    int d = wn * 64 + nt * 8 + 2 * q;
                    float2 sc = *(const float2*)&scaleV[d];
                    float2 cs = *(const float2*)&cosT[t * HD + d];
                    float2 sn = *(const float2*)&sinT[t * HD + d];
                    float v0 = acc[mt][nt][rr * 2 + 0] * rinv * sc.x;
                    float v1 = acc[mt][nt][rr * 2 + 1] * rinv * sc.y;
                    float o0 = (v0 * cs.x - v1 * sn.x) * prescale;
                    float o1 = (v1 * cs.y + v0 * sn.y) * prescale;
                    Ch[(((size_t)(bm + r)) * N + bn + d) >> 1] = pack_h2(o0, o1);
                }
            }
        }
    }
}

// ---------------- FP16 HMMA causal GQA flash attention ------------------------
// BQ=64 (4 warps x m16), BK=64, HD=128. Q persistent (16KB) +
// double-buffered K/V (2 x 32KB) = 80KB -> 2 CTAs/SM. 128 threads. fp16 out.
#define FA_KV_STAGE 32768
#define FA_SMEM (16384 + 2 * FA_KV_STAGE)
#define SWZ256(r, c) ((uint32_t)((r) * 256 + (((c) ^ ((r) & 7)) << 4)))

__global__ __launch_bounds__(128) void flash_mma(
    const __half* __restrict__ qh, const __half* __restrict__ kh,
    const __half* __restrict__ vh, __half* __restrict__ ohp)
{
    extern __shared__ char fsm[];
    const uint32_t sb = smem_u32(fsm);
    const uint32_t Qh_s = sb;
    const uint32_t ST = sb + 16384;  // per stage: Kh(16K) Vh(16K)

    const int qb = (int)gridDim.x - 1 - (int)blockIdx.x;  // heavy tiles first
    const int h = blockIdx.y, b = blockIdx.z;
    const int kvh = h >> 2;
    const int tid = threadIdx.x;
    const int lane = tid & 31, wid = tid >> 5;   // wid 0..3
    const int g = lane >> 2, qq = lane & 3;
    const int q0 = qb * 64;
    const int q0w = q0 + wid * 16;
    const int nkv = qb + 1;

#pragma unroll
    for (int i = 0; i < 8; i++) {
        int id = i * 128 + tid;
        int c = id & 15, r = id >> 4;
        CP16(Qh_s + SWZ256(r, c),
             qh + ((size_t)(b * T_LEN + q0 + r) * NH + h) * HD + c * 8);
    }
    CP_COMMIT();

    auto issue_kv = [&](int stage, int kt) {
        const int kv0 = kt * 64;
        const uint32_t sbs = ST + stage * FA_KV_STAGE;
#pragma unroll
        for (int i = 0; i < 16; i++) {
            int id = i * 128 + tid;
            int c = id & 15, r = (id >> 4) & 63, arr = id >> 10;  // k, v
            const __half* src = arr ? vh : kh;
            uint32_t dst = sbs + arr * 16384 + SWZ256(r, c);
            CP16(dst, src + ((size_t)(b * T_LEN + kv0 + r) * NKV + kvh) * HD + c * 8);
        }
    };

    issue_kv(0, 0);
    CP_COMMIT();

    float m0 = -1e30f, m1 = -1e30f, l0 = 0.f, l1 = 0.f;
    float Oacc[16][4];
#pragma unroll
    for (int nt = 0; nt < 16; nt++)
#pragma unroll
        for (int e = 0; e < 4; e++) Oacc[nt][e] = 0.f;

    const int lrow = lane & 15, lc = lane >> 4;

    for (int kt = 0; kt < nkv; kt++) {
        if (kt + 1 < nkv) {
            issue_kv((kt + 1) & 1, kt + 1);
            CP_COMMIT();
            CP_WAIT(1);
        } else {
            CP_WAIT(0);
        }
        __syncthreads();

        const int kv0 = kt * 64;
        const uint32_t sbs = ST + (kt & 1) * FA_KV_STAGE;

        {
            float S[8][4];
#pragma unroll
            for (int nt = 0; nt < 8; nt++)
#pragma unroll
                for (int e = 0; e < 4; e++) S[nt][e] = 0.f;

#pragma unroll
            for (int ks = 0; ks < 8; ks++) {
                const int c = ks * 2 + lc;
                int qr = wid * 16 + lrow;
                uint32_t aq[4];
                LDSM_X4(aq[0], aq[1], aq[2], aq[3], Qh_s + SWZ256(qr, c));
#pragma unroll
                for (int j = 0; j < 4; j++) {
                    int r = 16 * j + lrow;
                    uint32_t b4[4];
                    LDSM_X4(b4[0], b4[1], b4[2], b4[3], sbs + SWZ256(r, c));
#pragma unroll
                    for (int half = 0; half < 2; half++)
                        mma_h(S[2 * j + half], aq, b4[half], b4[half + 2]);
                }
            }

            if (kv0 + 63 > q0w) {  // diagonal region: mask
#pragma unroll
                for (int nt = 0; nt < 8; nt++) {
                    int col = kv0 + nt * 8 + qq * 2;
                    int r0 = q0w + g, r1 = q0w + g + 8;
                    if (col > r0) S[nt][0] = -1e30f;
                    if (col + 1 > r0) S[nt][1] = -1e30f;
                    if (col > r1) S[nt][2] = -1e30f;
                    if (col + 1 > r1) S[nt][3] = -1e30f;
                }
            }

            float mx0 = -1e30f, mx1 = -1e30f;
#pragma unroll
            for (int nt = 0; nt < 8; nt++) {
                mx0 = fmaxf(mx0, fmaxf(S[nt][0], S[nt][1]));
                mx1 = fmaxf(mx1, fmaxf(S[nt][2], S[nt][3]));
            }
            mx0 = fmaxf(mx0, __shfl_xor_sync(0xffffffffu, mx0, 1));
            mx0 = fmaxf(mx0, __shfl_xor_sync(0xffffffffu, mx0, 2));
            mx1 = fmaxf(mx1, __shfl_xor_sync(0xffffffffu, mx1, 1));
            mx1 = fmaxf(mx1, __shfl_xor_sync(0xffffffffu, mx1, 2));
            float mn0 = fmaxf(m0, mx0), mn1 = fmaxf(m1, mx1);
            float al0 = exp2f(m0 - mn0), al1 = exp2f(m1 - mn1);
            m0 = mn0; m1 = mn1;
            float sum0 = 0.f, sum1 = 0.f;
#pragma unroll
            for (int nt = 0; nt < 8; nt++) {
                S[nt][0] = exp2f(S[nt][0] - mn0);
                S[nt][1] = exp2f(S[nt][1] - mn0);
                S[nt][2] = exp2f(S[nt][2] - mn1);
                S[nt][3] = exp2f(S[nt][3] - mn1);
                sum0 += S[nt][0] + S[nt][1];
                sum1 += S[nt][2] + S[nt][3];
            }
            sum0 += __shfl_xor_sync(0xffffffffu, sum0, 1);
            sum0 += __shfl_xor_sync(0xffffffffu, sum0, 2);
            sum1 += __shfl_xor_sync(0xffffffffu, sum1, 1);
            sum1 += __shfl_xor_sync(0xffffffffu, sum1, 2);
            l0 = l0 * al0 + sum0;
            l1 = l1 * al1 + sum1;
#pragma unroll
            for (int nt = 0; nt < 16; nt++) {
                Oacc[nt][0] *= al0; Oacc[nt][1] *= al0;
                Oacc[nt][2] *= al1; Oacc[nt][3] *= al1;
            }

            uint32_t Ph[4][4];
#pragma unroll
            for (int ktp = 0; ktp < 4; ktp++) {
                Ph[ktp][0] = pack_h2(S[2 * ktp][0], S[2 * ktp][1]);
                Ph[ktp][1] = pack_h2(S[2 * ktp][2], S[2 * ktp][3]);
                Ph[ktp][2] = pack_h2(S[2 * ktp + 1][0], S[2 * ktp + 1][1]);
                Ph[ktp][3] = pack_h2(S[2 * ktp + 1][2], S[2 * ktp + 1][3]);
            }

#pragma unroll
            for (int ktp = 0; ktp < 4; ktp++) {
#pragma unroll
                for (int j = 0; j < 8; j++) {
                    int r = ktp * 16 + lrow;
                    int c = 2 * j + lc;
                    uint32_t v0, v1, v2, v3;
                    LDSM_X4_T(v0, v1, v2, v3, sbs + 16384 + SWZ256(r, c));
                    mma_h(Oacc[2 * j], Ph[ktp], v0, v1);
                    mma_h(Oacc[2 * j + 1], Ph[ktp], v2, v3);
                }
            }
        }
        __syncthreads();
    }

    // ---- write O as fp16 (att layout [b*T, NH*HD]) ----
    float inv0 = 1.f / l0, inv1 = 1.f / l1;
    const size_t base0 = (size_t)(b * T_LEN + q0w + g) * (NH * HD) + h * HD;
    const size_t base1 = base0 + (size_t)8 * NH * HD;
#pragma unroll
    for (int nt = 0; nt < 16; nt++) {
        int col = nt * 8 + qq * 2;
        ((uint32_t*)ohp)[(base0 + col) >> 1] =
            pack_h2(Oacc[nt][0] * inv0, Oacc[nt][1] * inv0);
        ((uint32_t*)ohp)[(base1 + col) >> 1] =
            pack_h2(Oacc[nt][2] * inv1, Oacc[nt][3] * inv1);
    }
}

// ---------------- launcher ---------------------------------------------------
extern "C" void kernel_launch(void* const* d_in, const int* in_sizes, int n_in,
                              void* d_out, int out_size)
{
    const float* x       = (const float*)d_in[0];
    const float* Wq      = (const float*)d_in[1];
    const float* Wk      = (const float*)d_in[2];
    const float* Wv      = (const float*)d_in[3];
    const float* Wo      = (const float*)d_in[4];
    const float* q_scale = (const float*)d_in[5];
    const float* k_scale = (const float*)d_in[6];
    const float* cosT    = (const float*)d_in[7];
    const float* sinT    = (const float*)d_in[8];
    float* out = (float*)d_out;

    __half *xh, *ah, *wq, *wk, *wv, *wo, *qh, *kh, *vh;
    cudaGetSymbolAddress((void**)&xh, g_xh);
    cudaGetSymbolAddress((void**)&ah, g_ah);
    cudaGetSymbolAddress((void**)&wq, g_wq);  cudaGetSymbolAddress((void**)&wk, g_wk);
    cudaGetSymbolAddress((void**)&wv, g_wv);  cudaGetSymbolAddress((void**)&wo, g_wo);
    cudaGetSymbolAddress((void**)&qh, g_qh);
    cudaGetSymbolAddress((void**)&kh, g_kh);  cudaGetSymbolAddress((void**)&vh, g_vh);

    static bool attr_set = false;
    if (!attr_set) {
        cudaFuncSetAttribute(mma_gemm, cudaFuncAttributeMaxDynamicSharedMemorySize, GEMM_SMEM);
        cudaFuncSetAttribute(flash_mma, cudaFuncAttributeMaxDynamicSharedMemorySize, FA_SMEM);
        attr_set = true;
    }

    const int M = M_ROWS;  // 4096
    const float qk_scale = 1.4426950408889634f * 0.08838834764831845f;  // log2e/sqrt(HD)

    // one merged conversion launch
    prep<<<18432, 256>>>(x, Wq, Wk, Wv, Wo, xh, wq, wk, wv, wo);

    // merged Q+K+V projections with fused RMSNorm+RoPE epilogues
    mma_gemm<<<dim3(24, M / 128), 256, GEMM_SMEM>>>(
        xh, wq, wk, wv, qh, kh, vh,
        2, 2, 1,
        q_scale, k_scale, cosT, sinT,
        qk_scale, 1.0f,
        D_MODEL, 16, 4, NH * HD, NKV * HD, NKV * HD);

    // flash attention -> fp16 (BQ=64, 2 CTAs/SM)
    flash_mma<<<dim3(T_LEN / 64, NH, BATCH), 128, FA_SMEM>>>(qh, kh, vh, ah);

    // output projection (fp32 out)
    mma_gemm<<<dim3(16, M / 128), 256, GEMM_SMEM>>>(
        ah, wo, nullptr, nullptr, out, nullptr, nullptr,
        0, 0, 0,
        nullptr, nullptr, nullptr, nullptr,
        1.0f, 1.0f,
        D_MODEL, 16, 0, D_MODEL, 0, 0);
}

// round 13
// speedup vs baseline: 11.9782x; 1.0007x over previous
#include <cuda_runtime.h>
#include <cuda_fp16.h>
#include <math.h>
#include <stdint.h>

// Problem constants
#define BATCH 2
#define T_LEN 2048
#define D_MODEL 2048
#define NH 16
#define NKV 4
#define HD 128
#define EPS 1e-6f
#define M_ROWS (BATCH * T_LEN)  // 4096

// ---------------- scratch (device globals; no allocation allowed) ----------
__device__ __half g_xh[M_ROWS * D_MODEL];
__device__ __half g_ah[M_ROWS * D_MODEL];
__device__ __half g_wq[D_MODEL * D_MODEL];      // [N,K] transposed
__device__ __half g_wk[NKV * HD * D_MODEL];
__device__ __half g_wv[NKV * HD * D_MODEL];
__device__ __half g_wo[D_MODEL * D_MODEL];

__device__ __half g_qh[M_ROWS * NH * HD];
__device__ __half g_kh[M_ROWS * NKV * HD];
__device__ __half g_vh[M_ROWS * NKV * HD];

// ---------------- helpers -----------------------------------------------------
__device__ __forceinline__ uint32_t smem_u32(const void* p) {
    uint32_t a;
    asm("{ .reg .u64 t; cvta.to.shared.u64 t, %1; cvt.u32.u64 %0, t; }"
        : "=r"(a) : "l"(p));
    return a;
}

#define CP16(dst, src) \
    asm volatile("cp.async.cg.shared.global [%0], [%1], 16;" :: "r"(dst), "l"(src))
#define CP_COMMIT() asm volatile("cp.async.commit_group;" ::: "memory")
#define CP_WAIT(n)  asm volatile("cp.async.wait_group %0;" :: "n"(n) : "memory")

#define LDSM_X4(r0, r1, r2, r3, addr) \
    asm volatile("ldmatrix.sync.aligned.m8n8.x4.shared.b16 {%0,%1,%2,%3}, [%4];" \
                 : "=r"(r0), "=r"(r1), "=r"(r2), "=r"(r3) : "r"(addr))
#define LDSM_X4_T(r0, r1, r2, r3, addr) \
    asm volatile("ldmatrix.sync.aligned.m8n8.x4.trans.shared.b16 {%0,%1,%2,%3}, [%4];" \
                 : "=r"(r0), "=r"(r1), "=r"(r2), "=r"(r3) : "r"(addr))

// fp16 inputs, fp32 accumulator
__device__ __forceinline__ void mma_h(float* c, const uint32_t* a, uint32_t b0, uint32_t b1) {
    asm volatile(
        "mma.sync.aligned.m16n8k16.row.col.f32.f16.f16.f32 "
        "{%0,%1,%2,%3}, {%4,%5,%6,%7}, {%8,%9}, {%0,%1,%2,%3};"
        : "+f"(c[0]), "+f"(c[1]), "+f"(c[2]), "+f"(c[3])
        : "r"(a[0]), "r"(a[1]), "r"(a[2]), "r"(a[3]), "r"(b0), "r"(b1));
}

__device__ __forceinline__ uint32_t pack_h2(float x, float y) {
    __half2 h = __floats2half2_rn(x, y);
    return *reinterpret_cast<uint32_t*>(&h);
}

// ---------------- merged prep kernel: x cvt + 4 weight transposes -------------
__global__ __launch_bounds__(256) void prep(
    const float* __restrict__ x,
    const float* __restrict__ Wq, const float* __restrict__ Wk,
    const float* __restrict__ Wv, const float* __restrict__ Wo,
    __half* __restrict__ xh, __half* __restrict__ wq, __half* __restrict__ wk,
    __half* __restrict__ wv, __half* __restrict__ wo)
{
    __shared__ float tile[32][33];
    int bx = blockIdx.x;
    if (bx < 8192) {
        int i = bx * 256 + threadIdx.x;
        float4 v = ((const float4*)x)[i];
        ((uint2*)xh)[i] = make_uint2(pack_h2(v.x, v.y), pack_h2(v.z, v.w));
        return;
    }
    bx -= 8192;
    const float* W;
    __half* T;
    int N, t;
    if (bx < 4096)      { W = Wq; T = wq; N = 2048; t = bx; }
    else if (bx < 5120) { W = Wk; T = wk; N = 512;  t = bx - 4096; }
    else if (bx < 6144) { W = Wv; T = wv; N = 512;  t = bx - 5120; }
    else                { W = Wo; T = wo; N = 2048; t = bx - 6144; }
    const int K = 2048;
    const int ntn = N >> 5;
    const int n0 = (t % ntn) * 32, k0 = (t / ntn) * 32;
    const int tx = threadIdx.x & 31, ty4 = (threadIdx.x >> 5) * 4;
#pragma unroll
    for (int i = 0; i < 4; i++)
        tile[ty4 + i][tx] = W[(size_t)(k0 + ty4 + i) * N + n0 + tx];
    __syncthreads();
#pragma unroll
    for (int i = 0; i < 4; i++)
        T[(size_t)(n0 + ty4 + i) * K + k0 + tx] = __float2half_rn(tile[tx][ty4 + i]);
}

// ---------------- FP16 HMMA GEMM, 128x128 tile, BK=64, 3-stage cp.async -------
// C[M,N] = A[M,K] @ Bt[N,K]^T. 256 threads (warps 4x2), warp tile 32x64.
// ONE barrier per stage (bottom barrier removed — safe with 3 stages).
// Epilogue modes: 0 = fp32 store, 1 = fp16 store, 2 = RMSNorm+RoPE -> fp16
#define G_STAGE 32768
#define GEMM_SMEM (3 * G_STAGE + 1024)
#define SWZG(r, c) ((uint32_t)((r) * 128 + (((c) ^ ((r) & 7)) << 4)))

__global__ __launch_bounds__(256, 2) void mma_gemm(
    const __half* __restrict__ Ahp,
    const __half* __restrict__ B0, const __half* __restrict__ B1,
    const __half* __restrict__ B2,
    void* __restrict__ O0, void* __restrict__ O1, void* __restrict__ O2,
    int mode0, int mode1, int mode2,
    const float* __restrict__ sv0, const float* __restrict__ sv1,
    const float* __restrict__ cosT, const float* __restrict__ sinT,
    float ps0, float ps1,
    int K, int n0, int n1, int N0, int N1, int N2)
{
    extern __shared__ char smem[];
    const uint32_t sbase = smem_u32(smem);

    const int tid = threadIdx.x;
    const int lane = tid & 31, wid = tid >> 5;
    const int wm = wid >> 1, wn = wid & 1;
    const int bx = blockIdx.x;
    int mode, bn, N;
    const __half* B;
    void* O;
    const float* scaleV;
    float prescale;
    if (bx < n0) {
        mode = mode0; bn = bx * 128; B = B0; N = N0; O = O0;
        scaleV = sv0; prescale = ps0;
    } else if (bx < n0 + n1) {
        mode = mode1; bn = (bx - n0) * 128; B = B1; N = N1; O = O1;
        scaleV = sv1; prescale = ps1;
    } else {
        mode = mode2; bn = (bx - n0 - n1) * 128; B = B2; N = N2; O = O2;
        scaleV = sv0; prescale = 1.f;
    }
    const int bm = blockIdx.y * 128;
    const int NT = K / 64;

    float acc[2][8][4];
#pragma unroll
    for (int i = 0; i < 2; i++)
#pragma unroll
        for (int j = 0; j < 8; j++)
#pragma unroll
            for (int l = 0; l < 4; l++) acc[i][j][l] = 0.f;

    auto issue = [&](int it) {
        const int k0 = it * 64;
        const uint32_t sb = sbase + (it % 3) * G_STAGE;
#pragma unroll
        for (int i = 0; i < 8; i++) {
            int id = i * 256 + tid;          // 0..2047
            int r = (id >> 3) & 127, c = id & 7;
            if (id < 1024) {                 // A: 128 rows x 8 chunks
                CP16(sb + SWZG(r, c), Ahp + (size_t)(bm + r) * K + k0 + c * 8);
            } else {                         // B: 128 rows x 8 chunks
                CP16(sb + 16384 + SWZG(r, c), B + (size_t)(bn + r) * K + k0 + c * 8);
            }
        }
    };

    issue(0); CP_COMMIT();
    issue(1); CP_COMMIT();

    const int lrow = lane & 15, lc = lane >> 4;

    for (int it = 0; it < NT; ++it) {
        if (it + 1 < NT) { CP_WAIT(1); } else { CP_WAIT(0); }
        __syncthreads();
        if (it + 2 < NT) { issue(it + 2); CP_COMMIT(); }

        const uint32_t sb = sbase + (it % 3) * G_STAGE;
#pragma unroll
        for (int ks = 0; ks < 4; ks++) {
            const int c = ks * 2 + lc;
            uint32_t ah[2][4];
#pragma unroll
            for (int mt = 0; mt < 2; mt++) {
                int r = wm * 32 + mt * 16 + lrow;
                LDSM_X4(ah[mt][0], ah[mt][1], ah[mt][2], ah[mt][3], sb + SWZG(r, c));
            }
#pragma unroll
            for (int j = 0; j < 4; j++) {
                int r = wn * 64 + 16 * j + lrow;
                uint32_t b4[4];
                LDSM_X4(b4[0], b4[1], b4[2], b4[3], sb + 16384 + SWZG(r, c));
#pragma unroll
                for (int half = 0; half < 2; half++) {
                    int nt = 2 * j + half;
#pragma unroll
                    for (int mt = 0; mt < 2; mt++)
                        mma_h(acc[mt][nt], ah[mt], b4[half], b4[half + 2]);
                }
            }
        }
        // no bottom barrier: next write to this stage is ordered by the
        // NEXT iteration's top barrier (3-stage rotation)
    }

    // ---- epilogue ----
    const int g = lane >> 2, q = lane & 3;
    if (mode == 0) {
        float* Cf = (float*)O;
#pragma unroll
        for (int mt = 0; mt < 2; mt++)
#pragma unroll
            for (int nt = 0; nt < 8; nt++) {
                int row = bm + wm * 32 + mt * 16 + g;
                int col = bn + wn * 64 + nt * 8 + 2 * q;
                *(float2*)&Cf[(size_t)row * N + col] =
                    make_float2(acc[mt][nt][0], acc[mt][nt][1]);
                *(float2*)&Cf[(size_t)(row + 8) * N + col] =
                    make_float2(acc[mt][nt][2], acc[mt][nt][3]);
            }
    } else if (mode == 1) {
        uint32_t* Ch = (uint32_t*)O;
#pragma unroll
        for (int mt = 0; mt < 2; mt++)
#pragma unroll
            for (int nt = 0; nt < 8; nt++) {
                int row = bm + wm * 32 + mt * 16 + g;
                int col = bn + wn * 64 + nt * 8 + 2 * q;
                Ch[((size_t)row * N + col) >> 1] =
                    pack_h2(acc[mt][nt][0], acc[mt][nt][1]);
                Ch[((size_t)(row + 8) * N + col) >> 1] =
                    pack_h2(acc[mt][nt][2], acc[mt][nt][3]);
            }
    } else {
        // fused RMSNorm (this block's 128 cols = one head) + RoPE -> fp16
        float* red = (float*)(smem + 3 * G_STAGE);  // [2 wn][128 rows]
        __syncthreads();  // ensure mainloop smem reads done before reuse
#pragma unroll
        for (int mt = 0; mt < 2; mt++) {
            float s0 = 0.f, s1 = 0.f;
#pragma unroll
            for (int nt = 0; nt < 8; nt++) {
                s0 += acc[mt][nt][0] * acc[mt][nt][0] + acc[mt][nt][1] * acc[mt][nt][1];
                s1 += acc[mt][nt][2] * acc[mt][nt][2] + acc[mt][nt][3] * acc[mt][nt][3];
            }
            s0 += __shfl_xor_sync(0xffffffffu, s0, 1);
            s0 += __shfl_xor_sync(0xffffffffu, s0, 2);
            s1 += __shfl_xor_sync(0xffffffffu, s1, 1);
            s1 += __shfl_xor_sync(0xffffffffu, s1, 2);
            if (q == 0) {
                red[wn * 128 + wm * 32 + mt * 16 + g] = s0;
                red[wn * 128 + wm * 32 + mt * 16 + g + 8] = s1;
            }
        }
        __syncthreads();
        uint32_t* Ch = (uint32_t*)O;
#pragma unroll
        for (int mt = 0; mt < 2; mt++) {
#pragma unroll
            for (int rr = 0; rr < 2; rr++) {
                int r = wm * 32 + mt * 16 + g + rr * 8;
                float rinv = rsqrtf((red[r] + red[128 + r]) * (1.0f / HD) + EPS);
                int t = (bm + r) & (T_LEN - 1);
#pragma unroll
                for (int nt = 0; nt < 8; nt++) {
                    int d = wn * 64 + nt * 8 + 2 * q;
                    float2 sc = *(const float2*)&scaleV[d];
                    float2 cs = *(const float2*)&cosT[t * HD + d];
                    float2 sn = *(const float2*)&sinT[t * HD + d];
                    float v0 = acc[mt][nt][rr * 2 + 0] * rinv * sc.x;
                    float v1 = acc[mt][nt][rr * 2 + 1] * rinv * sc.y;
                    float o0 = (v0 * cs.x - v1 * sn.x) * prescale;
                    float o1 = (v1 * cs.y + v0 * sn.y) * prescale;
                    Ch[(((size_t)(bm + r)) * N + bn + d) >> 1] = pack_h2(o0, o1);
                }
            }
        }
    }
}

// ---------------- FP16 HMMA causal GQA flash attention ------------------------
// BQ=64 (4 warps x m16), BK=64, HD=128. Q persistent (16KB) +
// 3-stage K/V (3 x 32KB) = 112KB -> 2 CTAs/SM. 128 threads.
// ONE barrier per kv-tile (3-stage rotation makes bottom barrier redundant).
#define FA_KV_STAGE 32768
#define FA_SMEM (16384 + 3 * FA_KV_STAGE)
#define SWZ256(r, c) ((uint32_t)((r) * 256 + (((c) ^ ((r) & 7)) << 4)))

__global__ __launch_bounds__(128) void flash_mma(
    const __half* __restrict__ qh, const __half* __restrict__ kh,
    const __half* __restrict__ vh, __half* __restrict__ ohp)
{
    extern __shared__ char fsm[];
    const uint32_t sb = smem_u32(fsm);
    const uint32_t Qh_s = sb;
    const uint32_t ST = sb + 16384;  // per stage: Kh(16K) Vh(16K)

    const int qb = (int)gridDim.x - 1 - (int)blockIdx.x;  // heavy tiles first
    const int h = blockIdx.y, b = blockIdx.z;
    const int kvh = h >> 2;
    const int tid = threadIdx.x;
    const int lane = tid & 31, wid = tid >> 5;   // wid 0..3
    const int g = lane >> 2, qq = lane & 3;
    const int q0 = qb * 64;
    const int q0w = q0 + wid * 16;
    const int nkv = qb + 1;

    // ---- load Q (group 0) ----
#pragma unroll
    for (int i = 0; i < 8; i++) {
        int id = i * 128 + tid;
        int c = id & 15, r = id >> 4;
        CP16(Qh_s + SWZ256(r, c),
             qh + ((size_t)(b * T_LEN + q0 + r) * NH + h) * HD + c * 8);
    }
    CP_COMMIT();

    auto issue_kv = [&](int kt) {
        const int kv0 = kt * 64;
        const uint32_t sbs = ST + (kt % 3) * FA_KV_STAGE;
#pragma unroll
        for (int i = 0; i < 16; i++) {
            int id = i * 128 + tid;
            int c = id & 15, r = (id >> 4) & 63, arr = id >> 10;  // k, v
            const __half* src = arr ? vh : kh;
            uint32_t dst = sbs + arr * 16384 + SWZ256(r, c);
            CP16(dst, src + ((size_t)(b * T_LEN + kv0 + r) * NKV + kvh) * HD + c * 8);
        }
    };

    issue_kv(0);
    CP_COMMIT();
    if (nkv > 1) { issue_kv(1); CP_COMMIT(); }

    float m0 = -1e30f, m1 = -1e30f, l0 = 0.f, l1 = 0.f;
    float Oacc[16][4];
#pragma unroll
    for (int nt = 0; nt < 16; nt++)
#pragma unroll
        for (int e = 0; e < 4; e++) Oacc[nt][e] = 0.f;

    const int lrow = lane & 15, lc = lane >> 4;

    for (int kt = 0; kt < nkv; kt++) {
        if (kt + 1 < nkv) { CP_WAIT(1); } else { CP_WAIT(0); }
        __syncthreads();
        if (kt + 2 < nkv) { issue_kv(kt + 2); CP_COMMIT(); }

        const int kv0 = kt * 64;
        const uint32_t sbs = ST + (kt % 3) * FA_KV_STAGE;

        {
            float S[8][4];
#pragma unroll
            for (int nt = 0; nt < 8; nt++)
#pragma unroll
                for (int e = 0; e < 4; e++) S[nt][e] = 0.f;

#pragma unroll
            for (int ks = 0; ks < 8; ks++) {
                const int c = ks * 2 + lc;
                int qr = wid * 16 + lrow;
                uint32_t aq[4];
                LDSM_X4(aq[0], aq[1], aq[2], aq[3], Qh_s + SWZ256(qr, c));
#pragma unroll
                for (int j = 0; j < 4; j++) {
                    int r = 16 * j + lrow;
                    uint32_t b4[4];
                    LDSM_X4(b4[0], b4[1], b4[2], b4[3], sbs + SWZ256(r, c));
#pragma unroll
                    for (int half = 0; half < 2; half++)
                        mma_h(S[2 * j + half], aq, b4[half], b4[half + 2]);
                }
            }

            if (kv0 + 63 > q0w) {  // diagonal region: mask
#pragma unroll
                for (int nt = 0; nt < 8; nt++) {
                    int col = kv0 + nt * 8 + qq * 2;
                    int r0 = q0w + g, r1 = q0w + g + 8;
                    if (col > r0) S[nt][0] = -1e30f;
                    if (col + 1 > r0) S[nt][1] = -1e30f;
                    if (col > r1) S[nt][2] = -1e30f;
                    if (col + 1 > r1) S[nt][3] = -1e30f;
                }
            }

            float mx0 = -1e30f, mx1 = -1e30f;
#pragma unroll
            for (int nt = 0; nt < 8; nt++) {
                mx0 = fmaxf(mx0, fmaxf(S[nt][0], S[nt][1]));
                mx1 = fmaxf(mx1, fmaxf(S[nt][2], S[nt][3]));
            }
            mx0 = fmaxf(mx0, __shfl_xor_sync(0xffffffffu, mx0, 1));
            mx0 = fmaxf(mx0, __shfl_xor_sync(0xffffffffu, mx0, 2));
            mx1 = fmaxf(mx1, __shfl_xor_sync(0xffffffffu, mx1, 1));
            mx1 = fmaxf(mx1, __shfl_xor_sync(0xffffffffu, mx1, 2));
            float mn0 = fmaxf(m0, mx0), mn1 = fmaxf(m1, mx1);
            float al0 = exp2f(m0 - mn0), al1 = exp2f(m1 - mn1);
            m0 = mn0; m1 = mn1;
            float sum0 = 0.f, sum1 = 0.f;
#pragma unroll
            for (int nt = 0; nt < 8; nt++) {
                S[nt][0] = exp2f(S[nt][0] - mn0);
                S[nt][1] = exp2f(S[nt][1] - mn0);
                S[nt][2] = exp2f(S[nt][2] - mn1);
                S[nt][3] = exp2f(S[nt][3] - mn1);
                sum0 += S[nt][0] + S[nt][1];
                sum1 += S[nt][2] + S[nt][3];
            }
            sum0 += __shfl_xor_sync(0xffffffffu, sum0, 1);
            sum0 += __shfl_xor_sync(0xffffffffu, sum0, 2);
            sum1 += __shfl_xor_sync(0xffffffffu, sum1, 1);
            sum1 += __shfl_xor_sync(0xffffffffu, sum1, 2);
            l0 = l0 * al0 + sum0;
            l1 = l1 * al1 + sum1;
#pragma unroll
            for (int nt = 0; nt < 16; nt++) {
                Oacc[nt][0] *= al0; Oacc[nt][1] *= al0;
                Oacc[nt][2] *= al1; Oacc[nt][3] *= al1;
            }

            uint32_t Ph[4][4];
#pragma unroll
            for (int ktp = 0; ktp < 4; ktp++) {
                Ph[ktp][0] = pack_h2(S[2 * ktp][0], S[2 * ktp][1]);
                Ph[ktp][1] = pack_h2(S[2 * ktp][2], S[2 * ktp][3]);
                Ph[ktp][2] = pack_h2(S[2 * ktp + 1][0], S[2 * ktp + 1][1]);
                Ph[ktp][3] = pack_h2(S[2 * ktp + 1][2], S[2 * ktp + 1][3]);
            }

#pragma unroll
            for (int ktp = 0; ktp < 4; ktp++) {
#pragma unroll
                for (int j = 0; j < 8; j++) {
                    int r = ktp * 16 + lrow;
                    int c = 2 * j + lc;
                    uint32_t v0, v1, v2, v3;
                    LDSM_X4_T(v0, v1, v2, v3, sbs + 16384 + SWZ256(r, c));
                    mma_h(Oacc[2 * j], Ph[ktp], v0, v1);
                    mma_h(Oacc[2 * j + 1], Ph[ktp], v2, v3);
                }
            }
        }
        // no bottom barrier: 3-stage rotation + next top barrier order reuse
    }

    // ---- write O as fp16 (att layout [b*T, NH*HD]) ----
    float inv0 = 1.f / l0, inv1 = 1.f / l1;
    const size_t base0 = (size_t)(b * T_LEN + q0w + g) * (NH * HD) + h * HD;
    const size_t base1 = base0 + (size_t)8 * NH * HD;
#pragma unroll
    for (int nt = 0; nt < 16; nt++) {
        int col = nt * 8 + qq * 2;
        ((uint32_t*)ohp)[(base0 + col) >> 1] =
            pack_h2(Oacc[nt][0] * inv0, Oacc[nt][1] * inv0);
        ((uint32_t*)ohp)[(base1 + col) >> 1] =
            pack_h2(Oacc[nt][2] * inv1, Oacc[nt][3] * inv1);
    }
}

// ---------------- launcher ---------------------------------------------------
extern "C" void kernel_launch(void* const* d_in, const int* in_sizes, int n_in,
                              void* d_out, int out_size)
{
    const float* x       = (const float*)d_in[0];
    const float* Wq      = (const float*)d_in[1];
    const float* Wk      = (const float*)d_in[2];
    const float* Wv      = (const float*)d_in[3];
    const float* Wo      = (const float*)d_in[4];
    const float* q_scale = (const float*)d_in[5];
    const float* k_scale = (const float*)d_in[6];
    const float* cosT    = (const float*)d_in[7];
    const float* sinT    = (const float*)d_in[8];
    float* out = (float*)d_out;

    __half *xh, *ah, *wq, *wk, *wv, *wo, *qh, *kh, *vh;
    cudaGetSymbolAddress((void**)&xh, g_xh);
    cudaGetSymbolAddress((void**)&ah, g_ah);
    cudaGetSymbolAddress((void**)&wq, g_wq);  cudaGetSymbolAddress((void**)&wk, g_wk);
    cudaGetSymbolAddress((void**)&wv, g_wv);  cudaGetSymbolAddress((void**)&wo, g_wo);
    cudaGetSymbolAddress((void**)&qh, g_qh);
    cudaGetSymbolAddress((void**)&kh, g_kh);  cudaGetSymbolAddress((void**)&vh, g_vh);

    static bool attr_set = false;
    if (!attr_set) {
        cudaFuncSetAttribute(mma_gemm, cudaFuncAttributeMaxDynamicSharedMemorySize, GEMM_SMEM);
        cudaFuncSetAttribute(flash_mma, cudaFuncAttributeMaxDynamicSharedMemorySize, FA_SMEM);
        attr_set = true;
    }

    const int M = M_ROWS;  // 4096
    const float qk_scale = 1.4426950408889634f * 0.08838834764831845f;  // log2e/sqrt(HD)

    // one merged conversion launch
    prep<<<18432, 256>>>(x, Wq, Wk, Wv, Wo, xh, wq, wk, wv, wo);

    // merged Q+K+V projections with fused RMSNorm+RoPE epilogues
    mma_gemm<<<dim3(24, M / 128), 256, GEMM_SMEM>>>(
        xh, wq, wk, wv, qh, kh, vh,
        2, 2, 1,
        q_scale, k_scale, cosT, sinT,
        qk_scale, 1.0f,
        D_MODEL, 16, 4, NH * HD, NKV * HD, NKV * HD);

    // flash attention -> fp16 (BQ=64, 3-stage KV, 2 CTAs/SM)
    flash_mma<<<dim3(T_LEN / 64, NH, BATCH), 128, FA_SMEM>>>(qh, kh, vh, ah);

    // output projection (fp32 out)
    mma_gemm<<<dim3(16, M / 128), 256, GEMM_SMEM>>>(
        ah, wo, nullptr, nullptr, out, nullptr, nullptr,
        0, 0, 0,
        nullptr, nullptr, nullptr, nullptr,
        1.0f, 1.0f,
        D_MODEL, 16, 0, D_MODEL, 0, 0);
}